// round 4
// baseline (speedup 1.0000x reference)
#include <cuda_runtime.h>
#include <cuda_bf16.h>
#include <math.h>
#include <stdint.h>

// ---------------- problem constants ----------------
#define B_   64
#define S_   100
#define D_   768
#define H_   8
#define HD_  96
#define P_   8
#define FF_  3072
#define M_   (B_ * S_)            // 6400 rows
#define NLAYERS 4
#define EPS_ 1e-5f
#define INV_SQRT_HD 0.10206207261596575f   // 1/sqrt(96)

// ---------------- device scratch ----------------
__device__ float g_x[M_ * D_];
__device__ float g_enc[M_ * D_];
__device__ float g_pbias[B_ * H_ * S_ * S_];
__device__ float g_tmp[M_ * D_];

__device__ __nv_bfloat16 g_xhi[M_ * D_];
__device__ __nv_bfloat16 g_xlo[M_ * D_];
__device__ __nv_bfloat16 g_phi[M_ * D_];
__device__ __nv_bfloat16 g_plo[M_ * D_];
__device__ __nv_bfloat16 g_ffhi[(size_t)M_ * FF_];
__device__ __nv_bfloat16 g_fflo[(size_t)M_ * FF_];
__device__ __nv_bfloat16 g_w1h[(size_t)FF_ * D_];   // [N=3072][K=768]
__device__ __nv_bfloat16 g_w1l[(size_t)FF_ * D_];
__device__ __nv_bfloat16 g_w2h[(size_t)D_ * FF_];   // [N=768][K=3072]
__device__ __nv_bfloat16 g_w2l[(size_t)D_ * FF_];
__device__ __nv_bfloat16 g_wch[(size_t)D_ * D_];    // [N=768][K=768]
__device__ __nv_bfloat16 g_wcl[(size_t)D_ * D_];

// ============================================================
// PTX helpers (mma.sync / ldmatrix / cp.async — all baseline sm_80+)
// ============================================================
__device__ __forceinline__ uint32_t smem_u32(const void* p) {
    uint32_t a;
    asm("{ .reg .u64 t; cvta.to.shared.u64 t, %1; cvt.u32.u64 %0, t; }" : "=r"(a) : "l"(p));
    return a;
}

#define CP_ASYNC16(dst, src) \
    asm volatile("cp.async.cg.shared.global [%0], [%1], 16;\n" :: "r"(dst), "l"(src) : "memory")
#define CP_COMMIT() asm volatile("cp.async.commit_group;\n" ::: "memory")
#define CP_WAIT0()  asm volatile("cp.async.wait_group 0;\n" ::: "memory")
#define CP_WAIT1()  asm volatile("cp.async.wait_group 1;\n" ::: "memory")
#define CP_WAIT2()  asm volatile("cp.async.wait_group 2;\n" ::: "memory")

#define LDSM4(r, addr) \
    asm volatile("ldmatrix.sync.aligned.m8n8.x4.shared.b16 {%0,%1,%2,%3}, [%4];" \
        : "=r"((r)[0]), "=r"((r)[1]), "=r"((r)[2]), "=r"((r)[3]) : "r"(addr))

#define MMA_BF16(c, a, b) \
    asm volatile("mma.sync.aligned.m16n8k16.row.col.f32.bf16.bf16.f32 " \
        "{%0,%1,%2,%3}, {%4,%5,%6,%7}, {%8,%9}, {%0,%1,%2,%3};" \
        : "+f"((c)[0]), "+f"((c)[1]), "+f"((c)[2]), "+f"((c)[3]) \
        : "r"((a)[0]), "r"((a)[1]), "r"((a)[2]), "r"((a)[3]), "r"((b)[0]), "r"((b)[1]))

__device__ __forceinline__ float gelu_exact(float v) {
    return 0.5f * v * (1.0f + erff(v * 0.70710678118654752f));
}
__device__ __forceinline__ void split_bf16(float v, __nv_bfloat16& h, __nv_bfloat16& l) {
    h = __float2bfloat16(v);
    l = __float2bfloat16(v - __bfloat162float(h));
}

// ============================================================
// GEMM: C[M,N] = A[M,K] @ B^T[N,K] (+ bias), fp32 via bf16 hi/lo x3 on HMMA
// EPI 0: store fp32 + bias.  EPI 1: bias + gelu -> bf16 hi/lo out.
// EPI 2: split-K partial, atomicAdd fp32, NO bias (folded into later LN).
//        gridDim.z = split count; each z handles K/gridDim.z.
// M%128==0, N%128==0, Kloc%32==0.
// ============================================================
#define BMT 128
#define BNT 128
#define BKS 32
#define NSTAGE 4
#define MATB 10240u                // 128*40*2 bytes
#define BUFB (4 * MATB)            // 40960
#define GEMM_SMEM (NSTAGE * BUFB)  // 163840

template <int EPI>
__global__ __launch_bounds__(256)
void mma_gemm(const __nv_bfloat16* __restrict__ Ah_, const __nv_bfloat16* __restrict__ Al_,
              const __nv_bfloat16* __restrict__ Bh_, const __nv_bfloat16* __restrict__ Bl_,
              const float* __restrict__ bias,
              float* __restrict__ Cf, __nv_bfloat16* __restrict__ Ch,
              __nv_bfloat16* __restrict__ Cl,
              int M, int N, int K)
{
    extern __shared__ char dsm[];
    const uint32_t sb0 = smem_u32(dsm);
    const int tid = threadIdx.x;
    const int wid = tid >> 5, lane = tid & 31;
    const int wm = wid >> 2, wn = wid & 3;          // warp tile: 64 x 32
    const int row0 = blockIdx.y * BMT, col0 = blockIdx.x * BNT;
    const int Kloc = K / gridDim.z;
    const int koff = blockIdx.z * Kloc;
    const int NS = Kloc / BKS;

    const __nv_bfloat16* Ahp = Ah_ + koff;
    const __nv_bfloat16* Alp = Al_ + koff;
    const __nv_bfloat16* Bhp = Bh_ + koff;
    const __nv_bfloat16* Blp = Bl_ + koff;

    float acc[4][4][4];
    #pragma unroll
    for (int i = 0; i < 4; i++)
        #pragma unroll
        for (int j = 0; j < 4; j++)
            #pragma unroll
            for (int k = 0; k < 4; k++) acc[i][j][k] = 0.f;

    // ldmatrix per-lane base offsets (bytes, within one stage buffer)
    const uint32_t aoff = (uint32_t)((wm * 64 + (lane & 15)) * 80 + (lane >> 4) * 16);
    const uint32_t boff = (uint32_t)((wn * 32 + ((lane >> 4) << 3) + (lane & 7)) * 80
                                     + ((lane >> 3) & 1) * 16);

    auto load_step = [&](int s) {
        const uint32_t sb = sb0 + (uint32_t)(s % NSTAGE) * BUFB;
        const int k0 = s * BKS;
        #pragma unroll
        for (int i = 0; i < 8; i++) {
            int u = i * 256 + tid;
            int mat = u >> 9;          // 0 Ah, 1 Al, 2 Bh, 3 Bl
            int v = u & 511;
            int r = v >> 2, c = v & 3;
            const __nv_bfloat16* src;
            if (mat == 0)      src = Ahp + (size_t)(row0 + r) * K + k0 + c * 8;
            else if (mat == 1) src = Alp + (size_t)(row0 + r) * K + k0 + c * 8;
            else if (mat == 2) src = Bhp + (size_t)(col0 + r) * K + k0 + c * 8;
            else               src = Blp + (size_t)(col0 + r) * K + k0 + c * 8;
            CP_ASYNC16(sb + (uint32_t)mat * MATB + (uint32_t)(r * 80 + c * 16), src);
        }
        CP_COMMIT();
    };

    load_step(0);
    if (NS > 1) load_step(1);
    if (NS > 2) load_step(2);

    for (int s = 0; s < NS; s++) {
        const int rem = NS - 1 - s;
        if (rem >= 2)      { CP_WAIT2(); }
        else if (rem == 1) { CP_WAIT1(); }
        else               { CP_WAIT0(); }
        __syncthreads();
        if (s + 3 < NS) load_step(s + 3);   // buffer (s+3)%4 == (s-1)%4: free after the barrier

        const uint32_t sb = sb0 + (uint32_t)(s % NSTAGE) * BUFB;
        #pragma unroll
        for (int kh = 0; kh < 2; kh++) {     // two k16 halves of the k32 step
            uint32_t ah[4][4], al[4][4], bh[4][2], bl[4][2];
            #pragma unroll
            for (int mf = 0; mf < 4; mf++) {
                LDSM4(ah[mf], sb + aoff + (uint32_t)(mf * 1280 + kh * 32));
                LDSM4(al[mf], sb + MATB + aoff + (uint32_t)(mf * 1280 + kh * 32));
            }
            #pragma unroll
            for (int p = 0; p < 2; p++) {
                uint32_t t[4];
                LDSM4(t, sb + 2 * MATB + boff + (uint32_t)(p * 1280 + kh * 32));
                bh[2 * p][0] = t[0]; bh[2 * p][1] = t[1];
                bh[2 * p + 1][0] = t[2]; bh[2 * p + 1][1] = t[3];
                LDSM4(t, sb + 3 * MATB + boff + (uint32_t)(p * 1280 + kh * 32));
                bl[2 * p][0] = t[0]; bl[2 * p][1] = t[1];
                bl[2 * p + 1][0] = t[2]; bl[2 * p + 1][1] = t[3];
            }
            #pragma unroll
            for (int mf = 0; mf < 4; mf++)
                #pragma unroll
                for (int nf = 0; nf < 4; nf++) {
                    MMA_BF16(acc[mf][nf], ah[mf], bh[nf]);
                    MMA_BF16(acc[mf][nf], ah[mf], bl[nf]);
                    MMA_BF16(acc[mf][nf], al[mf], bh[nf]);
                }
        }
    }

    // ---- epilogue: regs -> per-warp smem stage -> coalesced stores ----
    __syncthreads();
    float* stg = (float*)dsm + wid * (16 * 33);
    const int gcol = col0 + wn * 32 + lane;
    const float bv = (EPI == 2) ? 0.f : bias[gcol];
    const int r1 = lane >> 2, c0 = (lane & 3) * 2;

    #pragma unroll
    for (int mf = 0; mf < 4; mf++) {
        #pragma unroll
        for (int nf = 0; nf < 4; nf++) {
            stg[r1 * 33 + nf * 8 + c0]           = acc[mf][nf][0];
            stg[r1 * 33 + nf * 8 + c0 + 1]       = acc[mf][nf][1];
            stg[(r1 + 8) * 33 + nf * 8 + c0]     = acc[mf][nf][2];
            stg[(r1 + 8) * 33 + nf * 8 + c0 + 1] = acc[mf][nf][3];
        }
        __syncwarp();
        const int grow = row0 + wm * 64 + mf * 16;
        #pragma unroll
        for (int r = 0; r < 16; r++) {
            float v = stg[r * 33 + lane] + bv;
            if (EPI == 1) {
                v = gelu_exact(v);
                __nv_bfloat16 h = __float2bfloat16(v);
                Ch[(size_t)(grow + r) * N + gcol] = h;
                Cl[(size_t)(grow + r) * N + gcol] = __float2bfloat16(v - __bfloat162float(h));
            } else if (EPI == 2) {
                atomicAdd(&Cf[(size_t)(grow + r) * N + gcol], v);
            } else {
                Cf[(size_t)(grow + r) * N + gcol] = v;
            }
        }
        __syncwarp();
    }
}

// ============================================================
// weight transpose + bf16 hi/lo split: W[K][N] -> T{h,l}[N][K]
// ============================================================
__global__ void wconv_kernel(const float* __restrict__ W, __nv_bfloat16* __restrict__ Th,
                             __nv_bfloat16* __restrict__ Tl, int K, int N) {
    __shared__ float t[32][33];
    int k0 = blockIdx.x * 32, n0 = blockIdx.y * 32;
    int tx = threadIdx.x, ty = threadIdx.y;  // (32, 8)
    #pragma unroll
    for (int i = 0; i < 4; i++)
        t[ty + i * 8][tx] = W[(size_t)(k0 + ty + i * 8) * N + n0 + tx];
    __syncthreads();
    #pragma unroll
    for (int i = 0; i < 4; i++) {
        int n = n0 + ty + i * 8, k = k0 + tx;
        float v = t[tx][ty + i * 8];
        __nv_bfloat16 h, l;
        split_bf16(v, h, l);
        Th[(size_t)n * K + k] = h;
        Tl[(size_t)n * K + k] = l;
    }
}

// ---------------- elementwise: x = template + positional encoding ----------------
__global__ void add_pe_kernel(const float* __restrict__ t, float* __restrict__ x) {
    int idx = blockIdx.x * 256 + threadIdx.x;
    if (idx >= M_ * D_) return;
    int d = idx % D_;
    int s = (idx / D_) % S_;
    int i2 = d & ~1;
    float div = expf((float)i2 * (-9.210340371976184f / (float)D_));
    float ang = (float)s * div;
    float pe = (d & 1) ? cosf(ang) : sinf(ang);
    x[idx] = t[idx] + pe;
}

// ---------------- pooled = mean over P, emitted as bf16 hi/lo ----------------
__global__ void pool_kernel(const float* __restrict__ ps,
                            __nv_bfloat16* __restrict__ ph, __nv_bfloat16* __restrict__ pl) {
    int idx = blockIdx.x * 256 + threadIdx.x;
    if (idx >= M_ * D_) return;
    int bs = idx / D_;
    int c  = idx % D_;
    const float* base = ps + (size_t)bs * (P_ * D_) + c;
    float s = 0.f;
    #pragma unroll
    for (int p = 0; p < P_; p++) s += base[p * D_];
    float m = s * (1.0f / P_);
    __nv_bfloat16 h, l;
    split_bf16(m, h, l);
    ph[idx] = h; pl[idx] = l;
}

// ---------------- block-reduce helper ----------------
__device__ __forceinline__ float warp_sum(float v) {
    #pragma unroll
    for (int o = 16; o; o >>= 1) v += __shfl_down_sync(0xffffffffu, v, o);
    return v;
}

// ---------------- LayerNorm (row length 768) ----------------
// t = x (+ res) (+ colbias);  out = LN(t)*g + b;  optional bf16 hi/lo out
template <int BF16OUT>
__global__ void ln_kernel(const float* __restrict__ x, const float* __restrict__ res,
                          const float* __restrict__ colbias,
                          const float* __restrict__ g, const float* __restrict__ b,
                          float* __restrict__ out,
                          __nv_bfloat16* __restrict__ oh, __nv_bfloat16* __restrict__ ol) {
    const int row = blockIdx.x;
    const int tid = threadIdx.x;  // 256
    const float* xr = x + (size_t)row * D_;
    const float* rr = res ? res + (size_t)row * D_ : nullptr;

    float v[3];
    float s = 0.f, s2 = 0.f;
    #pragma unroll
    for (int i = 0; i < 3; i++) {
        int c = tid + i * 256;
        float t = xr[c];
        if (rr) t += rr[c];
        if (colbias) t += colbias[c];
        v[i] = t; s += t; s2 += t * t;
    }

    __shared__ float red[2][8];
    __shared__ float stat[2];
    int lane = tid & 31, wid = tid >> 5;
    s = warp_sum(s); s2 = warp_sum(s2);
    if (lane == 0) { red[0][wid] = s; red[1][wid] = s2; }
    __syncthreads();
    if (wid == 0) {
        float a = (lane < 8) ? red[0][lane] : 0.f;
        float c = (lane < 8) ? red[1][lane] : 0.f;
        a = warp_sum(a); c = warp_sum(c);
        if (lane == 0) {
            float mean = a * (1.0f / D_);
            float var = c * (1.0f / D_) - mean * mean;
            stat[0] = mean;
            stat[1] = rsqrtf(var + EPS_);
        }
    }
    __syncthreads();
    float mean = stat[0], inv = stat[1];
    float* orow = out + (size_t)row * D_;
    #pragma unroll
    for (int i = 0; i < 3; i++) {
        int c = tid + i * 256;
        float o = (v[i] - mean) * inv * g[c] + b[c];
        orow[c] = o;
        if (BF16OUT) {
            __nv_bfloat16 h, l;
            split_bf16(o, h, l);
            oh[(size_t)row * D_ + c] = h;
            ol[(size_t)row * D_ + c] = l;
        }
    }
}

// ---------------- param_bias[b,h] = (pe_bh @ pe_bh^T) * inv_sqrt_hd ----------------
__global__ __launch_bounds__(256)
void pbias_kernel(const float* __restrict__ enc, float* __restrict__ pbias) {
    __shared__ float Es[112 * 97];
    const int b = blockIdx.x >> 3;
    const int h = blockIdx.x & 7;
    const int tid = threadIdx.x;
    const float* src = enc + (size_t)(b * S_) * D_ + h * HD_;

    for (int i = tid; i < 112 * 96; i += 256) {
        int s = i / 96, d = i - s * 96;
        Es[s * 97 + d] = (s < S_) ? src[(size_t)s * D_ + d] : 0.f;
    }
    __syncthreads();

    const int tx = tid & 15, ty = tid >> 4;
    float acc[7][7];
    #pragma unroll
    for (int ii = 0; ii < 7; ii++)
        #pragma unroll
        for (int jj = 0; jj < 7; jj++) acc[ii][jj] = 0.f;

    for (int d = 0; d < 96; d++) {
        float a[7], bb[7];
        #pragma unroll
        for (int ii = 0; ii < 7; ii++) a[ii]  = Es[(ty + 16 * ii) * 97 + d];
        #pragma unroll
        for (int jj = 0; jj < 7; jj++) bb[jj] = Es[(tx + 16 * jj) * 97 + d];
        #pragma unroll
        for (int ii = 0; ii < 7; ii++)
            #pragma unroll
            for (int jj = 0; jj < 7; jj++) acc[ii][jj] += a[ii] * bb[jj];
    }

    float* dst = pbias + (size_t)blockIdx.x * (S_ * S_);
    #pragma unroll
    for (int ii = 0; ii < 7; ii++) {
        int i = ty + 16 * ii;
        if (i >= S_) continue;
        #pragma unroll
        for (int jj = 0; jj < 7; jj++) {
            int j = tx + 16 * jj;
            if (j < S_) dst[i * S_ + j] = acc[ii][jj] * INV_SQRT_HD;
        }
    }
}

// ---------------- fused attention per (b,h) ----------------
#define ATTN_SMEM ((112 * 97 + 112 * 101) * 4)
__global__ __launch_bounds__(256)
void attn_kernel(const float* __restrict__ x, const float* __restrict__ pbias,
                 float* __restrict__ out) {
    extern __shared__ float smem[];
    float* Qs = smem;               // [112][97]
    float* Ss = smem + 112 * 97;    // [112][101]

    const int b = blockIdx.x >> 3;
    const int h = blockIdx.x & 7;
    const int tid = threadIdx.x;
    const float* xb = x + (size_t)(b * S_) * D_ + h * HD_;

    for (int i = tid; i < 112 * 96; i += 256) {
        int s = i / 96, d = i - s * 96;
        Qs[s * 97 + d] = (s < S_) ? xb[(size_t)s * D_ + d] : 0.f;
    }
    __syncthreads();

    const int tx = tid & 15, ty = tid >> 4;
    {
        float acc[7][7];
        #pragma unroll
        for (int ii = 0; ii < 7; ii++)
            #pragma unroll
            for (int jj = 0; jj < 7; jj++) acc[ii][jj] = 0.f;

        for (int d = 0; d < 96; d++) {
            float a[7], bb[7];
            #pragma unroll
            for (int ii = 0; ii < 7; ii++) a[ii]  = Qs[(ty + 16 * ii) * 97 + d];
            #pragma unroll
            for (int jj = 0; jj < 7; jj++) bb[jj] = Qs[(tx + 16 * jj) * 97 + d];
            #pragma unroll
            for (int ii = 0; ii < 7; ii++)
                #pragma unroll
                for (int jj = 0; jj < 7; jj++) acc[ii][jj] += a[ii] * bb[jj];
        }
        const float* pb = pbias + (size_t)blockIdx.x * (S_ * S_);
        #pragma unroll
        for (int ii = 0; ii < 7; ii++) {
            int i = ty + 16 * ii;
            if (i >= S_) continue;
            #pragma unroll
            for (int jj = 0; jj < 7; jj++) {
                int j = tx + 16 * jj;
                if (j < S_)
                    Ss[i * 101 + j] = acc[ii][jj] * INV_SQRT_HD + pb[i * S_ + j];
            }
        }
    }
    __syncthreads();

    if (tid < S_) {
        float* row = Ss + tid * 101;
        float m = -1e30f;
        for (int j = 0; j < S_; j++) m = fmaxf(m, row[j]);
        float sum = 0.f;
        for (int j = 0; j < S_; j++) { float e = expf(row[j] - m); row[j] = e; sum += e; }
        float inv = 1.0f / sum;
        for (int j = 0; j < S_; j++) row[j] *= inv;
    }
    __syncthreads();

    {
        float acc[7][6];
        #pragma unroll
        for (int ii = 0; ii < 7; ii++)
            #pragma unroll
            for (int jj = 0; jj < 6; jj++) acc[ii][jj] = 0.f;

        for (int j = 0; j < S_; j++) {
            float a[7], bb[6];
            #pragma unroll
            for (int ii = 0; ii < 7; ii++) a[ii]  = Ss[(ty + 16 * ii) * 101 + j];
            #pragma unroll
            for (int jj = 0; jj < 6; jj++) bb[jj] = Qs[j * 97 + tx + 16 * jj];
            #pragma unroll
            for (int ii = 0; ii < 7; ii++)
                #pragma unroll
                for (int jj = 0; jj < 6; jj++) acc[ii][jj] += a[ii] * bb[jj];
        }
        float* dst = out + (size_t)(b * S_) * D_ + h * HD_;
        #pragma unroll
        for (int ii = 0; ii < 7; ii++) {
            int i = ty + 16 * ii;
            if (i >= S_) continue;
            #pragma unroll
            for (int jj = 0; jj < 6; jj++) {
                int dd = tx + 16 * jj;
                dst[(size_t)i * D_ + dd] = acc[ii][jj];
            }
        }
    }
}

// ---------------- final classifier ----------------
__global__ void fc_kernel(const float* __restrict__ x, const float* __restrict__ Wfc,
                          const float* __restrict__ bfc, float* __restrict__ out) {
    const int b = blockIdx.x;
    const int tid = threadIdx.x;
    const float* xr = x + (size_t)b * (S_ * D_);
    float a0 = 0.f, a1 = 0.f;
    for (int i = tid; i < S_ * D_; i += 256) {
        float v = xr[i];
        a0 += v * Wfc[2 * i];
        a1 += v * Wfc[2 * i + 1];
    }
    __shared__ float red[2][8];
    int lane = tid & 31, wid = tid >> 5;
    a0 = warp_sum(a0); a1 = warp_sum(a1);
    if (lane == 0) { red[0][wid] = a0; red[1][wid] = a1; }
    __syncthreads();
    if (wid == 0) {
        float r0 = (lane < 8) ? red[0][lane] : 0.f;
        float r1 = (lane < 8) ? red[1][lane] : 0.f;
        r0 = warp_sum(r0); r1 = warp_sum(r1);
        if (lane == 0) {
            out[2 * b + 0] = r0 + bfc[0];
            out[2 * b + 1] = r1 + bfc[1];
        }
    }
}

// ---------------- launch ----------------
extern "C" void kernel_launch(void* const* d_in, const int* in_sizes, int n_in,
                              void* d_out, int out_size) {
    const float* tseq = (const float*)d_in[0];
    const float* pseq = (const float*)d_in[1];
    const float* Wc  = (const float*)d_in[2];
    const float* bc  = (const float*)d_in[3];
    const float* gp  = (const float*)d_in[4];
    const float* bp  = (const float*)d_in[5];
    const float* W1  = (const float*)d_in[6];
    const float* b1  = (const float*)d_in[7];
    const float* W2  = (const float*)d_in[8];
    const float* b2  = (const float*)d_in[9];
    const float* g1  = (const float*)d_in[10];
    const float* bn1 = (const float*)d_in[11];
    const float* g2  = (const float*)d_in[12];
    const float* bn2 = (const float*)d_in[13];
    const float* Wfc = (const float*)d_in[14];
    const float* bfc = (const float*)d_in[15];
    float* out = (float*)d_out;

    float *x, *enc, *pbias, *tmp;
    __nv_bfloat16 *xhi, *xlo, *phi, *plo, *ffhi, *fflo;
    __nv_bfloat16 *w1h, *w1l, *w2h, *w2l, *wch, *wcl;
    cudaGetSymbolAddress((void**)&x, g_x);
    cudaGetSymbolAddress((void**)&enc, g_enc);
    cudaGetSymbolAddress((void**)&pbias, g_pbias);
    cudaGetSymbolAddress((void**)&tmp, g_tmp);
    cudaGetSymbolAddress((void**)&xhi, g_xhi);
    cudaGetSymbolAddress((void**)&xlo, g_xlo);
    cudaGetSymbolAddress((void**)&phi, g_phi);
    cudaGetSymbolAddress((void**)&plo, g_plo);
    cudaGetSymbolAddress((void**)&ffhi, g_ffhi);
    cudaGetSymbolAddress((void**)&fflo, g_fflo);
    cudaGetSymbolAddress((void**)&w1h, g_w1h);
    cudaGetSymbolAddress((void**)&w1l, g_w1l);
    cudaGetSymbolAddress((void**)&w2h, g_w2h);
    cudaGetSymbolAddress((void**)&w2l, g_w2l);
    cudaGetSymbolAddress((void**)&wch, g_wch);
    cudaGetSymbolAddress((void**)&wcl, g_wcl);

    cudaFuncSetAttribute(attn_kernel, cudaFuncAttributeMaxDynamicSharedMemorySize, ATTN_SMEM);
    cudaFuncSetAttribute(mma_gemm<0>, cudaFuncAttributeMaxDynamicSharedMemorySize, GEMM_SMEM);
    cudaFuncSetAttribute(mma_gemm<1>, cudaFuncAttributeMaxDynamicSharedMemorySize, GEMM_SMEM);
    cudaFuncSetAttribute(mma_gemm<2>, cudaFuncAttributeMaxDynamicSharedMemorySize, GEMM_SMEM);

    // weight transpose + split (tiny, one-time per launch)
    wconv_kernel<<<dim3(D_ / 32, FF_ / 32), dim3(32, 8)>>>(W1, w1h, w1l, D_, FF_);
    wconv_kernel<<<dim3(FF_ / 32, D_ / 32), dim3(32, 8)>>>(W2, w2h, w2l, FF_, D_);
    wconv_kernel<<<dim3(D_ / 32, D_ / 32),  dim3(32, 8)>>>(Wc, wch, wcl, D_, D_);

    const int total = M_ * D_;
    add_pe_kernel<<<(total + 255) / 256, 256>>>(tseq, x);
    pool_kernel<<<(total + 255) / 256, 256>>>(pseq, phi, plo);

    // param encoder: enc = LN(pooled @ Wc + bc)   (split-K=2, bias folded into LN)
    cudaMemsetAsync(enc, 0, (size_t)M_ * D_ * sizeof(float));
    mma_gemm<2><<<dim3(D_ / BNT, M_ / BMT, 2), 256, GEMM_SMEM>>>(
        phi, plo, wch, wcl, nullptr, enc, nullptr, nullptr, M_, D_, D_);
    ln_kernel<0><<<M_, 256>>>(enc, nullptr, bc, gp, bp, enc, nullptr, nullptr);

    // layer-invariant attention bias
    pbias_kernel<<<B_ * H_, 256>>>(enc, pbias);

    for (int l = 0; l < NLAYERS; l++) {
        attn_kernel<<<B_ * H_, 256, ATTN_SMEM>>>(x, pbias, tmp);
        ln_kernel<1><<<M_, 256>>>(x, tmp, nullptr, g1, bn1, x, xhi, xlo);
        mma_gemm<1><<<dim3(FF_ / BNT, M_ / BMT), 256, GEMM_SMEM>>>(
            xhi, xlo, w1h, w1l, b1, nullptr, ffhi, fflo, M_, FF_, D_);
        // FFN2: split-K=4, bias b2 folded into the following LN
        cudaMemsetAsync(tmp, 0, (size_t)M_ * D_ * sizeof(float));
        mma_gemm<2><<<dim3(D_ / BNT, M_ / BMT, 4), 256, GEMM_SMEM>>>(
            ffhi, fflo, w2h, w2l, nullptr, tmp, nullptr, nullptr, M_, D_, FF_);
        ln_kernel<0><<<M_, 256>>>(x, tmp, b2, g2, bn2, x, nullptr, nullptr);
    }

    fc_kernel<<<B_, 256>>>(x, Wfc, bfc, out);
}

// round 5
// speedup vs baseline: 1.1900x; 1.1900x over previous
#include <cuda_runtime.h>
#include <cuda_bf16.h>
#include <math.h>
#include <stdint.h>

// ---------------- problem constants ----------------
#define B_   64
#define S_   100
#define D_   768
#define H_   8
#define HD_  96
#define P_   8
#define FF_  3072
#define M_   (B_ * S_)            // 6400 rows
#define NLAYERS 4
#define EPS_ 1e-5f
#define INV_SQRT_HD 0.10206207261596575f   // 1/sqrt(96)

// ---------------- device scratch ----------------
__device__ float g_x[M_ * D_];
__device__ float g_enc[M_ * D_];
__device__ float g_pbias[B_ * H_ * S_ * S_];
__device__ float g_part[2][M_ * D_];   // split-K fp32 partials

__device__ __nv_bfloat16 g_xhi[M_ * D_];
__device__ __nv_bfloat16 g_xlo[M_ * D_];
__device__ __nv_bfloat16 g_phi[M_ * D_];
__device__ __nv_bfloat16 g_plo[M_ * D_];
__device__ __nv_bfloat16 g_ffhi[(size_t)M_ * FF_];
__device__ __nv_bfloat16 g_fflo[(size_t)M_ * FF_];
__device__ __nv_bfloat16 g_w1h[(size_t)FF_ * D_];   // [N=3072][K=768]
__device__ __nv_bfloat16 g_w1l[(size_t)FF_ * D_];
__device__ __nv_bfloat16 g_w2h[(size_t)D_ * FF_];   // [N=768][K=3072]
__device__ __nv_bfloat16 g_w2l[(size_t)D_ * FF_];
__device__ __nv_bfloat16 g_wch[(size_t)D_ * D_];    // [N=768][K=768]
__device__ __nv_bfloat16 g_wcl[(size_t)D_ * D_];

// ============================================================
// PTX helpers (mma.sync / ldmatrix / cp.async — all baseline sm_80+)
// ============================================================
__device__ __forceinline__ uint32_t smem_u32(const void* p) {
    uint32_t a;
    asm("{ .reg .u64 t; cvta.to.shared.u64 t, %1; cvt.u32.u64 %0, t; }" : "=r"(a) : "l"(p));
    return a;
}

#define CP_ASYNC16(dst, src) \
    asm volatile("cp.async.cg.shared.global [%0], [%1], 16;\n" :: "r"(dst), "l"(src) : "memory")
#define CP_COMMIT() asm volatile("cp.async.commit_group;\n" ::: "memory")
#define CP_WAIT0()  asm volatile("cp.async.wait_group 0;\n" ::: "memory")

#define LDSM4(r, addr) \
    asm volatile("ldmatrix.sync.aligned.m8n8.x4.shared.b16 {%0,%1,%2,%3}, [%4];" \
        : "=r"((r)[0]), "=r"((r)[1]), "=r"((r)[2]), "=r"((r)[3]) : "r"(addr))

#define MMA_BF16(c, a, b) \
    asm volatile("mma.sync.aligned.m16n8k16.row.col.f32.bf16.bf16.f32 " \
        "{%0,%1,%2,%3}, {%4,%5,%6,%7}, {%8,%9}, {%0,%1,%2,%3};" \
        : "+f"((c)[0]), "+f"((c)[1]), "+f"((c)[2]), "+f"((c)[3]) \
        : "r"((a)[0]), "r"((a)[1]), "r"((a)[2]), "r"((a)[3]), "r"((b)[0]), "r"((b)[1]))

__device__ __forceinline__ float gelu_exact(float v) {
    return 0.5f * v * (1.0f + erff(v * 0.70710678118654752f));
}
__device__ __forceinline__ void split_bf16(float v, __nv_bfloat16& h, __nv_bfloat16& l) {
    h = __float2bfloat16(v);
    l = __float2bfloat16(v - __bfloat162float(h));
}

// ============================================================
// GEMM: C[M,N] = A[M,K] @ B^T[N,K] (+ bias), fp32 via bf16 hi/lo x3 on HMMA
// EPI 1: bias + gelu -> bf16 hi/lo out (Ch, Cl).
// EPI 2: plain fp32 partial store, NO bias; z-th split writes Cf + z*M*N.
// Double-buffered (2 stages, 80KB smem), 2 CTAs/SM.
// ============================================================
#define BMT 128
#define BNT 128
#define BKS 32
#define MATB 10240u                // 128*40*2 bytes
#define BUFB (4 * MATB)            // 40960
#define GEMM_SMEM (2 * BUFB)       // 81920

template <int EPI>
__global__ __launch_bounds__(256, 2)
void mma_gemm(const __nv_bfloat16* __restrict__ Ah_, const __nv_bfloat16* __restrict__ Al_,
              const __nv_bfloat16* __restrict__ Bh_, const __nv_bfloat16* __restrict__ Bl_,
              const float* __restrict__ bias,
              float* __restrict__ Cf, __nv_bfloat16* __restrict__ Ch,
              __nv_bfloat16* __restrict__ Cl,
              int M, int N, int K)
{
    extern __shared__ char dsm[];
    const uint32_t sb0 = smem_u32(dsm);
    const int tid = threadIdx.x;
    const int wid = tid >> 5, lane = tid & 31;
    const int wm = wid >> 2, wn = wid & 3;          // warp tile: 64 x 32
    const int row0 = blockIdx.y * BMT, col0 = blockIdx.x * BNT;
    const int Kloc = K / gridDim.z;
    const int koff = blockIdx.z * Kloc;
    const int NS = Kloc / BKS;

    const __nv_bfloat16* Ahp = Ah_ + koff;
    const __nv_bfloat16* Alp = Al_ + koff;
    const __nv_bfloat16* Bhp = Bh_ + koff;
    const __nv_bfloat16* Blp = Bl_ + koff;

    float acc[4][4][4];
    #pragma unroll
    for (int i = 0; i < 4; i++)
        #pragma unroll
        for (int j = 0; j < 4; j++)
            #pragma unroll
            for (int k = 0; k < 4; k++) acc[i][j][k] = 0.f;

    // ldmatrix per-lane base offsets (bytes, within one stage buffer)
    const uint32_t aoff = (uint32_t)((wm * 64 + (lane & 15)) * 80 + (lane >> 4) * 16);
    const uint32_t boff = (uint32_t)((wn * 32 + ((lane >> 4) << 3) + (lane & 7)) * 80
                                     + ((lane >> 3) & 1) * 16);

    auto load_step = [&](int s) {
        const uint32_t sb = sb0 + (uint32_t)(s & 1) * BUFB;
        const int k0 = s * BKS;
        #pragma unroll
        for (int i = 0; i < 8; i++) {
            int u = i * 256 + tid;
            int mat = u >> 9;          // 0 Ah, 1 Al, 2 Bh, 3 Bl
            int v = u & 511;
            int r = v >> 2, c = v & 3;
            const __nv_bfloat16* src;
            if (mat == 0)      src = Ahp + (size_t)(row0 + r) * K + k0 + c * 8;
            else if (mat == 1) src = Alp + (size_t)(row0 + r) * K + k0 + c * 8;
            else if (mat == 2) src = Bhp + (size_t)(col0 + r) * K + k0 + c * 8;
            else               src = Blp + (size_t)(col0 + r) * K + k0 + c * 8;
            CP_ASYNC16(sb + (uint32_t)mat * MATB + (uint32_t)(r * 80 + c * 16), src);
        }
        CP_COMMIT();
    };

    load_step(0);

    for (int s = 0; s < NS; s++) {
        // only load(s) is outstanding here; after the barrier, buffer (s+1)&1
        // (last read in compute(s-1)) is free for load(s+1).
        CP_WAIT0();
        __syncthreads();
        if (s + 1 < NS) load_step(s + 1);

        const uint32_t sb = sb0 + (uint32_t)(s & 1) * BUFB;
        #pragma unroll
        for (int kh = 0; kh < 2; kh++) {     // two k16 halves of the k32 step
            uint32_t ah[4][4], al[4][4], bh[4][2], bl[4][2];
            #pragma unroll
            for (int mf = 0; mf < 4; mf++) {
                LDSM4(ah[mf], sb + aoff + (uint32_t)(mf * 1280 + kh * 32));
                LDSM4(al[mf], sb + MATB + aoff + (uint32_t)(mf * 1280 + kh * 32));
            }
            #pragma unroll
            for (int p = 0; p < 2; p++) {
                uint32_t t[4];
                LDSM4(t, sb + 2 * MATB + boff + (uint32_t)(p * 1280 + kh * 32));
                bh[2 * p][0] = t[0]; bh[2 * p][1] = t[1];
                bh[2 * p + 1][0] = t[2]; bh[2 * p + 1][1] = t[3];
                LDSM4(t, sb + 3 * MATB + boff + (uint32_t)(p * 1280 + kh * 32));
                bl[2 * p][0] = t[0]; bl[2 * p][1] = t[1];
                bl[2 * p + 1][0] = t[2]; bl[2 * p + 1][1] = t[3];
            }
            #pragma unroll
            for (int mf = 0; mf < 4; mf++)
                #pragma unroll
                for (int nf = 0; nf < 4; nf++) {
                    MMA_BF16(acc[mf][nf], ah[mf], bh[nf]);
                    MMA_BF16(acc[mf][nf], ah[mf], bl[nf]);
                    MMA_BF16(acc[mf][nf], al[mf], bh[nf]);
                }
        }
        __syncthreads();   // compute(s) done before next iter's load overwrites buf s&1... (next load writes (s+2)&1 == s&1)
    }

    // ---- epilogue: regs -> per-warp smem stage -> coalesced stores ----
    float* stg = (float*)dsm + wid * (16 * 33);
    const int gcol = col0 + wn * 32 + lane;
    const float bv = (EPI == 2) ? 0.f : bias[gcol];
    const int r1 = lane >> 2, c0 = (lane & 3) * 2;
    float* Cfz = (EPI == 2) ? Cf + (size_t)blockIdx.z * M * N : Cf;

    #pragma unroll
    for (int mf = 0; mf < 4; mf++) {
        #pragma unroll
        for (int nf = 0; nf < 4; nf++) {
            stg[r1 * 33 + nf * 8 + c0]           = acc[mf][nf][0];
            stg[r1 * 33 + nf * 8 + c0 + 1]       = acc[mf][nf][1];
            stg[(r1 + 8) * 33 + nf * 8 + c0]     = acc[mf][nf][2];
            stg[(r1 + 8) * 33 + nf * 8 + c0 + 1] = acc[mf][nf][3];
        }
        __syncwarp();
        const int grow = row0 + wm * 64 + mf * 16;
        #pragma unroll
        for (int r = 0; r < 16; r++) {
            float v = stg[r * 33 + lane] + bv;
            if (EPI == 1) {
                v = gelu_exact(v);
                __nv_bfloat16 h = __float2bfloat16(v);
                Ch[(size_t)(grow + r) * N + gcol] = h;
                Cl[(size_t)(grow + r) * N + gcol] = __float2bfloat16(v - __bfloat162float(h));
            } else {
                Cfz[(size_t)(grow + r) * N + gcol] = v;
            }
        }
        __syncwarp();
    }
}

// ============================================================
// weight transpose + bf16 hi/lo split: W[K][N] -> T{h,l}[N][K]
// ============================================================
__global__ void wconv_kernel(const float* __restrict__ W, __nv_bfloat16* __restrict__ Th,
                             __nv_bfloat16* __restrict__ Tl, int K, int N) {
    __shared__ float t[32][33];
    int k0 = blockIdx.x * 32, n0 = blockIdx.y * 32;
    int tx = threadIdx.x, ty = threadIdx.y;  // (32, 8)
    #pragma unroll
    for (int i = 0; i < 4; i++)
        t[ty + i * 8][tx] = W[(size_t)(k0 + ty + i * 8) * N + n0 + tx];
    __syncthreads();
    #pragma unroll
    for (int i = 0; i < 4; i++) {
        int n = n0 + ty + i * 8, k = k0 + tx;
        float v = t[tx][ty + i * 8];
        __nv_bfloat16 h, l;
        split_bf16(v, h, l);
        Th[(size_t)n * K + k] = h;
        Tl[(size_t)n * K + k] = l;
    }
}

// ---------------- elementwise: x = template + positional encoding ----------------
__global__ void add_pe_kernel(const float* __restrict__ t, float* __restrict__ x) {
    int idx = blockIdx.x * 256 + threadIdx.x;
    if (idx >= M_ * D_) return;
    int d = idx % D_;
    int s = (idx / D_) % S_;
    int i2 = d & ~1;
    float div = expf((float)i2 * (-9.210340371976184f / (float)D_));
    float ang = (float)s * div;
    float pe = (d & 1) ? cosf(ang) : sinf(ang);
    x[idx] = t[idx] + pe;
}

// ---------------- pooled = mean over P, emitted as bf16 hi/lo ----------------
__global__ void pool_kernel(const float* __restrict__ ps,
                            __nv_bfloat16* __restrict__ ph, __nv_bfloat16* __restrict__ pl) {
    int idx = blockIdx.x * 256 + threadIdx.x;
    if (idx >= M_ * D_) return;
    int bs = idx / D_;
    int c  = idx % D_;
    const float* base = ps + (size_t)bs * (P_ * D_) + c;
    float s = 0.f;
    #pragma unroll
    for (int p = 0; p < P_; p++) s += base[p * D_];
    float m = s * (1.0f / P_);
    __nv_bfloat16 h, l;
    split_bf16(m, h, l);
    ph[idx] = h; pl[idx] = l;
}

// ---------------- block-reduce helper ----------------
__device__ __forceinline__ float warp_sum(float v) {
    #pragma unroll
    for (int o = 16; o; o >>= 1) v += __shfl_down_sync(0xffffffffu, v, o);
    return v;
}

// ---------------- LayerNorm (row length 768) ----------------
// t = x (+ res) (+ res2) (+ colbias);  out = LN(t)*g + b;  optional bf16 hi/lo out
template <int BF16OUT>
__global__ void ln_kernel(const float* __restrict__ x, const float* __restrict__ res,
                          const float* __restrict__ res2,
                          const float* __restrict__ colbias,
                          const float* __restrict__ g, const float* __restrict__ b,
                          float* __restrict__ out,
                          __nv_bfloat16* __restrict__ oh, __nv_bfloat16* __restrict__ ol) {
    const int row = blockIdx.x;
    const int tid = threadIdx.x;  // 256
    const float* xr = x + (size_t)row * D_;
    const float* rr = res ? res + (size_t)row * D_ : nullptr;
    const float* r2 = res2 ? res2 + (size_t)row * D_ : nullptr;

    float v[3];
    float s = 0.f, s2 = 0.f;
    #pragma unroll
    for (int i = 0; i < 3; i++) {
        int c = tid + i * 256;
        float t = xr[c];
        if (rr) t += rr[c];
        if (r2) t += r2[c];
        if (colbias) t += colbias[c];
        v[i] = t; s += t; s2 += t * t;
    }

    __shared__ float red[2][8];
    __shared__ float stat[2];
    int lane = tid & 31, wid = tid >> 5;
    s = warp_sum(s); s2 = warp_sum(s2);
    if (lane == 0) { red[0][wid] = s; red[1][wid] = s2; }
    __syncthreads();
    if (wid == 0) {
        float a = (lane < 8) ? red[0][lane] : 0.f;
        float c = (lane < 8) ? red[1][lane] : 0.f;
        a = warp_sum(a); c = warp_sum(c);
        if (lane == 0) {
            float mean = a * (1.0f / D_);
            float var = c * (1.0f / D_) - mean * mean;
            stat[0] = mean;
            stat[1] = rsqrtf(var + EPS_);
        }
    }
    __syncthreads();
    float mean = stat[0], inv = stat[1];
    float* orow = out + (size_t)row * D_;
    #pragma unroll
    for (int i = 0; i < 3; i++) {
        int c = tid + i * 256;
        float o = (v[i] - mean) * inv * g[c] + b[c];
        orow[c] = o;
        if (BF16OUT) {
            __nv_bfloat16 h, l;
            split_bf16(o, h, l);
            oh[(size_t)row * D_ + c] = h;
            ol[(size_t)row * D_ + c] = l;
        }
    }
}

// ---------------- param_bias[b,h] = (pe_bh @ pe_bh^T) * inv_sqrt_hd ----------------
__global__ __launch_bounds__(256)
void pbias_kernel(const float* __restrict__ enc, float* __restrict__ pbias) {
    __shared__ float Es[112 * 97];
    const int b = blockIdx.x >> 3;
    const int h = blockIdx.x & 7;
    const int tid = threadIdx.x;
    const float* src = enc + (size_t)(b * S_) * D_ + h * HD_;

    for (int i = tid; i < 112 * 96; i += 256) {
        int s = i / 96, d = i - s * 96;
        Es[s * 97 + d] = (s < S_) ? src[(size_t)s * D_ + d] : 0.f;
    }
    __syncthreads();

    const int tx = tid & 15, ty = tid >> 4;
    float acc[7][7];
    #pragma unroll
    for (int ii = 0; ii < 7; ii++)
        #pragma unroll
        for (int jj = 0; jj < 7; jj++) acc[ii][jj] = 0.f;

    for (int d = 0; d < 96; d++) {
        float a[7], bb[7];
        #pragma unroll
        for (int ii = 0; ii < 7; ii++) a[ii]  = Es[(ty + 16 * ii) * 97 + d];
        #pragma unroll
        for (int jj = 0; jj < 7; jj++) bb[jj] = Es[(tx + 16 * jj) * 97 + d];
        #pragma unroll
        for (int ii = 0; ii < 7; ii++)
            #pragma unroll
            for (int jj = 0; jj < 7; jj++) acc[ii][jj] += a[ii] * bb[jj];
    }

    float* dst = pbias + (size_t)blockIdx.x * (S_ * S_);
    #pragma unroll
    for (int ii = 0; ii < 7; ii++) {
        int i = ty + 16 * ii;
        if (i >= S_) continue;
        #pragma unroll
        for (int jj = 0; jj < 7; jj++) {
            int j = tx + 16 * jj;
            if (j < S_) dst[i * S_ + j] = acc[ii][jj] * INV_SQRT_HD;
        }
    }
}

// ---------------- fused attention per (b,h) ----------------
#define ATTN_SMEM ((112 * 97 + 112 * 101) * 4)
__global__ __launch_bounds__(256)
void attn_kernel(const float* __restrict__ x, const float* __restrict__ pbias,
                 float* __restrict__ out) {
    extern __shared__ float smem[];
    float* Qs = smem;               // [112][97]
    float* Ss = smem + 112 * 97;    // [112][101]

    const int b = blockIdx.x >> 3;
    const int h = blockIdx.x & 7;
    const int tid = threadIdx.x;
    const float* xb = x + (size_t)(b * S_) * D_ + h * HD_;

    for (int i = tid; i < 112 * 96; i += 256) {
        int s = i / 96, d = i - s * 96;
        Qs[s * 97 + d] = (s < S_) ? xb[(size_t)s * D_ + d] : 0.f;
    }
    __syncthreads();

    const int tx = tid & 15, ty = tid >> 4;
    {
        float acc[7][7];
        #pragma unroll
        for (int ii = 0; ii < 7; ii++)
            #pragma unroll
            for (int jj = 0; jj < 7; jj++) acc[ii][jj] = 0.f;

        for (int d = 0; d < 96; d++) {
            float a[7], bb[7];
            #pragma unroll
            for (int ii = 0; ii < 7; ii++) a[ii]  = Qs[(ty + 16 * ii) * 97 + d];
            #pragma unroll
            for (int jj = 0; jj < 7; jj++) bb[jj] = Qs[(tx + 16 * jj) * 97 + d];
            #pragma unroll
            for (int ii = 0; ii < 7; ii++)
                #pragma unroll
                for (int jj = 0; jj < 7; jj++) acc[ii][jj] += a[ii] * bb[jj];
        }
        const float* pb = pbias + (size_t)blockIdx.x * (S_ * S_);
        #pragma unroll
        for (int ii = 0; ii < 7; ii++) {
            int i = ty + 16 * ii;
            if (i >= S_) continue;
            #pragma unroll
            for (int jj = 0; jj < 7; jj++) {
                int j = tx + 16 * jj;
                if (j < S_)
                    Ss[i * 101 + j] = acc[ii][jj] * INV_SQRT_HD + pb[i * S_ + j];
            }
        }
    }
    __syncthreads();

    if (tid < S_) {
        float* row = Ss + tid * 101;
        float m = -1e30f;
        for (int j = 0; j < S_; j++) m = fmaxf(m, row[j]);
        float sum = 0.f;
        for (int j = 0; j < S_; j++) { float e = expf(row[j] - m); row[j] = e; sum += e; }
        float inv = 1.0f / sum;
        for (int j = 0; j < S_; j++) row[j] *= inv;
    }
    __syncthreads();

    {
        float acc[7][6];
        #pragma unroll
        for (int ii = 0; ii < 7; ii++)
            #pragma unroll
            for (int jj = 0; jj < 6; jj++) acc[ii][jj] = 0.f;

        for (int j = 0; j < S_; j++) {
            float a[7], bb[6];
            #pragma unroll
            for (int ii = 0; ii < 7; ii++) a[ii]  = Ss[(ty + 16 * ii) * 101 + j];
            #pragma unroll
            for (int jj = 0; jj < 6; jj++) bb[jj] = Qs[j * 97 + tx + 16 * jj];
            #pragma unroll
            for (int ii = 0; ii < 7; ii++)
                #pragma unroll
                for (int jj = 0; jj < 6; jj++) acc[ii][jj] += a[ii] * bb[jj];
        }
        float* dst = out + (size_t)(b * S_) * D_ + h * HD_;
        #pragma unroll
        for (int ii = 0; ii < 7; ii++) {
            int i = ty + 16 * ii;
            if (i >= S_) continue;
            #pragma unroll
            for (int jj = 0; jj < 6; jj++) {
                int dd = tx + 16 * jj;
                dst[(size_t)i * D_ + dd] = acc[ii][jj];
            }
        }
    }
}

// ---------------- final classifier ----------------
__global__ void fc_kernel(const float* __restrict__ x, const float* __restrict__ Wfc,
                          const float* __restrict__ bfc, float* __restrict__ out) {
    const int b = blockIdx.x;
    const int tid = threadIdx.x;
    const float* xr = x + (size_t)b * (S_ * D_);
    float a0 = 0.f, a1 = 0.f;
    for (int i = tid; i < S_ * D_; i += 256) {
        float v = xr[i];
        a0 += v * Wfc[2 * i];
        a1 += v * Wfc[2 * i + 1];
    }
    __shared__ float red[2][8];
    int lane = tid & 31, wid = tid >> 5;
    a0 = warp_sum(a0); a1 = warp_sum(a1);
    if (lane == 0) { red[0][wid] = a0; red[1][wid] = a1; }
    __syncthreads();
    if (wid == 0) {
        float r0 = (lane < 8) ? red[0][lane] : 0.f;
        float r1 = (lane < 8) ? red[1][lane] : 0.f;
        r0 = warp_sum(r0); r1 = warp_sum(r1);
        if (lane == 0) {
            out[2 * b + 0] = r0 + bfc[0];
            out[2 * b + 1] = r1 + bfc[1];
        }
    }
}

// ---------------- launch ----------------
extern "C" void kernel_launch(void* const* d_in, const int* in_sizes, int n_in,
                              void* d_out, int out_size) {
    const float* tseq = (const float*)d_in[0];
    const float* pseq = (const float*)d_in[1];
    const float* Wc  = (const float*)d_in[2];
    const float* bc  = (const float*)d_in[3];
    const float* gp  = (const float*)d_in[4];
    const float* bp  = (const float*)d_in[5];
    const float* W1  = (const float*)d_in[6];
    const float* b1  = (const float*)d_in[7];
    const float* W2  = (const float*)d_in[8];
    const float* b2  = (const float*)d_in[9];
    const float* g1  = (const float*)d_in[10];
    const float* bn1 = (const float*)d_in[11];
    const float* g2  = (const float*)d_in[12];
    const float* bn2 = (const float*)d_in[13];
    const float* Wfc = (const float*)d_in[14];
    const float* bfc = (const float*)d_in[15];
    float* out = (float*)d_out;

    float *x, *enc, *pbias, *part;
    __nv_bfloat16 *xhi, *xlo, *phi, *plo, *ffhi, *fflo;
    __nv_bfloat16 *w1h, *w1l, *w2h, *w2l, *wch, *wcl;
    cudaGetSymbolAddress((void**)&x, g_x);
    cudaGetSymbolAddress((void**)&enc, g_enc);
    cudaGetSymbolAddress((void**)&pbias, g_pbias);
    cudaGetSymbolAddress((void**)&part, g_part);
    cudaGetSymbolAddress((void**)&xhi, g_xhi);
    cudaGetSymbolAddress((void**)&xlo, g_xlo);
    cudaGetSymbolAddress((void**)&phi, g_phi);
    cudaGetSymbolAddress((void**)&plo, g_plo);
    cudaGetSymbolAddress((void**)&ffhi, g_ffhi);
    cudaGetSymbolAddress((void**)&fflo, g_fflo);
    cudaGetSymbolAddress((void**)&w1h, g_w1h);
    cudaGetSymbolAddress((void**)&w1l, g_w1l);
    cudaGetSymbolAddress((void**)&w2h, g_w2h);
    cudaGetSymbolAddress((void**)&w2l, g_w2l);
    cudaGetSymbolAddress((void**)&wch, g_wch);
    cudaGetSymbolAddress((void**)&wcl, g_wcl);
    float* part0 = part;
    float* part1 = part + (size_t)M_ * D_;

    cudaFuncSetAttribute(attn_kernel, cudaFuncAttributeMaxDynamicSharedMemorySize, ATTN_SMEM);
    cudaFuncSetAttribute(mma_gemm<1>, cudaFuncAttributeMaxDynamicSharedMemorySize, GEMM_SMEM);
    cudaFuncSetAttribute(mma_gemm<2>, cudaFuncAttributeMaxDynamicSharedMemorySize, GEMM_SMEM);

    // weight transpose + split (tiny, one-time per launch)
    wconv_kernel<<<dim3(D_ / 32, FF_ / 32), dim3(32, 8)>>>(W1, w1h, w1l, D_, FF_);
    wconv_kernel<<<dim3(FF_ / 32, D_ / 32), dim3(32, 8)>>>(W2, w2h, w2l, FF_, D_);
    wconv_kernel<<<dim3(D_ / 32, D_ / 32),  dim3(32, 8)>>>(Wc, wch, wcl, D_, D_);

    const int total = M_ * D_;
    add_pe_kernel<<<(total + 255) / 256, 256>>>(tseq, x);
    pool_kernel<<<(total + 255) / 256, 256>>>(pseq, phi, plo);

    // param encoder: enc = LN(pooled @ Wc + bc)  (split-K=2 -> partial buffers)
    mma_gemm<2><<<dim3(D_ / BNT, M_ / BMT, 2), 256, GEMM_SMEM>>>(
        phi, plo, wch, wcl, nullptr, part0, nullptr, nullptr, M_, D_, D_);
    ln_kernel<0><<<M_, 256>>>(part0, part1, nullptr, bc, gp, bp, enc, nullptr, nullptr);

    // layer-invariant attention bias
    pbias_kernel<<<B_ * H_, 256>>>(enc, pbias);

    for (int l = 0; l < NLAYERS; l++) {
        attn_kernel<<<B_ * H_, 256, ATTN_SMEM>>>(x, pbias, part0);
        ln_kernel<1><<<M_, 256>>>(x, part0, nullptr, nullptr, g1, bn1, x, xhi, xlo);
        mma_gemm<1><<<dim3(FF_ / BNT, M_ / BMT), 256, GEMM_SMEM>>>(
            xhi, xlo, w1h, w1l, b1, nullptr, ffhi, fflo, M_, FF_, D_);
        // FFN2: split-K=2 -> two fp32 partial buffers, bias b2 folded into LN
        mma_gemm<2><<<dim3(D_ / BNT, M_ / BMT, 2), 256, GEMM_SMEM>>>(
            ffhi, fflo, w2h, w2l, nullptr, part0, nullptr, nullptr, M_, D_, FF_);
        ln_kernel<0><<<M_, 256>>>(x, part0, part1, b2, g2, bn2, x, nullptr, nullptr);
    }

    fc_kernel<<<B_, 256>>>(x, Wfc, bfc, out);
}

// round 6
// speedup vs baseline: 1.5354x; 1.2903x over previous
#include <cuda_runtime.h>
#include <cuda_fp16.h>
#include <math.h>
#include <stdint.h>

// ---------------- problem constants ----------------
#define B_   64
#define S_   100
#define D_   768
#define H_   8
#define HD_  96
#define P_   8
#define FF_  3072
#define M_   (B_ * S_)            // 6400 rows
#define NLAYERS 4
#define EPS_ 1e-5f
#define INV_SQRT_HD 0.10206207261596575f   // 1/sqrt(96)

// ---------------- device scratch ----------------
__device__ float g_x[M_ * D_];
__device__ float g_enc[M_ * D_];
__device__ float g_pbias[B_ * H_ * S_ * S_];
__device__ float g_part[2][M_ * D_];   // split-K fp32 partials

__device__ __half g_xhi[M_ * D_];
__device__ __half g_xlo[M_ * D_];
__device__ __half g_phi[M_ * D_];
__device__ __half g_plo[M_ * D_];
__device__ __half g_ffhi[(size_t)M_ * FF_];
__device__ __half g_fflo[(size_t)M_ * FF_];
__device__ __half g_w1h[(size_t)FF_ * D_];   // [N=3072][K=768] fp16
__device__ __half g_w2h[(size_t)D_ * FF_];   // [N=768][K=3072] fp16
__device__ __half g_wch[(size_t)D_ * D_];    // [N=768][K=768]  fp16

// ============================================================
// PTX helpers (mma.sync / ldmatrix / cp.async — all baseline sm_80+)
// ============================================================
__device__ __forceinline__ uint32_t smem_u32(const void* p) {
    uint32_t a;
    asm("{ .reg .u64 t; cvta.to.shared.u64 t, %1; cvt.u32.u64 %0, t; }" : "=r"(a) : "l"(p));
    return a;
}

#define CP_ASYNC16(dst, src) \
    asm volatile("cp.async.cg.shared.global [%0], [%1], 16;\n" :: "r"(dst), "l"(src) : "memory")
#define CP_COMMIT() asm volatile("cp.async.commit_group;\n" ::: "memory")
#define CP_WAIT0()  asm volatile("cp.async.wait_group 0;\n" ::: "memory")

#define LDSM4(r, addr) \
    asm volatile("ldmatrix.sync.aligned.m8n8.x4.shared.b16 {%0,%1,%2,%3}, [%4];" \
        : "=r"((r)[0]), "=r"((r)[1]), "=r"((r)[2]), "=r"((r)[3]) : "r"(addr))

#define MMA_F16(c, a, b) \
    asm volatile("mma.sync.aligned.m16n8k16.row.col.f32.f16.f16.f32 " \
        "{%0,%1,%2,%3}, {%4,%5,%6,%7}, {%8,%9}, {%0,%1,%2,%3};" \
        : "+f"((c)[0]), "+f"((c)[1]), "+f"((c)[2]), "+f"((c)[3]) \
        : "r"((a)[0]), "r"((a)[1]), "r"((a)[2]), "r"((a)[3]), "r"((b)[0]), "r"((b)[1]))

__device__ __forceinline__ float gelu_exact(float v) {
    return 0.5f * v * (1.0f + erff(v * 0.70710678118654752f));
}
__device__ __forceinline__ void split_f16(float v, __half& h, __half& l) {
    h = __float2half(v);
    l = __float2half(v - __half2float(h));
}

// ============================================================
// GEMM: C[M,N] = A[M,K] @ B^T[N,K] (+ bias)
// A = Ah + Al (fp16 pair, exact to 2^-22), B single fp16.
// C = Ah*B + Al*B  (2 MMAs per fragment; only error = B fp16 rounding)
// EPI 1: bias + gelu -> fp16 hi/lo out (Ch, Cl).
// EPI 2: plain fp32 partial store, NO bias; z-th split writes Cf + z*M*N.
// Double-buffered (2 stages, 60KB smem), 2 CTAs/SM, warp tile 32x64.
// ============================================================
#define BMT 128
#define BNT 128
#define BKS 32
#define MATB 10240u                // 128*40*2 bytes (rows padded to 40 fp16)
#define BUFB (3 * MATB)            // 30720: Ah, Al, B
#define GEMM_SMEM (2 * BUFB)       // 61440

template <int EPI>
__global__ __launch_bounds__(256, 2)
void mma_gemm(const __half* __restrict__ Ah_, const __half* __restrict__ Al_,
              const __half* __restrict__ Bh_,
              const float* __restrict__ bias,
              float* __restrict__ Cf, __half* __restrict__ Ch, __half* __restrict__ Cl,
              int M, int N, int K)
{
    extern __shared__ char dsm[];
    const uint32_t sb0 = smem_u32(dsm);
    const int tid = threadIdx.x;
    const int wid = tid >> 5, lane = tid & 31;
    const int wm = wid >> 1, wn = wid & 1;          // warp tile: 32 x 64
    const int row0 = blockIdx.y * BMT, col0 = blockIdx.x * BNT;
    const int Kloc = K / gridDim.z;
    const int koff = blockIdx.z * Kloc;
    const int NS = Kloc / BKS;

    const __half* Ahp = Ah_ + koff;
    const __half* Alp = Al_ + koff;
    const __half* Bhp = Bh_ + koff;

    float acc[2][8][4];
    #pragma unroll
    for (int i = 0; i < 2; i++)
        #pragma unroll
        for (int j = 0; j < 8; j++)
            #pragma unroll
            for (int k = 0; k < 4; k++) acc[i][j][k] = 0.f;

    // ldmatrix per-lane base offsets (bytes, within one stage buffer)
    // A m16k16 frag: lanes 0-15 rows, lanes 16-31 same rows at k+8
    const uint32_t aoff = (uint32_t)((wm * 32 + (lane & 15)) * 80 + (lane >> 4) * 16);
    // B: two n8k16 frags per LDSM4 (16 n-rows x k16)
    const uint32_t boff = (uint32_t)((wn * 64 + ((lane >> 4) << 3) + (lane & 7)) * 80
                                     + ((lane >> 3) & 1) * 16);

    auto load_step = [&](int s) {
        const uint32_t sb = sb0 + (uint32_t)(s & 1) * BUFB;
        const int k0 = s * BKS;
        #pragma unroll
        for (int i = 0; i < 6; i++) {
            int u = i * 256 + tid;
            int mat = u >> 9;          // 0 Ah, 1 Al, 2 B
            int v = u & 511;
            int r = v >> 2, c = v & 3;
            const __half* src;
            if (mat == 0)      src = Ahp + (size_t)(row0 + r) * K + k0 + c * 8;
            else if (mat == 1) src = Alp + (size_t)(row0 + r) * K + k0 + c * 8;
            else               src = Bhp + (size_t)(col0 + r) * K + k0 + c * 8;
            CP_ASYNC16(sb + (uint32_t)mat * MATB + (uint32_t)(r * 80 + c * 16), src);
        }
        CP_COMMIT();
    };

    load_step(0);

    for (int s = 0; s < NS; s++) {
        CP_WAIT0();
        __syncthreads();
        if (s + 1 < NS) load_step(s + 1);

        const uint32_t sb = sb0 + (uint32_t)(s & 1) * BUFB;
        #pragma unroll
        for (int kh = 0; kh < 2; kh++) {     // two k16 halves of the k32 step
            uint32_t ah[2][4], al[2][4], b[8][2];
            #pragma unroll
            for (int mf = 0; mf < 2; mf++) {
                LDSM4(ah[mf], sb + aoff + (uint32_t)(mf * 1280 + kh * 32));
                LDSM4(al[mf], sb + MATB + aoff + (uint32_t)(mf * 1280 + kh * 32));
            }
            #pragma unroll
            for (int p = 0; p < 4; p++) {
                uint32_t t[4];
                LDSM4(t, sb + 2 * MATB + boff + (uint32_t)(p * 1280 + kh * 32));
                b[2 * p][0] = t[0]; b[2 * p][1] = t[1];
                b[2 * p + 1][0] = t[2]; b[2 * p + 1][1] = t[3];
            }
            #pragma unroll
            for (int mf = 0; mf < 2; mf++)
                #pragma unroll
                for (int nf = 0; nf < 8; nf++) {
                    MMA_F16(acc[mf][nf], ah[mf], b[nf]);
                    MMA_F16(acc[mf][nf], al[mf], b[nf]);
                }
        }
        __syncthreads();
    }

    // ---- epilogue: regs -> per-warp smem stage (16x65 fp32) -> coalesced stores ----
    float* stg = (float*)dsm + wid * (16 * 65);
    const int gcol0 = col0 + wn * 64;
    const float bv0 = (EPI == 2) ? 0.f : bias[gcol0 + lane];
    const float bv1 = (EPI == 2) ? 0.f : bias[gcol0 + 32 + lane];
    const int r1 = lane >> 2, c0 = (lane & 3) * 2;
    float* Cfz = (EPI == 2) ? Cf + (size_t)blockIdx.z * M * N : Cf;

    #pragma unroll
    for (int mf = 0; mf < 2; mf++) {
        #pragma unroll
        for (int nf = 0; nf < 8; nf++) {
            stg[r1 * 65 + nf * 8 + c0]           = acc[mf][nf][0];
            stg[r1 * 65 + nf * 8 + c0 + 1]       = acc[mf][nf][1];
            stg[(r1 + 8) * 65 + nf * 8 + c0]     = acc[mf][nf][2];
            stg[(r1 + 8) * 65 + nf * 8 + c0 + 1] = acc[mf][nf][3];
        }
        __syncwarp();
        const int grow = row0 + wm * 32 + mf * 16;
        #pragma unroll
        for (int r = 0; r < 16; r++) {
            float v0 = stg[r * 65 + lane] + bv0;
            float v1 = stg[r * 65 + 32 + lane] + bv1;
            if (EPI == 1) {
                v0 = gelu_exact(v0);
                v1 = gelu_exact(v1);
                __half h0, l0, h1, l1;
                split_f16(v0, h0, l0);
                split_f16(v1, h1, l1);
                size_t base = (size_t)(grow + r) * N + gcol0;
                Ch[base + lane] = h0;      Cl[base + lane] = l0;
                Ch[base + 32 + lane] = h1; Cl[base + 32 + lane] = l1;
            } else {
                size_t base = (size_t)(grow + r) * N + gcol0;
                Cfz[base + lane] = v0;
                Cfz[base + 32 + lane] = v1;
            }
        }
        __syncwarp();
    }
}

// ============================================================
// weight transpose + fp16 convert: W[K][N] -> T[N][K]
// ============================================================
__global__ void wconv_kernel(const float* __restrict__ W, __half* __restrict__ Th,
                             int K, int N) {
    __shared__ float t[32][33];
    int k0 = blockIdx.x * 32, n0 = blockIdx.y * 32;
    int tx = threadIdx.x, ty = threadIdx.y;  // (32, 8)
    #pragma unroll
    for (int i = 0; i < 4; i++)
        t[ty + i * 8][tx] = W[(size_t)(k0 + ty + i * 8) * N + n0 + tx];
    __syncthreads();
    #pragma unroll
    for (int i = 0; i < 4; i++) {
        int n = n0 + ty + i * 8, k = k0 + tx;
        Th[(size_t)n * K + k] = __float2half(t[tx][ty + i * 8]);
    }
}

// ---------------- elementwise: x = template + positional encoding ----------------
__global__ void add_pe_kernel(const float* __restrict__ t, float* __restrict__ x) {
    int idx = blockIdx.x * 256 + threadIdx.x;
    if (idx >= M_ * D_) return;
    int d = idx % D_;
    int s = (idx / D_) % S_;
    int i2 = d & ~1;
    float div = expf((float)i2 * (-9.210340371976184f / (float)D_));
    float ang = (float)s * div;
    float pe = (d & 1) ? cosf(ang) : sinf(ang);
    x[idx] = t[idx] + pe;
}

// ---------------- pooled = mean over P, emitted as fp16 hi/lo ----------------
__global__ void pool_kernel(const float* __restrict__ ps,
                            __half* __restrict__ ph, __half* __restrict__ pl) {
    int idx = blockIdx.x * 256 + threadIdx.x;
    if (idx >= M_ * D_) return;
    int bs = idx / D_;
    int c  = idx % D_;
    const float* base = ps + (size_t)bs * (P_ * D_) + c;
    float s = 0.f;
    #pragma unroll
    for (int p = 0; p < P_; p++) s += base[p * D_];
    float m = s * (1.0f / P_);
    __half h, l;
    split_f16(m, h, l);
    ph[idx] = h; pl[idx] = l;
}

// ---------------- block-reduce helper ----------------
__device__ __forceinline__ float warp_sum(float v) {
    #pragma unroll
    for (int o = 16; o; o >>= 1) v += __shfl_down_sync(0xffffffffu, v, o);
    return v;
}

// ---------------- LayerNorm (row length 768) ----------------
// t = x (+ res) (+ res2) (+ colbias);  out = LN(t)*g + b;  optional fp16 hi/lo out
template <int F16OUT>
__global__ void ln_kernel(const float* __restrict__ x, const float* __restrict__ res,
                          const float* __restrict__ res2,
                          const float* __restrict__ colbias,
                          const float* __restrict__ g, const float* __restrict__ b,
                          float* __restrict__ out,
                          __half* __restrict__ oh, __half* __restrict__ ol) {
    const int row = blockIdx.x;
    const int tid = threadIdx.x;  // 256
    const float* xr = x + (size_t)row * D_;
    const float* rr = res ? res + (size_t)row * D_ : nullptr;
    const float* r2 = res2 ? res2 + (size_t)row * D_ : nullptr;

    float v[3];
    float s = 0.f, s2 = 0.f;
    #pragma unroll
    for (int i = 0; i < 3; i++) {
        int c = tid + i * 256;
        float t = xr[c];
        if (rr) t += rr[c];
        if (r2) t += r2[c];
        if (colbias) t += colbias[c];
        v[i] = t; s += t; s2 += t * t;
    }

    __shared__ float red[2][8];
    __shared__ float stat[2];
    int lane = tid & 31, wid = tid >> 5;
    s = warp_sum(s); s2 = warp_sum(s2);
    if (lane == 0) { red[0][wid] = s; red[1][wid] = s2; }
    __syncthreads();
    if (wid == 0) {
        float a = (lane < 8) ? red[0][lane] : 0.f;
        float c = (lane < 8) ? red[1][lane] : 0.f;
        a = warp_sum(a); c = warp_sum(c);
        if (lane == 0) {
            float mean = a * (1.0f / D_);
            float var = c * (1.0f / D_) - mean * mean;
            stat[0] = mean;
            stat[1] = rsqrtf(var + EPS_);
        }
    }
    __syncthreads();
    float mean = stat[0], inv = stat[1];
    float* orow = out + (size_t)row * D_;
    #pragma unroll
    for (int i = 0; i < 3; i++) {
        int c = tid + i * 256;
        float o = (v[i] - mean) * inv * g[c] + b[c];
        orow[c] = o;
        if (F16OUT) {
            __half h, l;
            split_f16(o, h, l);
            oh[(size_t)row * D_ + c] = h;
            ol[(size_t)row * D_ + c] = l;
        }
    }
}

// ---------------- param_bias[b,h] = (pe_bh @ pe_bh^T) * inv_sqrt_hd ----------------
__global__ __launch_bounds__(256)
void pbias_kernel(const float* __restrict__ enc, float* __restrict__ pbias) {
    __shared__ float Es[112 * 97];
    const int b = blockIdx.x >> 3;
    const int h = blockIdx.x & 7;
    const int tid = threadIdx.x;
    const float* src = enc + (size_t)(b * S_) * D_ + h * HD_;

    for (int i = tid; i < 112 * 96; i += 256) {
        int s = i / 96, d = i - s * 96;
        Es[s * 97 + d] = (s < S_) ? src[(size_t)s * D_ + d] : 0.f;
    }
    __syncthreads();

    const int tx = tid & 15, ty = tid >> 4;
    float acc[7][7];
    #pragma unroll
    for (int ii = 0; ii < 7; ii++)
        #pragma unroll
        for (int jj = 0; jj < 7; jj++) acc[ii][jj] = 0.f;

    for (int d = 0; d < 96; d++) {
        float a[7], bb[7];
        #pragma unroll
        for (int ii = 0; ii < 7; ii++) a[ii]  = Es[(ty + 16 * ii) * 97 + d];
        #pragma unroll
        for (int jj = 0; jj < 7; jj++) bb[jj] = Es[(tx + 16 * jj) * 97 + d];
        #pragma unroll
        for (int ii = 0; ii < 7; ii++)
            #pragma unroll
            for (int jj = 0; jj < 7; jj++) acc[ii][jj] += a[ii] * bb[jj];
    }

    float* dst = pbias + (size_t)blockIdx.x * (S_ * S_);
    #pragma unroll
    for (int ii = 0; ii < 7; ii++) {
        int i = ty + 16 * ii;
        if (i >= S_) continue;
        #pragma unroll
        for (int jj = 0; jj < 7; jj++) {
            int j = tx + 16 * jj;
            if (j < S_) dst[i * S_ + j] = acc[ii][jj] * INV_SQRT_HD;
        }
    }
}

// ---------------- fused attention per (b,h) ----------------
#define ATTN_SMEM ((112 * 97 + 112 * 101) * 4)
__global__ __launch_bounds__(256)
void attn_kernel(const float* __restrict__ x, const float* __restrict__ pbias,
                 float* __restrict__ out) {
    extern __shared__ float smem[];
    float* Qs = smem;               // [112][97]
    float* Ss = smem + 112 * 97;    // [112][101]

    const int b = blockIdx.x >> 3;
    const int h = blockIdx.x & 7;
    const int tid = threadIdx.x;
    const float* xb = x + (size_t)(b * S_) * D_ + h * HD_;

    for (int i = tid; i < 112 * 96; i += 256) {
        int s = i / 96, d = i - s * 96;
        Qs[s * 97 + d] = (s < S_) ? xb[(size_t)s * D_ + d] : 0.f;
    }
    __syncthreads();

    const int tx = tid & 15, ty = tid >> 4;
    {
        float acc[7][7];
        #pragma unroll
        for (int ii = 0; ii < 7; ii++)
            #pragma unroll
            for (int jj = 0; jj < 7; jj++) acc[ii][jj] = 0.f;

        for (int d = 0; d < 96; d++) {
            float a[7], bb[7];
            #pragma unroll
            for (int ii = 0; ii < 7; ii++) a[ii]  = Qs[(ty + 16 * ii) * 97 + d];
            #pragma unroll
            for (int jj = 0; jj < 7; jj++) bb[jj] = Qs[(tx + 16 * jj) * 97 + d];
            #pragma unroll
            for (int ii = 0; ii < 7; ii++)
                #pragma unroll
                for (int jj = 0; jj < 7; jj++) acc[ii][jj] += a[ii] * bb[jj];
        }
        const float* pb = pbias + (size_t)blockIdx.x * (S_ * S_);
        #pragma unroll
        for (int ii = 0; ii < 7; ii++) {
            int i = ty + 16 * ii;
            if (i >= S_) continue;
            #pragma unroll
            for (int jj = 0; jj < 7; jj++) {
                int j = tx + 16 * jj;
                if (j < S_)
                    Ss[i * 101 + j] = acc[ii][jj] * INV_SQRT_HD + pb[i * S_ + j];
            }
        }
    }
    __syncthreads();

    if (tid < S_) {
        float* row = Ss + tid * 101;
        float m = -1e30f;
        for (int j = 0; j < S_; j++) m = fmaxf(m, row[j]);
        float sum = 0.f;
        for (int j = 0; j < S_; j++) { float e = expf(row[j] - m); row[j] = e; sum += e; }
        float inv = 1.0f / sum;
        for (int j = 0; j < S_; j++) row[j] *= inv;
    }
    __syncthreads();

    {
        float acc[7][6];
        #pragma unroll
        for (int ii = 0; ii < 7; ii++)
            #pragma unroll
            for (int jj = 0; jj < 6; jj++) acc[ii][jj] = 0.f;

        for (int j = 0; j < S_; j++) {
            float a[7], bb[6];
            #pragma unroll
            for (int ii = 0; ii < 7; ii++) a[ii]  = Ss[(ty + 16 * ii) * 101 + j];
            #pragma unroll
            for (int jj = 0; jj < 6; jj++) bb[jj] = Qs[j * 97 + tx + 16 * jj];
            #pragma unroll
            for (int ii = 0; ii < 7; ii++)
                #pragma unroll
                for (int jj = 0; jj < 6; jj++) acc[ii][jj] += a[ii] * bb[jj];
        }
        float* dst = out + (size_t)(b * S_) * D_ + h * HD_;
        #pragma unroll
        for (int ii = 0; ii < 7; ii++) {
            int i = ty + 16 * ii;
            if (i >= S_) continue;
            #pragma unroll
            for (int jj = 0; jj < 6; jj++) {
                int dd = tx + 16 * jj;
                dst[(size_t)i * D_ + dd] = acc[ii][jj];
            }
        }
    }
}

// ---------------- final classifier ----------------
__global__ void fc_kernel(const float* __restrict__ x, const float* __restrict__ Wfc,
                          const float* __restrict__ bfc, float* __restrict__ out) {
    const int b = blockIdx.x;
    const int tid = threadIdx.x;
    const float* xr = x + (size_t)b * (S_ * D_);
    float a0 = 0.f, a1 = 0.f;
    for (int i = tid; i < S_ * D_; i += 256) {
        float v = xr[i];
        a0 += v * Wfc[2 * i];
        a1 += v * Wfc[2 * i + 1];
    }
    __shared__ float red[2][8];
    int lane = tid & 31, wid = tid >> 5;
    a0 = warp_sum(a0); a1 = warp_sum(a1);
    if (lane == 0) { red[0][wid] = a0; red[1][wid] = a1; }
    __syncthreads();
    if (wid == 0) {
        float r0 = (lane < 8) ? red[0][lane] : 0.f;
        float r1 = (lane < 8) ? red[1][lane] : 0.f;
        r0 = warp_sum(r0); r1 = warp_sum(r1);
        if (lane == 0) {
            out[2 * b + 0] = r0 + bfc[0];
            out[2 * b + 1] = r1 + bfc[1];
        }
    }
}

// ---------------- launch ----------------
extern "C" void kernel_launch(void* const* d_in, const int* in_sizes, int n_in,
                              void* d_out, int out_size) {
    const float* tseq = (const float*)d_in[0];
    const float* pseq = (const float*)d_in[1];
    const float* Wc  = (const float*)d_in[2];
    const float* bc  = (const float*)d_in[3];
    const float* gp  = (const float*)d_in[4];
    const float* bp  = (const float*)d_in[5];
    const float* W1  = (const float*)d_in[6];
    const float* b1  = (const float*)d_in[7];
    const float* W2  = (const float*)d_in[8];
    const float* b2  = (const float*)d_in[9];
    const float* g1  = (const float*)d_in[10];
    const float* bn1 = (const float*)d_in[11];
    const float* g2  = (const float*)d_in[12];
    const float* bn2 = (const float*)d_in[13];
    const float* Wfc = (const float*)d_in[14];
    const float* bfc = (const float*)d_in[15];
    float* out = (float*)d_out;

    float *x, *enc, *pbias, *part;
    __half *xhi, *xlo, *phi, *plo, *ffhi, *fflo;
    __half *w1h, *w2h, *wch;
    cudaGetSymbolAddress((void**)&x, g_x);
    cudaGetSymbolAddress((void**)&enc, g_enc);
    cudaGetSymbolAddress((void**)&pbias, g_pbias);
    cudaGetSymbolAddress((void**)&part, g_part);
    cudaGetSymbolAddress((void**)&xhi, g_xhi);
    cudaGetSymbolAddress((void**)&xlo, g_xlo);
    cudaGetSymbolAddress((void**)&phi, g_phi);
    cudaGetSymbolAddress((void**)&plo, g_plo);
    cudaGetSymbolAddress((void**)&ffhi, g_ffhi);
    cudaGetSymbolAddress((void**)&fflo, g_fflo);
    cudaGetSymbolAddress((void**)&w1h, g_w1h);
    cudaGetSymbolAddress((void**)&w2h, g_w2h);
    cudaGetSymbolAddress((void**)&wch, g_wch);
    float* part0 = part;
    float* part1 = part + (size_t)M_ * D_;

    cudaFuncSetAttribute(attn_kernel, cudaFuncAttributeMaxDynamicSharedMemorySize, ATTN_SMEM);
    cudaFuncSetAttribute(mma_gemm<1>, cudaFuncAttributeMaxDynamicSharedMemorySize, GEMM_SMEM);
    cudaFuncSetAttribute(mma_gemm<2>, cudaFuncAttributeMaxDynamicSharedMemorySize, GEMM_SMEM);

    // weight transpose + fp16 convert (tiny, one-time per launch)
    wconv_kernel<<<dim3(D_ / 32, FF_ / 32), dim3(32, 8)>>>(W1, w1h, D_, FF_);
    wconv_kernel<<<dim3(FF_ / 32, D_ / 32), dim3(32, 8)>>>(W2, w2h, FF_, D_);
    wconv_kernel<<<dim3(D_ / 32, D_ / 32),  dim3(32, 8)>>>(Wc, wch, D_, D_);

    const int total = M_ * D_;
    add_pe_kernel<<<(total + 255) / 256, 256>>>(tseq, x);
    pool_kernel<<<(total + 255) / 256, 256>>>(pseq, phi, plo);

    // param encoder: enc = LN(pooled @ Wc + bc)  (split-K=2 -> partial buffers)
    mma_gemm<2><<<dim3(D_ / BNT, M_ / BMT, 2), 256, GEMM_SMEM>>>(
        phi, plo, wch, nullptr, part0, nullptr, nullptr, M_, D_, D_);
    ln_kernel<0><<<M_, 256>>>(part0, part1, nullptr, bc, gp, bp, enc, nullptr, nullptr);

    // layer-invariant attention bias
    pbias_kernel<<<B_ * H_, 256>>>(enc, pbias);

    for (int l = 0; l < NLAYERS; l++) {
        attn_kernel<<<B_ * H_, 256, ATTN_SMEM>>>(x, pbias, part0);
        ln_kernel<1><<<M_, 256>>>(x, part0, nullptr, nullptr, g1, bn1, x, xhi, xlo);
        mma_gemm<1><<<dim3(FF_ / BNT, M_ / BMT), 256, GEMM_SMEM>>>(
            xhi, xlo, w1h, b1, nullptr, ffhi, fflo, M_, FF_, D_);
        // FFN2: split-K=2 -> two fp32 partial buffers, bias b2 folded into LN
        mma_gemm<2><<<dim3(D_ / BNT, M_ / BMT, 2), 256, GEMM_SMEM>>>(
            ffhi, fflo, w2h, nullptr, part0, nullptr, nullptr, M_, D_, FF_);
        ln_kernel<0><<<M_, 256>>>(x, part0, part1, b2, g2, bn2, x, nullptr, nullptr);
    }

    fc_kernel<<<B_, 256>>>(x, Wfc, bfc, out);
}

// round 7
// speedup vs baseline: 1.5421x; 1.0043x over previous
#include <cuda_runtime.h>
#include <cuda_fp16.h>
#include <math.h>
#include <stdint.h>

// ---------------- problem constants ----------------
#define B_   64
#define S_   100
#define D_   768
#define H_   8
#define HD_  96
#define P_   8
#define FF_  3072
#define M_   (B_ * S_)            // 6400 rows
#define NLAYERS 4
#define EPS_ 1e-5f
#define INV_SQRT_HD 0.10206207261596575f   // 1/sqrt(96)

// ---------------- device scratch ----------------
__device__ float g_x[M_ * D_];
__device__ float g_enc[M_ * D_];
__device__ float g_pbias[B_ * H_ * S_ * S_];
__device__ float g_part[2][M_ * D_];   // split-K fp32 partials

__device__ __half g_xhi[M_ * D_];
__device__ __half g_xlo[M_ * D_];
__device__ __half g_phi[M_ * D_];
__device__ __half g_plo[M_ * D_];
__device__ __half g_ffhi[(size_t)M_ * FF_];
__device__ __half g_fflo[(size_t)M_ * FF_];
__device__ __half g_w1h[(size_t)FF_ * D_];   // [N=3072][K=768] fp16
__device__ __half g_w2h[(size_t)D_ * FF_];   // [N=768][K=3072] fp16
__device__ __half g_wch[(size_t)D_ * D_];    // [N=768][K=768]  fp16

// ============================================================
// PTX helpers (mma.sync / ldmatrix / cp.async — all baseline sm_80+)
// ============================================================
__device__ __forceinline__ uint32_t smem_u32(const void* p) {
    uint32_t a;
    asm("{ .reg .u64 t; cvta.to.shared.u64 t, %1; cvt.u32.u64 %0, t; }" : "=r"(a) : "l"(p));
    return a;
}

#define CP_ASYNC16(dst, src) \
    asm volatile("cp.async.cg.shared.global [%0], [%1], 16;\n" :: "r"(dst), "l"(src) : "memory")
#define CP_COMMIT() asm volatile("cp.async.commit_group;\n" ::: "memory")
#define CP_WAIT0()  asm volatile("cp.async.wait_group 0;\n" ::: "memory")
#define CP_WAIT1()  asm volatile("cp.async.wait_group 1;\n" ::: "memory")

#define LDSM4(r, addr) \
    asm volatile("ldmatrix.sync.aligned.m8n8.x4.shared.b16 {%0,%1,%2,%3}, [%4];" \
        : "=r"((r)[0]), "=r"((r)[1]), "=r"((r)[2]), "=r"((r)[3]) : "r"(addr))

#define MMA_F16(c, a, b) \
    asm volatile("mma.sync.aligned.m16n8k16.row.col.f32.f16.f16.f32 " \
        "{%0,%1,%2,%3}, {%4,%5,%6,%7}, {%8,%9}, {%0,%1,%2,%3};" \
        : "+f"((c)[0]), "+f"((c)[1]), "+f"((c)[2]), "+f"((c)[3]) \
        : "r"((a)[0]), "r"((a)[1]), "r"((a)[2]), "r"((a)[3]), "r"((b)[0]), "r"((b)[1]))

__device__ __forceinline__ float gelu_exact(float v) {
    return 0.5f * v * (1.0f + erff(v * 0.70710678118654752f));
}
__device__ __forceinline__ void split_f16(float v, __half& h, __half& l) {
    h = __float2half(v);
    l = __float2half(v - __half2float(h));
}

// ============================================================
// GEMM: C[M,N] = A[M,K] @ B^T[N,K] (+ bias)
// A = Ah + Al (fp16 pair, exact to 2^-22), B single fp16.
// C = Ah*B + Al*B  (2 MMAs per fragment; only error = B fp16 rounding)
// EPI 1: bias + gelu -> fp16 hi/lo out (Ch, Cl).
// EPI 2: plain fp32 partial store, NO bias; z-th split writes Cf + z*M*N.
// 3-stage cp.async ring (90KB smem), 2 CTAs/SM, one barrier per k-step.
// ============================================================
#define BMT 128
#define BNT 128
#define BKS 32
#define NSTAGE 3
#define MATB 10240u                // 128*40*2 bytes (rows padded to 40 fp16)
#define BUFB (3 * MATB)            // 30720: Ah, Al, B
#define GEMM_SMEM (NSTAGE * BUFB)  // 92160

template <int EPI>
__global__ __launch_bounds__(256, 2)
void mma_gemm(const __half* __restrict__ Ah_, const __half* __restrict__ Al_,
              const __half* __restrict__ Bh_,
              const float* __restrict__ bias,
              float* __restrict__ Cf, __half* __restrict__ Ch, __half* __restrict__ Cl,
              int M, int N, int K)
{
    extern __shared__ char dsm[];
    const uint32_t sb0 = smem_u32(dsm);
    const int tid = threadIdx.x;
    const int wid = tid >> 5, lane = tid & 31;
    const int wm = wid >> 1, wn = wid & 1;          // warp tile: 32 x 64
    const int row0 = blockIdx.y * BMT, col0 = blockIdx.x * BNT;
    const int Kloc = K / gridDim.z;
    const int koff = blockIdx.z * Kloc;
    const int NS = Kloc / BKS;

    const __half* Ahp = Ah_ + koff;
    const __half* Alp = Al_ + koff;
    const __half* Bhp = Bh_ + koff;

    float acc[2][8][4];
    #pragma unroll
    for (int i = 0; i < 2; i++)
        #pragma unroll
        for (int j = 0; j < 8; j++)
            #pragma unroll
            for (int k = 0; k < 4; k++) acc[i][j][k] = 0.f;

    // ldmatrix per-lane base offsets (bytes, within one stage buffer)
    const uint32_t aoff = (uint32_t)((wm * 32 + (lane & 15)) * 80 + (lane >> 4) * 16);
    const uint32_t boff = (uint32_t)((wn * 64 + ((lane >> 4) << 3) + (lane & 7)) * 80
                                     + ((lane >> 3) & 1) * 16);

    auto load_step = [&](int s) {
        const uint32_t sb = sb0 + (uint32_t)(s % NSTAGE) * BUFB;
        const int k0 = s * BKS;
        #pragma unroll
        for (int i = 0; i < 6; i++) {
            int u = i * 256 + tid;
            int mat = u >> 9;          // 0 Ah, 1 Al, 2 B
            int v = u & 511;
            int r = v >> 2, c = v & 3;
            const __half* src;
            if (mat == 0)      src = Ahp + (size_t)(row0 + r) * K + k0 + c * 8;
            else if (mat == 1) src = Alp + (size_t)(row0 + r) * K + k0 + c * 8;
            else               src = Bhp + (size_t)(col0 + r) * K + k0 + c * 8;
            CP_ASYNC16(sb + (uint32_t)mat * MATB + (uint32_t)(r * 80 + c * 16), src);
        }
        CP_COMMIT();
    };

    load_step(0);
    if (NS > 1) load_step(1);

    for (int s = 0; s < NS; s++) {
        // wait for load(s), keep load(s+1) in flight
        if (s < NS - 1) { CP_WAIT1(); } else { CP_WAIT0(); }
        // one barrier: (a) all threads see buffer s%3 filled; (b) all threads
        // finished compute(s-1) reading buffer (s-1)%3 == (s+2)%3, so load(s+2)
        // may overwrite it.
        __syncthreads();
        if (s + 2 < NS) load_step(s + 2);

        const uint32_t sb = sb0 + (uint32_t)(s % NSTAGE) * BUFB;
        #pragma unroll
        for (int kh = 0; kh < 2; kh++) {     // two k16 halves of the k32 step
            uint32_t ah[2][4], al[2][4], b[8][2];
            #pragma unroll
            for (int mf = 0; mf < 2; mf++) {
                LDSM4(ah[mf], sb + aoff + (uint32_t)(mf * 1280 + kh * 32));
                LDSM4(al[mf], sb + MATB + aoff + (uint32_t)(mf * 1280 + kh * 32));
            }
            #pragma unroll
            for (int p = 0; p < 4; p++) {
                uint32_t t[4];
                LDSM4(t, sb + 2 * MATB + boff + (uint32_t)(p * 1280 + kh * 32));
                b[2 * p][0] = t[0]; b[2 * p][1] = t[1];
                b[2 * p + 1][0] = t[2]; b[2 * p + 1][1] = t[3];
            }
            #pragma unroll
            for (int mf = 0; mf < 2; mf++)
                #pragma unroll
                for (int nf = 0; nf < 8; nf++) {
                    MMA_F16(acc[mf][nf], ah[mf], b[nf]);
                    MMA_F16(acc[mf][nf], al[mf], b[nf]);
                }
        }
    }

    // ---- epilogue: regs -> per-warp smem stage (16x65 fp32) -> coalesced stores ----
    __syncthreads();
    float* stg = (float*)dsm + wid * (16 * 65);
    const int gcol0 = col0 + wn * 64;
    const float bv0 = (EPI == 2) ? 0.f : bias[gcol0 + lane];
    const float bv1 = (EPI == 2) ? 0.f : bias[gcol0 + 32 + lane];
    const int r1 = lane >> 2, c0 = (lane & 3) * 2;
    float* Cfz = (EPI == 2) ? Cf + (size_t)blockIdx.z * M * N : Cf;

    #pragma unroll
    for (int mf = 0; mf < 2; mf++) {
        #pragma unroll
        for (int nf = 0; nf < 8; nf++) {
            stg[r1 * 65 + nf * 8 + c0]           = acc[mf][nf][0];
            stg[r1 * 65 + nf * 8 + c0 + 1]       = acc[mf][nf][1];
            stg[(r1 + 8) * 65 + nf * 8 + c0]     = acc[mf][nf][2];
            stg[(r1 + 8) * 65 + nf * 8 + c0 + 1] = acc[mf][nf][3];
        }
        __syncwarp();
        const int grow = row0 + wm * 32 + mf * 16;
        #pragma unroll
        for (int r = 0; r < 16; r++) {
            float v0 = stg[r * 65 + lane] + bv0;
            float v1 = stg[r * 65 + 32 + lane] + bv1;
            if (EPI == 1) {
                v0 = gelu_exact(v0);
                v1 = gelu_exact(v1);
                __half h0, l0, h1, l1;
                split_f16(v0, h0, l0);
                split_f16(v1, h1, l1);
                size_t base = (size_t)(grow + r) * N + gcol0;
                Ch[base + lane] = h0;      Cl[base + lane] = l0;
                Ch[base + 32 + lane] = h1; Cl[base + 32 + lane] = l1;
            } else {
                size_t base = (size_t)(grow + r) * N + gcol0;
                Cfz[base + lane] = v0;
                Cfz[base + 32 + lane] = v1;
            }
        }
        __syncwarp();
    }
}

// ============================================================
// weight transpose + fp16 convert: W[K][N] -> T[N][K]
// ============================================================
__global__ void wconv_kernel(const float* __restrict__ W, __half* __restrict__ Th,
                             int K, int N) {
    __shared__ float t[32][33];
    int k0 = blockIdx.x * 32, n0 = blockIdx.y * 32;
    int tx = threadIdx.x, ty = threadIdx.y;  // (32, 8)
    #pragma unroll
    for (int i = 0; i < 4; i++)
        t[ty + i * 8][tx] = W[(size_t)(k0 + ty + i * 8) * N + n0 + tx];
    __syncthreads();
    #pragma unroll
    for (int i = 0; i < 4; i++) {
        int n = n0 + ty + i * 8, k = k0 + tx;
        Th[(size_t)n * K + k] = __float2half(t[tx][ty + i * 8]);
    }
}

// ---------------- elementwise: x = template + positional encoding ----------------
__global__ void add_pe_kernel(const float* __restrict__ t, float* __restrict__ x) {
    int idx = blockIdx.x * 256 + threadIdx.x;
    if (idx >= M_ * D_) return;
    int d = idx % D_;
    int s = (idx / D_) % S_;
    int i2 = d & ~1;
    float div = expf((float)i2 * (-9.210340371976184f / (float)D_));
    float ang = (float)s * div;
    float pe = (d & 1) ? cosf(ang) : sinf(ang);
    x[idx] = t[idx] + pe;
}

// ---------------- pooled = mean over P, emitted as fp16 hi/lo ----------------
__global__ void pool_kernel(const float* __restrict__ ps,
                            __half* __restrict__ ph, __half* __restrict__ pl) {
    int idx = blockIdx.x * 256 + threadIdx.x;
    if (idx >= M_ * D_) return;
    int bs = idx / D_;
    int c  = idx % D_;
    const float* base = ps + (size_t)bs * (P_ * D_) + c;
    float s = 0.f;
    #pragma unroll
    for (int p = 0; p < P_; p++) s += base[p * D_];
    float m = s * (1.0f / P_);
    __half h, l;
    split_f16(m, h, l);
    ph[idx] = h; pl[idx] = l;
}

// ---------------- block-reduce helper ----------------
__device__ __forceinline__ float warp_sum(float v) {
    #pragma unroll
    for (int o = 16; o; o >>= 1) v += __shfl_down_sync(0xffffffffu, v, o);
    return v;
}

// ---------------- LayerNorm (row length 768) ----------------
// t = x (+ res) (+ res2) (+ colbias);  out = LN(t)*g + b;  optional fp16 hi/lo out
template <int F16OUT>
__global__ void ln_kernel(const float* __restrict__ x, const float* __restrict__ res,
                          const float* __restrict__ res2,
                          const float* __restrict__ colbias,
                          const float* __restrict__ g, const float* __restrict__ b,
                          float* __restrict__ out,
                          __half* __restrict__ oh, __half* __restrict__ ol) {
    const int row = blockIdx.x;
    const int tid = threadIdx.x;  // 256
    const float* xr = x + (size_t)row * D_;
    const float* rr = res ? res + (size_t)row * D_ : nullptr;
    const float* r2 = res2 ? res2 + (size_t)row * D_ : nullptr;

    float v[3];
    float s = 0.f, s2 = 0.f;
    #pragma unroll
    for (int i = 0; i < 3; i++) {
        int c = tid + i * 256;
        float t = xr[c];
        if (rr) t += rr[c];
        if (r2) t += r2[c];
        if (colbias) t += colbias[c];
        v[i] = t; s += t; s2 += t * t;
    }

    __shared__ float red[2][8];
    __shared__ float stat[2];
    int lane = tid & 31, wid = tid >> 5;
    s = warp_sum(s); s2 = warp_sum(s2);
    if (lane == 0) { red[0][wid] = s; red[1][wid] = s2; }
    __syncthreads();
    if (wid == 0) {
        float a = (lane < 8) ? red[0][lane] : 0.f;
        float c = (lane < 8) ? red[1][lane] : 0.f;
        a = warp_sum(a); c = warp_sum(c);
        if (lane == 0) {
            float mean = a * (1.0f / D_);
            float var = c * (1.0f / D_) - mean * mean;
            stat[0] = mean;
            stat[1] = rsqrtf(var + EPS_);
        }
    }
    __syncthreads();
    float mean = stat[0], inv = stat[1];
    float* orow = out + (size_t)row * D_;
    #pragma unroll
    for (int i = 0; i < 3; i++) {
        int c = tid + i * 256;
        float o = (v[i] - mean) * inv * g[c] + b[c];
        orow[c] = o;
        if (F16OUT) {
            __half h, l;
            split_f16(o, h, l);
            oh[(size_t)row * D_ + c] = h;
            ol[(size_t)row * D_ + c] = l;
        }
    }
}

// ---------------- param_bias[b,h] = (pe_bh @ pe_bh^T) * inv_sqrt_hd ----------------
__global__ __launch_bounds__(256)
void pbias_kernel(const float* __restrict__ enc, float* __restrict__ pbias) {
    __shared__ float Es[112 * 97];
    const int b = blockIdx.x >> 3;
    const int h = blockIdx.x & 7;
    const int tid = threadIdx.x;
    const float* src = enc + (size_t)(b * S_) * D_ + h * HD_;

    for (int i = tid; i < 112 * 96; i += 256) {
        int s = i / 96, d = i - s * 96;
        Es[s * 97 + d] = (s < S_) ? src[(size_t)s * D_ + d] : 0.f;
    }
    __syncthreads();

    const int tx = tid & 15, ty = tid >> 4;
    float acc[7][7];
    #pragma unroll
    for (int ii = 0; ii < 7; ii++)
        #pragma unroll
        for (int jj = 0; jj < 7; jj++) acc[ii][jj] = 0.f;

    for (int d = 0; d < 96; d++) {
        float a[7], bb[7];
        #pragma unroll
        for (int ii = 0; ii < 7; ii++) a[ii]  = Es[(ty + 16 * ii) * 97 + d];
        #pragma unroll
        for (int jj = 0; jj < 7; jj++) bb[jj] = Es[(tx + 16 * jj) * 97 + d];
        #pragma unroll
        for (int ii = 0; ii < 7; ii++)
            #pragma unroll
            for (int jj = 0; jj < 7; jj++) acc[ii][jj] += a[ii] * bb[jj];
    }

    float* dst = pbias + (size_t)blockIdx.x * (S_ * S_);
    #pragma unroll
    for (int ii = 0; ii < 7; ii++) {
        int i = ty + 16 * ii;
        if (i >= S_) continue;
        #pragma unroll
        for (int jj = 0; jj < 7; jj++) {
            int j = tx + 16 * jj;
            if (j < S_) dst[i * S_ + j] = acc[ii][jj] * INV_SQRT_HD;
        }
    }
}

// ---------------- fused attention per (b,h) ----------------
#define ATTN_SMEM ((112 * 97 + 112 * 101) * 4)
__global__ __launch_bounds__(256)
void attn_kernel(const float* __restrict__ x, const float* __restrict__ pbias,
                 float* __restrict__ out) {
    extern __shared__ float smem[];
    float* Qs = smem;               // [112][97]
    float* Ss = smem + 112 * 97;    // [112][101]

    const int b = blockIdx.x >> 3;
    const int h = blockIdx.x & 7;
    const int tid = threadIdx.x;
    const float* xb = x + (size_t)(b * S_) * D_ + h * HD_;

    for (int i = tid; i < 112 * 96; i += 256) {
        int s = i / 96, d = i - s * 96;
        Qs[s * 97 + d] = (s < S_) ? xb[(size_t)s * D_ + d] : 0.f;
    }
    __syncthreads();

    const int tx = tid & 15, ty = tid >> 4;
    {
        float acc[7][7];
        #pragma unroll
        for (int ii = 0; ii < 7; ii++)
            #pragma unroll
            for (int jj = 0; jj < 7; jj++) acc[ii][jj] = 0.f;

        for (int d = 0; d < 96; d++) {
            float a[7], bb[7];
            #pragma unroll
            for (int ii = 0; ii < 7; ii++) a[ii]  = Qs[(ty + 16 * ii) * 97 + d];
            #pragma unroll
            for (int jj = 0; jj < 7; jj++) bb[jj] = Qs[(tx + 16 * jj) * 97 + d];
            #pragma unroll
            for (int ii = 0; ii < 7; ii++)
                #pragma unroll
                for (int jj = 0; jj < 7; jj++) acc[ii][jj] += a[ii] * bb[jj];
        }
        const float* pb = pbias + (size_t)blockIdx.x * (S_ * S_);
        #pragma unroll
        for (int ii = 0; ii < 7; ii++) {
            int i = ty + 16 * ii;
            if (i >= S_) continue;
            #pragma unroll
            for (int jj = 0; jj < 7; jj++) {
                int j = tx + 16 * jj;
                if (j < S_)
                    Ss[i * 101 + j] = acc[ii][jj] * INV_SQRT_HD + pb[i * S_ + j];
            }
        }
    }
    __syncthreads();

    if (tid < S_) {
        float* row = Ss + tid * 101;
        float m = -1e30f;
        for (int j = 0; j < S_; j++) m = fmaxf(m, row[j]);
        float sum = 0.f;
        for (int j = 0; j < S_; j++) { float e = expf(row[j] - m); row[j] = e; sum += e; }
        float inv = 1.0f / sum;
        for (int j = 0; j < S_; j++) row[j] *= inv;
    }
    __syncthreads();

    {
        float acc[7][6];
        #pragma unroll
        for (int ii = 0; ii < 7; ii++)
            #pragma unroll
            for (int jj = 0; jj < 6; jj++) acc[ii][jj] = 0.f;

        for (int j = 0; j < S_; j++) {
            float a[7], bb[6];
            #pragma unroll
            for (int ii = 0; ii < 7; ii++) a[ii]  = Ss[(ty + 16 * ii) * 101 + j];
            #pragma unroll
            for (int jj = 0; jj < 6; jj++) bb[jj] = Qs[j * 97 + tx + 16 * jj];
            #pragma unroll
            for (int ii = 0; ii < 7; ii++)
                #pragma unroll
                for (int jj = 0; jj < 6; jj++) acc[ii][jj] += a[ii] * bb[jj];
        }
        float* dst = out + (size_t)(b * S_) * D_ + h * HD_;
        #pragma unroll
        for (int ii = 0; ii < 7; ii++) {
            int i = ty + 16 * ii;
            if (i >= S_) continue;
            #pragma unroll
            for (int jj = 0; jj < 6; jj++) {
                int dd = tx + 16 * jj;
                dst[(size_t)i * D_ + dd] = acc[ii][jj];
            }
        }
    }
}

// ---------------- final classifier ----------------
__global__ void fc_kernel(const float* __restrict__ x, const float* __restrict__ Wfc,
                          const float* __restrict__ bfc, float* __restrict__ out) {
    const int b = blockIdx.x;
    const int tid = threadIdx.x;
    const float* xr = x + (size_t)b * (S_ * D_);
    float a0 = 0.f, a1 = 0.f;
    for (int i = tid; i < S_ * D_; i += 256) {
        float v = xr[i];
        a0 += v * Wfc[2 * i];
        a1 += v * Wfc[2 * i + 1];
    }
    __shared__ float red[2][8];
    int lane = tid & 31, wid = tid >> 5;
    a0 = warp_sum(a0); a1 = warp_sum(a1);
    if (lane == 0) { red[0][wid] = a0; red[1][wid] = a1; }
    __syncthreads();
    if (wid == 0) {
        float r0 = (lane < 8) ? red[0][lane] : 0.f;
        float r1 = (lane < 8) ? red[1][lane] : 0.f;
        r0 = warp_sum(r0); r1 = warp_sum(r1);
        if (lane == 0) {
            out[2 * b + 0] = r0 + bfc[0];
            out[2 * b + 1] = r1 + bfc[1];
        }
    }
}

// ---------------- launch ----------------
extern "C" void kernel_launch(void* const* d_in, const int* in_sizes, int n_in,
                              void* d_out, int out_size) {
    const float* tseq = (const float*)d_in[0];
    const float* pseq = (const float*)d_in[1];
    const float* Wc  = (const float*)d_in[2];
    const float* bc  = (const float*)d_in[3];
    const float* gp  = (const float*)d_in[4];
    const float* bp  = (const float*)d_in[5];
    const float* W1  = (const float*)d_in[6];
    const float* b1  = (const float*)d_in[7];
    const float* W2  = (const float*)d_in[8];
    const float* b2  = (const float*)d_in[9];
    const float* g1  = (const float*)d_in[10];
    const float* bn1 = (const float*)d_in[11];
    const float* g2  = (const float*)d_in[12];
    const float* bn2 = (const float*)d_in[13];
    const float* Wfc = (const float*)d_in[14];
    const float* bfc = (const float*)d_in[15];
    float* out = (float*)d_out;

    float *x, *enc, *pbias, *part;
    __half *xhi, *xlo, *phi, *plo, *ffhi, *fflo;
    __half *w1h, *w2h, *wch;
    cudaGetSymbolAddress((void**)&x, g_x);
    cudaGetSymbolAddress((void**)&enc, g_enc);
    cudaGetSymbolAddress((void**)&pbias, g_pbias);
    cudaGetSymbolAddress((void**)&part, g_part);
    cudaGetSymbolAddress((void**)&xhi, g_xhi);
    cudaGetSymbolAddress((void**)&xlo, g_xlo);
    cudaGetSymbolAddress((void**)&phi, g_phi);
    cudaGetSymbolAddress((void**)&plo, g_plo);
    cudaGetSymbolAddress((void**)&ffhi, g_ffhi);
    cudaGetSymbolAddress((void**)&fflo, g_fflo);
    cudaGetSymbolAddress((void**)&w1h, g_w1h);
    cudaGetSymbolAddress((void**)&w2h, g_w2h);
    cudaGetSymbolAddress((void**)&wch, g_wch);
    float* part0 = part;
    float* part1 = part + (size_t)M_ * D_;

    cudaFuncSetAttribute(attn_kernel, cudaFuncAttributeMaxDynamicSharedMemorySize, ATTN_SMEM);
    cudaFuncSetAttribute(mma_gemm<1>, cudaFuncAttributeMaxDynamicSharedMemorySize, GEMM_SMEM);
    cudaFuncSetAttribute(mma_gemm<2>, cudaFuncAttributeMaxDynamicSharedMemorySize, GEMM_SMEM);

    // weight transpose + fp16 convert (tiny, one-time per launch)
    wconv_kernel<<<dim3(D_ / 32, FF_ / 32), dim3(32, 8)>>>(W1, w1h, D_, FF_);
    wconv_kernel<<<dim3(FF_ / 32, D_ / 32), dim3(32, 8)>>>(W2, w2h, FF_, D_);
    wconv_kernel<<<dim3(D_ / 32, D_ / 32),  dim3(32, 8)>>>(Wc, wch, D_, D_);

    const int total = M_ * D_;
    add_pe_kernel<<<(total + 255) / 256, 256>>>(tseq, x);
    pool_kernel<<<(total + 255) / 256, 256>>>(pseq, phi, plo);

    // param encoder: enc = LN(pooled @ Wc + bc)  (split-K=2 -> partial buffers)
    mma_gemm<2><<<dim3(D_ / BNT, M_ / BMT, 2), 256, GEMM_SMEM>>>(
        phi, plo, wch, nullptr, part0, nullptr, nullptr, M_, D_, D_);
    ln_kernel<0><<<M_, 256>>>(part0, part1, nullptr, bc, gp, bp, enc, nullptr, nullptr);

    // layer-invariant attention bias
    pbias_kernel<<<B_ * H_, 256>>>(enc, pbias);

    for (int l = 0; l < NLAYERS; l++) {
        attn_kernel<<<B_ * H_, 256, ATTN_SMEM>>>(x, pbias, part0);
        ln_kernel<1><<<M_, 256>>>(x, part0, nullptr, nullptr, g1, bn1, x, xhi, xlo);
        mma_gemm<1><<<dim3(FF_ / BNT, M_ / BMT), 256, GEMM_SMEM>>>(
            xhi, xlo, w1h, b1, nullptr, ffhi, fflo, M_, FF_, D_);
        // FFN2: split-K=2 -> two fp32 partial buffers, bias b2 folded into LN
        mma_gemm<2><<<dim3(D_ / BNT, M_ / BMT, 2), 256, GEMM_SMEM>>>(
            ffhi, fflo, w2h, nullptr, part0, nullptr, nullptr, M_, D_, FF_);
        ln_kernel<0><<<M_, 256>>>(x, part0, part1, b2, g2, bn2, x, nullptr, nullptr);
    }

    fc_kernel<<<B_, 256>>>(x, Wfc, bfc, out);
}

// round 8
// speedup vs baseline: 1.8049x; 1.1704x over previous
#include <cuda_runtime.h>
#include <cuda_fp16.h>
#include <math.h>
#include <stdint.h>

// ---------------- problem constants ----------------
#define B_   64
#define S_   100
#define D_   768
#define H_   8
#define HD_  96
#define P_   8
#define FF_  3072
#define M_   (B_ * S_)            // 6400 rows
#define NLAYERS 4
#define EPS_ 1e-5f
#define INV_SQRT_HD 0.10206207261596575f   // 1/sqrt(96)

// ---------------- device scratch ----------------
__device__ float g_x[M_ * D_];
__device__ float g_enc[M_ * D_];
__device__ float g_pbias[B_ * H_ * S_ * S_];
__device__ float g_part[2][M_ * D_];   // split-K fp32 partials

__device__ __half g_xhi[M_ * D_];
__device__ __half g_xlo[M_ * D_];
__device__ __half g_phi[M_ * D_];
__device__ __half g_plo[M_ * D_];
__device__ __half g_ffhi[(size_t)M_ * FF_];
__device__ __half g_w1h[(size_t)FF_ * D_];   // [N=3072][K=768] fp16
__device__ __half g_w2h[(size_t)D_ * FF_];   // [N=768][K=3072] fp16
__device__ __half g_wch[(size_t)D_ * D_];    // [N=768][K=768]  fp16

// ============================================================
// PTX helpers (mma.sync / ldmatrix / cp.async — all baseline sm_80+)
// ============================================================
__device__ __forceinline__ uint32_t smem_u32(const void* p) {
    uint32_t a;
    asm("{ .reg .u64 t; cvta.to.shared.u64 t, %1; cvt.u32.u64 %0, t; }" : "=r"(a) : "l"(p));
    return a;
}

#define CP_ASYNC16(dst, src) \
    asm volatile("cp.async.cg.shared.global [%0], [%1], 16;\n" :: "r"(dst), "l"(src) : "memory")
#define CP_COMMIT() asm volatile("cp.async.commit_group;\n" ::: "memory")
#define CP_WAIT0()  asm volatile("cp.async.wait_group 0;\n" ::: "memory")
#define CP_WAIT1()  asm volatile("cp.async.wait_group 1;\n" ::: "memory")

#define LDSM4(r, addr) \
    asm volatile("ldmatrix.sync.aligned.m8n8.x4.shared.b16 {%0,%1,%2,%3}, [%4];" \
        : "=r"((r)[0]), "=r"((r)[1]), "=r"((r)[2]), "=r"((r)[3]) : "r"(addr))

#define MMA_F16(c, a, b) \
    asm volatile("mma.sync.aligned.m16n8k16.row.col.f32.f16.f16.f32 " \
        "{%0,%1,%2,%3}, {%4,%5,%6,%7}, {%8,%9}, {%0,%1,%2,%3};" \
        : "+f"((c)[0]), "+f"((c)[1]), "+f"((c)[2]), "+f"((c)[3]) \
        : "r"((a)[0]), "r"((a)[1]), "r"((a)[2]), "r"((a)[3]), "r"((b)[0]), "r"((b)[1]))

__device__ __forceinline__ float gelu_exact(float v) {
    return 0.5f * v * (1.0f + erff(v * 0.70710678118654752f));
}
__device__ __forceinline__ void split_f16(float v, __half& h, __half& l) {
    h = __float2half(v);
    l = __float2half(v - __half2float(h));
}

// ============================================================
// GEMM: C[M,N] = A[M,K] @ B^T[N,K] (+ bias)
// TT=1: A = Ah + Al (fp16 pair, exact to 2^-22); 2 MMAs per fragment.
// TT=0: A = Ah single fp16; 1 MMA per fragment.
// B single fp16 in both cases.
// EPI 1: bias + gelu -> single fp16 out (Ch).
// EPI 2: plain fp32 partial store, NO bias; z-th split writes Cf + z*M*N.
// 3-stage cp.async ring, 2 CTAs/SM, one barrier per k-step.
// ============================================================
#define BMT 128
#define BNT 128
#define BKS 32
#define NSTAGE 3
#define MATB 10240u                // 128*40*2 bytes (rows padded to 40 fp16)
#define BUFB (3 * MATB)            // 30720 (TT=0 leaves the Al slot unused)
#define GEMM_SMEM (NSTAGE * BUFB)  // 92160

template <int EPI, int TT>
__global__ __launch_bounds__(256, 2)
void mma_gemm(const __half* __restrict__ Ah_, const __half* __restrict__ Al_,
              const __half* __restrict__ Bh_,
              const float* __restrict__ bias,
              float* __restrict__ Cf, __half* __restrict__ Ch,
              int M, int N, int K)
{
    extern __shared__ char dsm[];
    const uint32_t sb0 = smem_u32(dsm);
    const int tid = threadIdx.x;
    const int wid = tid >> 5, lane = tid & 31;
    const int wm = wid >> 1, wn = wid & 1;          // warp tile: 32 x 64
    const int row0 = blockIdx.y * BMT, col0 = blockIdx.x * BNT;
    const int Kloc = K / gridDim.z;
    const int koff = blockIdx.z * Kloc;
    const int NS = Kloc / BKS;

    const __half* Ahp = Ah_ + koff;
    const __half* Alp = TT ? Al_ + koff : nullptr;
    const __half* Bhp = Bh_ + koff;

    float acc[2][8][4];
    #pragma unroll
    for (int i = 0; i < 2; i++)
        #pragma unroll
        for (int j = 0; j < 8; j++)
            #pragma unroll
            for (int k = 0; k < 4; k++) acc[i][j][k] = 0.f;

    // ldmatrix per-lane base offsets (bytes, within one stage buffer)
    const uint32_t aoff = (uint32_t)((wm * 32 + (lane & 15)) * 80 + (lane >> 4) * 16);
    const uint32_t boff = (uint32_t)((wn * 64 + ((lane >> 4) << 3) + (lane & 7)) * 80
                                     + ((lane >> 3) & 1) * 16);
    const uint32_t BOFFM = (TT ? 2u : 1u) * MATB;    // B matrix slot

    auto load_step = [&](int s) {
        const uint32_t sb = sb0 + (uint32_t)(s % NSTAGE) * BUFB;
        const int k0 = s * BKS;
        #pragma unroll
        for (int i = 0; i < (TT ? 6 : 4); i++) {
            int u = i * 256 + tid;
            int mat = u >> 9;          // TT=1: 0 Ah, 1 Al, 2 B ; TT=0: 0 Ah, 1 B
            int v = u & 511;
            int r = v >> 2, c = v & 3;
            const __half* src;
            if (TT) {
                if (mat == 0)      src = Ahp + (size_t)(row0 + r) * K + k0 + c * 8;
                else if (mat == 1) src = Alp + (size_t)(row0 + r) * K + k0 + c * 8;
                else               src = Bhp + (size_t)(col0 + r) * K + k0 + c * 8;
            } else {
                if (mat == 0)      src = Ahp + (size_t)(row0 + r) * K + k0 + c * 8;
                else               src = Bhp + (size_t)(col0 + r) * K + k0 + c * 8;
            }
            CP_ASYNC16(sb + (uint32_t)mat * MATB + (uint32_t)(r * 80 + c * 16), src);
        }
        CP_COMMIT();
    };

    load_step(0);
    if (NS > 1) load_step(1);

    for (int s = 0; s < NS; s++) {
        if (s < NS - 1) { CP_WAIT1(); } else { CP_WAIT0(); }
        __syncthreads();
        if (s + 2 < NS) load_step(s + 2);

        const uint32_t sb = sb0 + (uint32_t)(s % NSTAGE) * BUFB;
        #pragma unroll
        for (int kh = 0; kh < 2; kh++) {     // two k16 halves of the k32 step
            uint32_t ah[2][4], al[2][4], b[8][2];
            #pragma unroll
            for (int mf = 0; mf < 2; mf++) {
                LDSM4(ah[mf], sb + aoff + (uint32_t)(mf * 1280 + kh * 32));
                if (TT) LDSM4(al[mf], sb + MATB + aoff + (uint32_t)(mf * 1280 + kh * 32));
            }
            #pragma unroll
            for (int p = 0; p < 4; p++) {
                uint32_t t[4];
                LDSM4(t, sb + BOFFM + boff + (uint32_t)(p * 1280 + kh * 32));
                b[2 * p][0] = t[0]; b[2 * p][1] = t[1];
                b[2 * p + 1][0] = t[2]; b[2 * p + 1][1] = t[3];
            }
            #pragma unroll
            for (int mf = 0; mf < 2; mf++)
                #pragma unroll
                for (int nf = 0; nf < 8; nf++) {
                    MMA_F16(acc[mf][nf], ah[mf], b[nf]);
                    if (TT) MMA_F16(acc[mf][nf], al[mf], b[nf]);
                }
        }
    }

    // ---- epilogue: regs -> per-warp smem stage (16x65 fp32) -> coalesced stores ----
    __syncthreads();
    float* stg = (float*)dsm + wid * (16 * 65);
    const int gcol0 = col0 + wn * 64;
    const float bv0 = (EPI == 2) ? 0.f : bias[gcol0 + lane];
    const float bv1 = (EPI == 2) ? 0.f : bias[gcol0 + 32 + lane];
    const int r1 = lane >> 2, c0 = (lane & 3) * 2;
    float* Cfz = (EPI == 2) ? Cf + (size_t)blockIdx.z * M * N : Cf;

    #pragma unroll
    for (int mf = 0; mf < 2; mf++) {
        #pragma unroll
        for (int nf = 0; nf < 8; nf++) {
            stg[r1 * 65 + nf * 8 + c0]           = acc[mf][nf][0];
            stg[r1 * 65 + nf * 8 + c0 + 1]       = acc[mf][nf][1];
            stg[(r1 + 8) * 65 + nf * 8 + c0]     = acc[mf][nf][2];
            stg[(r1 + 8) * 65 + nf * 8 + c0 + 1] = acc[mf][nf][3];
        }
        __syncwarp();
        const int grow = row0 + wm * 32 + mf * 16;
        #pragma unroll
        for (int r = 0; r < 16; r++) {
            float v0 = stg[r * 65 + lane] + bv0;
            float v1 = stg[r * 65 + 32 + lane] + bv1;
            if (EPI == 1) {
                v0 = gelu_exact(v0);
                v1 = gelu_exact(v1);
                size_t base = (size_t)(grow + r) * N + gcol0;
                Ch[base + lane] = __float2half(v0);
                Ch[base + 32 + lane] = __float2half(v1);
            } else {
                size_t base = (size_t)(grow + r) * N + gcol0;
                Cfz[base + lane] = v0;
                Cfz[base + 32 + lane] = v1;
            }
        }
        __syncwarp();
    }
}

// ============================================================
// weight transpose + fp16 convert: W[K][N] -> T[N][K]
// ============================================================
__global__ void wconv_kernel(const float* __restrict__ W, __half* __restrict__ Th,
                             int K, int N) {
    __shared__ float t[32][33];
    int k0 = blockIdx.x * 32, n0 = blockIdx.y * 32;
    int tx = threadIdx.x, ty = threadIdx.y;  // (32, 8)
    #pragma unroll
    for (int i = 0; i < 4; i++)
        t[ty + i * 8][tx] = W[(size_t)(k0 + ty + i * 8) * N + n0 + tx];
    __syncthreads();
    #pragma unroll
    for (int i = 0; i < 4; i++) {
        int n = n0 + ty + i * 8, k = k0 + tx;
        Th[(size_t)n * K + k] = __float2half(t[tx][ty + i * 8]);
    }
}

// ---------------- elementwise: x = template + positional encoding ----------------
__global__ void add_pe_kernel(const float* __restrict__ t, float* __restrict__ x) {
    int idx = blockIdx.x * 256 + threadIdx.x;
    if (idx >= M_ * D_) return;
    int d = idx % D_;
    int s = (idx / D_) % S_;
    int i2 = d & ~1;
    float div = expf((float)i2 * (-9.210340371976184f / (float)D_));
    float ang = (float)s * div;
    float pe = (d & 1) ? cosf(ang) : sinf(ang);
    x[idx] = t[idx] + pe;
}

// ---------------- pooled = mean over P, emitted as fp16 hi/lo ----------------
__global__ void pool_kernel(const float* __restrict__ ps,
                            __half* __restrict__ ph, __half* __restrict__ pl) {
    int idx = blockIdx.x * 256 + threadIdx.x;
    if (idx >= M_ * D_) return;
    int bs = idx / D_;
    int c  = idx % D_;
    const float* base = ps + (size_t)bs * (P_ * D_) + c;
    float s = 0.f;
    #pragma unroll
    for (int p = 0; p < P_; p++) s += base[p * D_];
    float m = s * (1.0f / P_);
    __half h, l;
    split_f16(m, h, l);
    ph[idx] = h; pl[idx] = l;
}

// ---------------- block-reduce helper ----------------
__device__ __forceinline__ float warp_sum(float v) {
    #pragma unroll
    for (int o = 16; o; o >>= 1) v += __shfl_down_sync(0xffffffffu, v, o);
    return v;
}

// ---------------- LayerNorm (row length 768) ----------------
// t = x (+ res) (+ res2) (+ colbias);  out = LN(t)*g + b;  optional fp16 hi/lo out
template <int F16OUT>
__global__ void ln_kernel(const float* __restrict__ x, const float* __restrict__ res,
                          const float* __restrict__ res2,
                          const float* __restrict__ colbias,
                          const float* __restrict__ g, const float* __restrict__ b,
                          float* __restrict__ out,
                          __half* __restrict__ oh, __half* __restrict__ ol) {
    const int row = blockIdx.x;
    const int tid = threadIdx.x;  // 256
    const float* xr = x + (size_t)row * D_;
    const float* rr = res ? res + (size_t)row * D_ : nullptr;
    const float* r2 = res2 ? res2 + (size_t)row * D_ : nullptr;

    float v[3];
    float s = 0.f, s2 = 0.f;
    #pragma unroll
    for (int i = 0; i < 3; i++) {
        int c = tid + i * 256;
        float t = xr[c];
        if (rr) t += rr[c];
        if (r2) t += r2[c];
        if (colbias) t += colbias[c];
        v[i] = t; s += t; s2 += t * t;
    }

    __shared__ float red[2][8];
    __shared__ float stat[2];
    int lane = tid & 31, wid = tid >> 5;
    s = warp_sum(s); s2 = warp_sum(s2);
    if (lane == 0) { red[0][wid] = s; red[1][wid] = s2; }
    __syncthreads();
    if (wid == 0) {
        float a = (lane < 8) ? red[0][lane] : 0.f;
        float c = (lane < 8) ? red[1][lane] : 0.f;
        a = warp_sum(a); c = warp_sum(c);
        if (lane == 0) {
            float mean = a * (1.0f / D_);
            float var = c * (1.0f / D_) - mean * mean;
            stat[0] = mean;
            stat[1] = rsqrtf(var + EPS_);
        }
    }
    __syncthreads();
    float mean = stat[0], inv = stat[1];
    float* orow = out + (size_t)row * D_;
    #pragma unroll
    for (int i = 0; i < 3; i++) {
        int c = tid + i * 256;
        float o = (v[i] - mean) * inv * g[c] + b[c];
        orow[c] = o;
        if (F16OUT) {
            __half h, l;
            split_f16(o, h, l);
            oh[(size_t)row * D_ + c] = h;
            ol[(size_t)row * D_ + c] = l;
        }
    }
}

// ---------------- param_bias[b,h] = (pe_bh @ pe_bh^T) * inv_sqrt_hd ----------------
__global__ __launch_bounds__(256)
void pbias_kernel(const float* __restrict__ enc, float* __restrict__ pbias) {
    __shared__ float Es[112 * 97];
    const int b = blockIdx.x >> 3;
    const int h = blockIdx.x & 7;
    const int tid = threadIdx.x;
    const float* src = enc + (size_t)(b * S_) * D_ + h * HD_;

    for (int i = tid; i < 112 * 96; i += 256) {
        int s = i / 96, d = i - s * 96;
        Es[s * 97 + d] = (s < S_) ? src[(size_t)s * D_ + d] : 0.f;
    }
    __syncthreads();

    const int tx = tid & 15, ty = tid >> 4;
    float acc[7][7];
    #pragma unroll
    for (int ii = 0; ii < 7; ii++)
        #pragma unroll
        for (int jj = 0; jj < 7; jj++) acc[ii][jj] = 0.f;

    for (int d = 0; d < 96; d++) {
        float a[7], bb[7];
        #pragma unroll
        for (int ii = 0; ii < 7; ii++) a[ii]  = Es[(ty + 16 * ii) * 97 + d];
        #pragma unroll
        for (int jj = 0; jj < 7; jj++) bb[jj] = Es[(tx + 16 * jj) * 97 + d];
        #pragma unroll
        for (int ii = 0; ii < 7; ii++)
            #pragma unroll
            for (int jj = 0; jj < 7; jj++) acc[ii][jj] += a[ii] * bb[jj];
    }

    float* dst = pbias + (size_t)blockIdx.x * (S_ * S_);
    #pragma unroll
    for (int ii = 0; ii < 7; ii++) {
        int i = ty + 16 * ii;
        if (i >= S_) continue;
        #pragma unroll
        for (int jj = 0; jj < 7; jj++) {
            int j = tx + 16 * jj;
            if (j < S_) dst[i * S_ + j] = acc[ii][jj] * INV_SQRT_HD;
        }
    }
}

// ---------------- fused attention per (b,h) ----------------
#define ATTN_SMEM ((112 * 97 + 112 * 101) * 4)
__global__ __launch_bounds__(256)
void attn_kernel(const float* __restrict__ x, const float* __restrict__ pbias,
                 float* __restrict__ out) {
    extern __shared__ float smem[];
    float* Qs = smem;               // [112][97]
    float* Ss = smem + 112 * 97;    // [112][101]

    const int b = blockIdx.x >> 3;
    const int h = blockIdx.x & 7;
    const int tid = threadIdx.x;
    const float* xb = x + (size_t)(b * S_) * D_ + h * HD_;

    for (int i = tid; i < 112 * 96; i += 256) {
        int s = i / 96, d = i - s * 96;
        Qs[s * 97 + d] = (s < S_) ? xb[(size_t)s * D_ + d] : 0.f;
    }
    __syncthreads();

    const int tx = tid & 15, ty = tid >> 4;
    {
        float acc[7][7];
        #pragma unroll
        for (int ii = 0; ii < 7; ii++)
            #pragma unroll
            for (int jj = 0; jj < 7; jj++) acc[ii][jj] = 0.f;

        for (int d = 0; d < 96; d++) {
            float a[7], bb[7];
            #pragma unroll
            for (int ii = 0; ii < 7; ii++) a[ii]  = Qs[(ty + 16 * ii) * 97 + d];
            #pragma unroll
            for (int jj = 0; jj < 7; jj++) bb[jj] = Qs[(tx + 16 * jj) * 97 + d];
            #pragma unroll
            for (int ii = 0; ii < 7; ii++)
                #pragma unroll
                for (int jj = 0; jj < 7; jj++) acc[ii][jj] += a[ii] * bb[jj];
        }
        const float* pb = pbias + (size_t)blockIdx.x * (S_ * S_);
        #pragma unroll
        for (int ii = 0; ii < 7; ii++) {
            int i = ty + 16 * ii;
            if (i >= S_) continue;
            #pragma unroll
            for (int jj = 0; jj < 7; jj++) {
                int j = tx + 16 * jj;
                if (j < S_)
                    Ss[i * 101 + j] = acc[ii][jj] * INV_SQRT_HD + pb[i * S_ + j];
            }
        }
    }
    __syncthreads();

    if (tid < S_) {
        float* row = Ss + tid * 101;
        float m = -1e30f;
        for (int j = 0; j < S_; j++) m = fmaxf(m, row[j]);
        float sum = 0.f;
        for (int j = 0; j < S_; j++) { float e = expf(row[j] - m); row[j] = e; sum += e; }
        float inv = 1.0f / sum;
        for (int j = 0; j < S_; j++) row[j] *= inv;
    }
    __syncthreads();

    {
        float acc[7][6];
        #pragma unroll
        for (int ii = 0; ii < 7; ii++)
            #pragma unroll
            for (int jj = 0; jj < 6; jj++) acc[ii][jj] = 0.f;

        for (int j = 0; j < S_; j++) {
            float a[7], bb[6];
            #pragma unroll
            for (int ii = 0; ii < 7; ii++) a[ii]  = Ss[(ty + 16 * ii) * 101 + j];
            #pragma unroll
            for (int jj = 0; jj < 6; jj++) bb[jj] = Qs[j * 97 + tx + 16 * jj];
            #pragma unroll
            for (int ii = 0; ii < 7; ii++)
                #pragma unroll
                for (int jj = 0; jj < 6; jj++) acc[ii][jj] += a[ii] * bb[jj];
        }
        float* dst = out + (size_t)(b * S_) * D_ + h * HD_;
        #pragma unroll
        for (int ii = 0; ii < 7; ii++) {
            int i = ty + 16 * ii;
            if (i >= S_) continue;
            #pragma unroll
            for (int jj = 0; jj < 6; jj++) {
                int dd = tx + 16 * jj;
                dst[(size_t)i * D_ + dd] = acc[ii][jj];
            }
        }
    }
}

// ---------------- final classifier ----------------
__global__ void fc_kernel(const float* __restrict__ x, const float* __restrict__ Wfc,
                          const float* __restrict__ bfc, float* __restrict__ out) {
    const int b = blockIdx.x;
    const int tid = threadIdx.x;
    const float* xr = x + (size_t)b * (S_ * D_);
    float a0 = 0.f, a1 = 0.f;
    for (int i = tid; i < S_ * D_; i += 256) {
        float v = xr[i];
        a0 += v * Wfc[2 * i];
        a1 += v * Wfc[2 * i + 1];
    }
    __shared__ float red[2][8];
    int lane = tid & 31, wid = tid >> 5;
    a0 = warp_sum(a0); a1 = warp_sum(a1);
    if (lane == 0) { red[0][wid] = a0; red[1][wid] = a1; }
    __syncthreads();
    if (wid == 0) {
        float r0 = (lane < 8) ? red[0][lane] : 0.f;
        float r1 = (lane < 8) ? red[1][lane] : 0.f;
        r0 = warp_sum(r0); r1 = warp_sum(r1);
        if (lane == 0) {
            out[2 * b + 0] = r0 + bfc[0];
            out[2 * b + 1] = r1 + bfc[1];
        }
    }
}

// ---------------- launch ----------------
extern "C" void kernel_launch(void* const* d_in, const int* in_sizes, int n_in,
                              void* d_out, int out_size) {
    const float* tseq = (const float*)d_in[0];
    const float* pseq = (const float*)d_in[1];
    const float* Wc  = (const float*)d_in[2];
    const float* bc  = (const float*)d_in[3];
    const float* gp  = (const float*)d_in[4];
    const float* bp  = (const float*)d_in[5];
    const float* W1  = (const float*)d_in[6];
    const float* b1  = (const float*)d_in[7];
    const float* W2  = (const float*)d_in[8];
    const float* b2  = (const float*)d_in[9];
    const float* g1  = (const float*)d_in[10];
    const float* bn1 = (const float*)d_in[11];
    const float* g2  = (const float*)d_in[12];
    const float* bn2 = (const float*)d_in[13];
    const float* Wfc = (const float*)d_in[14];
    const float* bfc = (const float*)d_in[15];
    float* out = (float*)d_out;

    float *x, *enc, *pbias, *part;
    __half *xhi, *xlo, *phi, *plo, *ffhi;
    __half *w1h, *w2h, *wch;
    cudaGetSymbolAddress((void**)&x, g_x);
    cudaGetSymbolAddress((void**)&enc, g_enc);
    cudaGetSymbolAddress((void**)&pbias, g_pbias);
    cudaGetSymbolAddress((void**)&part, g_part);
    cudaGetSymbolAddress((void**)&xhi, g_xhi);
    cudaGetSymbolAddress((void**)&xlo, g_xlo);
    cudaGetSymbolAddress((void**)&phi, g_phi);
    cudaGetSymbolAddress((void**)&plo, g_plo);
    cudaGetSymbolAddress((void**)&ffhi, g_ffhi);
    cudaGetSymbolAddress((void**)&w1h, g_w1h);
    cudaGetSymbolAddress((void**)&w2h, g_w2h);
    cudaGetSymbolAddress((void**)&wch, g_wch);
    float* part0 = part;
    float* part1 = part + (size_t)M_ * D_;

    cudaFuncSetAttribute(attn_kernel, cudaFuncAttributeMaxDynamicSharedMemorySize, ATTN_SMEM);
    cudaFuncSetAttribute((mma_gemm<1, 1>), cudaFuncAttributeMaxDynamicSharedMemorySize, GEMM_SMEM);
    cudaFuncSetAttribute((mma_gemm<2, 1>), cudaFuncAttributeMaxDynamicSharedMemorySize, GEMM_SMEM);
    cudaFuncSetAttribute((mma_gemm<2, 0>), cudaFuncAttributeMaxDynamicSharedMemorySize, GEMM_SMEM);

    // weight transpose + fp16 convert (tiny, one-time per launch)
    wconv_kernel<<<dim3(D_ / 32, FF_ / 32), dim3(32, 8)>>>(W1, w1h, D_, FF_);
    wconv_kernel<<<dim3(FF_ / 32, D_ / 32), dim3(32, 8)>>>(W2, w2h, FF_, D_);
    wconv_kernel<<<dim3(D_ / 32, D_ / 32),  dim3(32, 8)>>>(Wc, wch, D_, D_);

    const int total = M_ * D_;
    add_pe_kernel<<<(total + 255) / 256, 256>>>(tseq, x);
    pool_kernel<<<(total + 255) / 256, 256>>>(pseq, phi, plo);

    // param encoder: enc = LN(pooled @ Wc + bc)  (split-K=2 -> partial buffers)
    mma_gemm<2, 1><<<dim3(D_ / BNT, M_ / BMT, 2), 256, GEMM_SMEM>>>(
        phi, plo, wch, nullptr, part0, nullptr, M_, D_, D_);
    ln_kernel<0><<<M_, 256>>>(part0, part1, nullptr, bc, gp, bp, enc, nullptr, nullptr);

    // layer-invariant attention bias
    pbias_kernel<<<B_ * H_, 256>>>(enc, pbias);

    for (int l = 0; l < NLAYERS; l++) {
        attn_kernel<<<B_ * H_, 256, ATTN_SMEM>>>(x, pbias, part0);
        ln_kernel<1><<<M_, 256>>>(x, part0, nullptr, nullptr, g1, bn1, x, xhi, xlo);
        // FFN1: 2-term exact A, fp16 W1, gelu -> single fp16 ff
        mma_gemm<1, 1><<<dim3(FF_ / BNT, M_ / BMT), 256, GEMM_SMEM>>>(
            xhi, xlo, w1h, b1, nullptr, ffhi, M_, FF_, D_);
        // FFN2: 1-term fp16 A (gelu output), split-K=2 -> fp32 partials, b2 folded into LN
        mma_gemm<2, 0><<<dim3(D_ / BNT, M_ / BMT, 2), 256, GEMM_SMEM>>>(
            ffhi, nullptr, w2h, nullptr, part0, nullptr, M_, D_, FF_);
        ln_kernel<0><<<M_, 256>>>(x, part0, part1, b2, g2, bn2, x, nullptr, nullptr);
    }

    fc_kernel<<<B_, 256>>>(x, Wfc, bfc, out);
}

// round 9
// speedup vs baseline: 2.0985x; 1.1627x over previous
#include <cuda_runtime.h>
#include <cuda_fp16.h>
#include <math.h>
#include <stdint.h>

// ---------------- problem constants ----------------
#define B_   64
#define S_   100
#define D_   768
#define H_   8
#define HD_  96
#define P_   8
#define FF_  3072
#define M_   (B_ * S_)            // 6400 rows
#define NLAYERS 4
#define EPS_ 1e-5f
#define INV_SQRT_HD 0.10206207261596575f   // 1/sqrt(96)

// ---------------- device scratch ----------------
__device__ float g_x[M_ * D_];
__device__ float g_enc[M_ * D_];
__device__ float g_pbias[B_ * H_ * S_ * S_];
__device__ float g_part[2][M_ * D_];   // split-K fp32 partials

__device__ __half g_xhi[M_ * D_];
__device__ __half g_phi[M_ * D_];
__device__ __half g_plo[M_ * D_];
__device__ __half g_ffhi[(size_t)M_ * FF_];
__device__ __half g_w1h[(size_t)FF_ * D_];   // [N=3072][K=768] fp16
__device__ __half g_w2h[(size_t)D_ * FF_];   // [N=768][K=3072] fp16
__device__ __half g_wch[(size_t)D_ * D_];    // [N=768][K=768]  fp16

// ============================================================
// PTX helpers (mma.sync / ldmatrix / cp.async — all baseline sm_80+)
// ============================================================
__device__ __forceinline__ uint32_t smem_u32(const void* p) {
    uint32_t a;
    asm("{ .reg .u64 t; cvta.to.shared.u64 t, %1; cvt.u32.u64 %0, t; }" : "=r"(a) : "l"(p));
    return a;
}

#define CP_ASYNC16(dst, src) \
    asm volatile("cp.async.cg.shared.global [%0], [%1], 16;\n" :: "r"(dst), "l"(src) : "memory")
#define CP_COMMIT() asm volatile("cp.async.commit_group;\n" ::: "memory")
#define CP_WAIT0()  asm volatile("cp.async.wait_group 0;\n" ::: "memory")
#define CP_WAIT1()  asm volatile("cp.async.wait_group 1;\n" ::: "memory")

#define LDSM4(r, addr) \
    asm volatile("ldmatrix.sync.aligned.m8n8.x4.shared.b16 {%0,%1,%2,%3}, [%4];" \
        : "=r"((r)[0]), "=r"((r)[1]), "=r"((r)[2]), "=r"((r)[3]) : "r"(addr))

#define MMA_F16(c, a, b) \
    asm volatile("mma.sync.aligned.m16n8k16.row.col.f32.f16.f16.f32 " \
        "{%0,%1,%2,%3}, {%4,%5,%6,%7}, {%8,%9}, {%0,%1,%2,%3};" \
        : "+f"((c)[0]), "+f"((c)[1]), "+f"((c)[2]), "+f"((c)[3]) \
        : "r"((a)[0]), "r"((a)[1]), "r"((a)[2]), "r"((a)[3]), "r"((b)[0]), "r"((b)[1]))

__device__ __forceinline__ float gelu_exact(float v) {
    return 0.5f * v * (1.0f + erff(v * 0.70710678118654752f));
}
__device__ __forceinline__ void split_f16(float v, __half& h, __half& l) {
    h = __float2half(v);
    l = __float2half(v - __half2float(h));
}

// ============================================================
// GEMM: C[M,N] = A[M,K] @ B^T[N,K] (+ bias)
// TT=1: A = Ah + Al (fp16 pair, exact to 2^-22); 2 MMAs per fragment.
// TT=0: A = Ah single fp16; 1 MMA per fragment.
// B single fp16 in both cases.
// EPI 1: bias + gelu -> single fp16 out (Ch).
// EPI 2: plain fp32 partial store, NO bias; z-th split writes Cf + z*M*N.
// 3-stage cp.async ring, 2 CTAs/SM, one barrier per k-step.
// ============================================================
#define BMT 128
#define BNT 128
#define BKS 32
#define NSTAGE 3
#define MATB 10240u                // 128*40*2 bytes (rows padded to 40 fp16)
#define BUFB (3 * MATB)            // 30720 (TT=0 leaves the Al slot unused)
#define GEMM_SMEM (NSTAGE * BUFB)  // 92160

template <int EPI, int TT>
__global__ __launch_bounds__(256, 2)
void mma_gemm(const __half* __restrict__ Ah_, const __half* __restrict__ Al_,
              const __half* __restrict__ Bh_,
              const float* __restrict__ bias,
              float* __restrict__ Cf, __half* __restrict__ Ch,
              int M, int N, int K)
{
    extern __shared__ char dsm[];
    const uint32_t sb0 = smem_u32(dsm);
    const int tid = threadIdx.x;
    const int wid = tid >> 5, lane = tid & 31;
    const int wm = wid >> 1, wn = wid & 1;          // warp tile: 32 x 64
    const int row0 = blockIdx.y * BMT, col0 = blockIdx.x * BNT;
    const int Kloc = K / gridDim.z;
    const int koff = blockIdx.z * Kloc;
    const int NS = Kloc / BKS;

    const __half* Ahp = Ah_ + koff;
    const __half* Alp = TT ? Al_ + koff : nullptr;
    const __half* Bhp = Bh_ + koff;

    float acc[2][8][4];
    #pragma unroll
    for (int i = 0; i < 2; i++)
        #pragma unroll
        for (int j = 0; j < 8; j++)
            #pragma unroll
            for (int k = 0; k < 4; k++) acc[i][j][k] = 0.f;

    // ldmatrix per-lane base offsets (bytes, within one stage buffer)
    const uint32_t aoff = (uint32_t)((wm * 32 + (lane & 15)) * 80 + (lane >> 4) * 16);
    const uint32_t boff = (uint32_t)((wn * 64 + ((lane >> 4) << 3) + (lane & 7)) * 80
                                     + ((lane >> 3) & 1) * 16);
    const uint32_t BOFFM = (TT ? 2u : 1u) * MATB;    // B matrix slot

    auto load_step = [&](int s) {
        const uint32_t sb = sb0 + (uint32_t)(s % NSTAGE) * BUFB;
        const int k0 = s * BKS;
        #pragma unroll
        for (int i = 0; i < (TT ? 6 : 4); i++) {
            int u = i * 256 + tid;
            int mat = u >> 9;          // TT=1: 0 Ah, 1 Al, 2 B ; TT=0: 0 Ah, 1 B
            int v = u & 511;
            int r = v >> 2, c = v & 3;
            const __half* src;
            if (TT) {
                if (mat == 0)      src = Ahp + (size_t)(row0 + r) * K + k0 + c * 8;
                else if (mat == 1) src = Alp + (size_t)(row0 + r) * K + k0 + c * 8;
                else               src = Bhp + (size_t)(col0 + r) * K + k0 + c * 8;
            } else {
                if (mat == 0)      src = Ahp + (size_t)(row0 + r) * K + k0 + c * 8;
                else               src = Bhp + (size_t)(col0 + r) * K + k0 + c * 8;
            }
            CP_ASYNC16(sb + (uint32_t)mat * MATB + (uint32_t)(r * 80 + c * 16), src);
        }
        CP_COMMIT();
    };

    load_step(0);
    if (NS > 1) load_step(1);

    for (int s = 0; s < NS; s++) {
        if (s < NS - 1) { CP_WAIT1(); } else { CP_WAIT0(); }
        __syncthreads();
        if (s + 2 < NS) load_step(s + 2);

        const uint32_t sb = sb0 + (uint32_t)(s % NSTAGE) * BUFB;
        #pragma unroll
        for (int kh = 0; kh < 2; kh++) {     // two k16 halves of the k32 step
            uint32_t ah[2][4], al[2][4], b[8][2];
            #pragma unroll
            for (int mf = 0; mf < 2; mf++) {
                LDSM4(ah[mf], sb + aoff + (uint32_t)(mf * 1280 + kh * 32));
                if (TT) LDSM4(al[mf], sb + MATB + aoff + (uint32_t)(mf * 1280 + kh * 32));
            }
            #pragma unroll
            for (int p = 0; p < 4; p++) {
                uint32_t t[4];
                LDSM4(t, sb + BOFFM + boff + (uint32_t)(p * 1280 + kh * 32));
                b[2 * p][0] = t[0]; b[2 * p][1] = t[1];
                b[2 * p + 1][0] = t[2]; b[2 * p + 1][1] = t[3];
            }
            #pragma unroll
            for (int mf = 0; mf < 2; mf++)
                #pragma unroll
                for (int nf = 0; nf < 8; nf++) {
                    MMA_F16(acc[mf][nf], ah[mf], b[nf]);
                    if (TT) MMA_F16(acc[mf][nf], al[mf], b[nf]);
                }
        }
    }

    // ---- epilogue: regs -> per-warp smem stage (16x65 fp32) -> coalesced stores ----
    __syncthreads();
    float* stg = (float*)dsm + wid * (16 * 65);
    const int gcol0 = col0 + wn * 64;
    const float bv0 = (EPI == 2) ? 0.f : bias[gcol0 + lane];
    const float bv1 = (EPI == 2) ? 0.f : bias[gcol0 + 32 + lane];
    const int r1 = lane >> 2, c0 = (lane & 3) * 2;
    float* Cfz = (EPI == 2) ? Cf + (size_t)blockIdx.z * M * N : Cf;

    #pragma unroll
    for (int mf = 0; mf < 2; mf++) {
        #pragma unroll
        for (int nf = 0; nf < 8; nf++) {
            stg[r1 * 65 + nf * 8 + c0]           = acc[mf][nf][0];
            stg[r1 * 65 + nf * 8 + c0 + 1]       = acc[mf][nf][1];
            stg[(r1 + 8) * 65 + nf * 8 + c0]     = acc[mf][nf][2];
            stg[(r1 + 8) * 65 + nf * 8 + c0 + 1] = acc[mf][nf][3];
        }
        __syncwarp();
        const int grow = row0 + wm * 32 + mf * 16;
        #pragma unroll
        for (int r = 0; r < 16; r++) {
            float v0 = stg[r * 65 + lane] + bv0;
            float v1 = stg[r * 65 + 32 + lane] + bv1;
            if (EPI == 1) {
                v0 = gelu_exact(v0);
                v1 = gelu_exact(v1);
                size_t base = (size_t)(grow + r) * N + gcol0;
                Ch[base + lane] = __float2half(v0);
                Ch[base + 32 + lane] = __float2half(v1);
            } else {
                size_t base = (size_t)(grow + r) * N + gcol0;
                Cfz[base + lane] = v0;
                Cfz[base + 32 + lane] = v1;
            }
        }
        __syncwarp();
    }
}

// ============================================================
// weight transpose + fp16 convert: W[K][N] -> T[N][K]
// ============================================================
__global__ void wconv_kernel(const float* __restrict__ W, __half* __restrict__ Th,
                             int K, int N) {
    __shared__ float t[32][33];
    int k0 = blockIdx.x * 32, n0 = blockIdx.y * 32;
    int tx = threadIdx.x, ty = threadIdx.y;  // (32, 8)
    #pragma unroll
    for (int i = 0; i < 4; i++)
        t[ty + i * 8][tx] = W[(size_t)(k0 + ty + i * 8) * N + n0 + tx];
    __syncthreads();
    #pragma unroll
    for (int i = 0; i < 4; i++) {
        int n = n0 + ty + i * 8, k = k0 + tx;
        Th[(size_t)n * K + k] = __float2half(t[tx][ty + i * 8]);
    }
}

// ---------------- elementwise: x = template + positional encoding ----------------
__global__ void add_pe_kernel(const float* __restrict__ t, float* __restrict__ x) {
    int idx = blockIdx.x * 256 + threadIdx.x;
    if (idx >= M_ * D_) return;
    int d = idx % D_;
    int s = (idx / D_) % S_;
    int i2 = d & ~1;
    float div = expf((float)i2 * (-9.210340371976184f / (float)D_));
    float ang = (float)s * div;
    float pe = (d & 1) ? cosf(ang) : sinf(ang);
    x[idx] = t[idx] + pe;
}

// ---------------- pooled = mean over P, emitted as fp16 hi/lo ----------------
__global__ void pool_kernel(const float* __restrict__ ps,
                            __half* __restrict__ ph, __half* __restrict__ pl) {
    int idx = blockIdx.x * 256 + threadIdx.x;
    if (idx >= M_ * D_) return;
    int bs = idx / D_;
    int c  = idx % D_;
    const float* base = ps + (size_t)bs * (P_ * D_) + c;
    float s = 0.f;
    #pragma unroll
    for (int p = 0; p < P_; p++) s += base[p * D_];
    float m = s * (1.0f / P_);
    __half h, l;
    split_f16(m, h, l);
    ph[idx] = h; pl[idx] = l;
}

// ---------------- block-reduce helper ----------------
__device__ __forceinline__ float warp_sum(float v) {
    #pragma unroll
    for (int o = 16; o; o >>= 1) v += __shfl_down_sync(0xffffffffu, v, o);
    return v;
}

// ---------------- LayerNorm (row length 768) ----------------
// t = x (+ res) (+ res2) (+ colbias);  out = LN(t)*g + b;  optional single-fp16 out
template <int F16OUT>
__global__ void ln_kernel(const float* __restrict__ x, const float* __restrict__ res,
                          const float* __restrict__ res2,
                          const float* __restrict__ colbias,
                          const float* __restrict__ g, const float* __restrict__ b,
                          float* __restrict__ out,
                          __half* __restrict__ oh) {
    const int row = blockIdx.x;
    const int tid = threadIdx.x;  // 256
    const float* xr = x + (size_t)row * D_;
    const float* rr = res ? res + (size_t)row * D_ : nullptr;
    const float* r2 = res2 ? res2 + (size_t)row * D_ : nullptr;

    float v[3];
    float s = 0.f, s2 = 0.f;
    #pragma unroll
    for (int i = 0; i < 3; i++) {
        int c = tid + i * 256;
        float t = xr[c];
        if (rr) t += rr[c];
        if (r2) t += r2[c];
        if (colbias) t += colbias[c];
        v[i] = t; s += t; s2 += t * t;
    }

    __shared__ float red[2][8];
    __shared__ float stat[2];
    int lane = tid & 31, wid = tid >> 5;
    s = warp_sum(s); s2 = warp_sum(s2);
    if (lane == 0) { red[0][wid] = s; red[1][wid] = s2; }
    __syncthreads();
    if (wid == 0) {
        float a = (lane < 8) ? red[0][lane] : 0.f;
        float c = (lane < 8) ? red[1][lane] : 0.f;
        a = warp_sum(a); c = warp_sum(c);
        if (lane == 0) {
            float mean = a * (1.0f / D_);
            float var = c * (1.0f / D_) - mean * mean;
            stat[0] = mean;
            stat[1] = rsqrtf(var + EPS_);
        }
    }
    __syncthreads();
    float mean = stat[0], inv = stat[1];
    float* orow = out + (size_t)row * D_;
    #pragma unroll
    for (int i = 0; i < 3; i++) {
        int c = tid + i * 256;
        float o = (v[i] - mean) * inv * g[c] + b[c];
        orow[c] = o;
        if (F16OUT) {
            oh[(size_t)row * D_ + c] = __float2half(o);
        }
    }
}

// ---------------- param_bias[b,h] = (pe_bh @ pe_bh^T) * inv_sqrt_hd ----------------
__global__ __launch_bounds__(256)
void pbias_kernel(const float* __restrict__ enc, float* __restrict__ pbias) {
    __shared__ float Es[112 * 97];
    const int b = blockIdx.x >> 3;
    const int h = blockIdx.x & 7;
    const int tid = threadIdx.x;
    const float* src = enc + (size_t)(b * S_) * D_ + h * HD_;

    for (int i = tid; i < 112 * 96; i += 256) {
        int s = i / 96, d = i - s * 96;
        Es[s * 97 + d] = (s < S_) ? src[(size_t)s * D_ + d] : 0.f;
    }
    __syncthreads();

    const int tx = tid & 15, ty = tid >> 4;
    float acc[7][7];
    #pragma unroll
    for (int ii = 0; ii < 7; ii++)
        #pragma unroll
        for (int jj = 0; jj < 7; jj++) acc[ii][jj] = 0.f;

    for (int d = 0; d < 96; d++) {
        float a[7], bb[7];
        #pragma unroll
        for (int ii = 0; ii < 7; ii++) a[ii]  = Es[(ty + 16 * ii) * 97 + d];
        #pragma unroll
        for (int jj = 0; jj < 7; jj++) bb[jj] = Es[(tx + 16 * jj) * 97 + d];
        #pragma unroll
        for (int ii = 0; ii < 7; ii++)
            #pragma unroll
            for (int jj = 0; jj < 7; jj++) acc[ii][jj] += a[ii] * bb[jj];
    }

    float* dst = pbias + (size_t)blockIdx.x * (S_ * S_);
    #pragma unroll
    for (int ii = 0; ii < 7; ii++) {
        int i = ty + 16 * ii;
        if (i >= S_) continue;
        #pragma unroll
        for (int jj = 0; jj < 7; jj++) {
            int j = tx + 16 * jj;
            if (j < S_) dst[i * S_ + j] = acc[ii][jj] * INV_SQRT_HD;
        }
    }
}

// ---------------- fused attention per (b,h) ----------------
#define ATTN_SMEM ((112 * 97 + 112 * 101) * 4)
__global__ __launch_bounds__(256)
void attn_kernel(const float* __restrict__ x, const float* __restrict__ pbias,
                 float* __restrict__ out) {
    extern __shared__ float smem[];
    float* Qs = smem;               // [112][97]
    float* Ss = smem + 112 * 97;    // [112][101]

    const int b = blockIdx.x >> 3;
    const int h = blockIdx.x & 7;
    const int tid = threadIdx.x;
    const float* xb = x + (size_t)(b * S_) * D_ + h * HD_;

    for (int i = tid; i < 112 * 96; i += 256) {
        int s = i / 96, d = i - s * 96;
        Qs[s * 97 + d] = (s < S_) ? xb[(size_t)s * D_ + d] : 0.f;
    }
    __syncthreads();

    const int tx = tid & 15, ty = tid >> 4;
    {
        float acc[7][7];
        #pragma unroll
        for (int ii = 0; ii < 7; ii++)
            #pragma unroll
            for (int jj = 0; jj < 7; jj++) acc[ii][jj] = 0.f;

        for (int d = 0; d < 96; d++) {
            float a[7], bb[7];
            #pragma unroll
            for (int ii = 0; ii < 7; ii++) a[ii]  = Qs[(ty + 16 * ii) * 97 + d];
            #pragma unroll
            for (int jj = 0; jj < 7; jj++) bb[jj] = Qs[(tx + 16 * jj) * 97 + d];
            #pragma unroll
            for (int ii = 0; ii < 7; ii++)
                #pragma unroll
                for (int jj = 0; jj < 7; jj++) acc[ii][jj] += a[ii] * bb[jj];
        }
        const float* pb = pbias + (size_t)blockIdx.x * (S_ * S_);
        #pragma unroll
        for (int ii = 0; ii < 7; ii++) {
            int i = ty + 16 * ii;
            if (i >= S_) continue;
            #pragma unroll
            for (int jj = 0; jj < 7; jj++) {
                int j = tx + 16 * jj;
                if (j < S_)
                    Ss[i * 101 + j] = acc[ii][jj] * INV_SQRT_HD + pb[i * S_ + j];
            }
        }
    }
    __syncthreads();

    if (tid < S_) {
        float* row = Ss + tid * 101;
        float m = -1e30f;
        for (int j = 0; j < S_; j++) m = fmaxf(m, row[j]);
        float sum = 0.f;
        for (int j = 0; j < S_; j++) { float e = expf(row[j] - m); row[j] = e; sum += e; }
        float inv = 1.0f / sum;
        for (int j = 0; j < S_; j++) row[j] *= inv;
    }
    __syncthreads();

    {
        float acc[7][6];
        #pragma unroll
        for (int ii = 0; ii < 7; ii++)
            #pragma unroll
            for (int jj = 0; jj < 6; jj++) acc[ii][jj] = 0.f;

        for (int j = 0; j < S_; j++) {
            float a[7], bb[6];
            #pragma unroll
            for (int ii = 0; ii < 7; ii++) a[ii]  = Ss[(ty + 16 * ii) * 101 + j];
            #pragma unroll
            for (int jj = 0; jj < 6; jj++) bb[jj] = Qs[j * 97 + tx + 16 * jj];
            #pragma unroll
            for (int ii = 0; ii < 7; ii++)
                #pragma unroll
                for (int jj = 0; jj < 6; jj++) acc[ii][jj] += a[ii] * bb[jj];
        }
        float* dst = out + (size_t)(b * S_) * D_ + h * HD_;
        #pragma unroll
        for (int ii = 0; ii < 7; ii++) {
            int i = ty + 16 * ii;
            if (i >= S_) continue;
            #pragma unroll
            for (int jj = 0; jj < 6; jj++) {
                int dd = tx + 16 * jj;
                dst[(size_t)i * D_ + dd] = acc[ii][jj];
            }
        }
    }
}

// ---------------- final classifier ----------------
__global__ void fc_kernel(const float* __restrict__ x, const float* __restrict__ Wfc,
                          const float* __restrict__ bfc, float* __restrict__ out) {
    const int b = blockIdx.x;
    const int tid = threadIdx.x;
    const float* xr = x + (size_t)b * (S_ * D_);
    float a0 = 0.f, a1 = 0.f;
    for (int i = tid; i < S_ * D_; i += 256) {
        float v = xr[i];
        a0 += v * Wfc[2 * i];
        a1 += v * Wfc[2 * i + 1];
    }
    __shared__ float red[2][8];
    int lane = tid & 31, wid = tid >> 5;
    a0 = warp_sum(a0); a1 = warp_sum(a1);
    if (lane == 0) { red[0][wid] = a0; red[1][wid] = a1; }
    __syncthreads();
    if (wid == 0) {
        float r0 = (lane < 8) ? red[0][lane] : 0.f;
        float r1 = (lane < 8) ? red[1][lane] : 0.f;
        r0 = warp_sum(r0); r1 = warp_sum(r1);
        if (lane == 0) {
            out[2 * b + 0] = r0 + bfc[0];
            out[2 * b + 1] = r1 + bfc[1];
        }
    }
}

// ---------------- launch ----------------
extern "C" void kernel_launch(void* const* d_in, const int* in_sizes, int n_in,
                              void* d_out, int out_size) {
    const float* tseq = (const float*)d_in[0];
    const float* pseq = (const float*)d_in[1];
    const float* Wc  = (const float*)d_in[2];
    const float* bc  = (const float*)d_in[3];
    const float* gp  = (const float*)d_in[4];
    const float* bp  = (const float*)d_in[5];
    const float* W1  = (const float*)d_in[6];
    const float* b1  = (const float*)d_in[7];
    const float* W2  = (const float*)d_in[8];
    const float* b2  = (const float*)d_in[9];
    const float* g1  = (const float*)d_in[10];
    const float* bn1 = (const float*)d_in[11];
    const float* g2  = (const float*)d_in[12];
    const float* bn2 = (const float*)d_in[13];
    const float* Wfc = (const float*)d_in[14];
    const float* bfc = (const float*)d_in[15];
    float* out = (float*)d_out;

    float *x, *enc, *pbias, *part;
    __half *xhi, *phi, *plo, *ffhi;
    __half *w1h, *w2h, *wch;
    cudaGetSymbolAddress((void**)&x, g_x);
    cudaGetSymbolAddress((void**)&enc, g_enc);
    cudaGetSymbolAddress((void**)&pbias, g_pbias);
    cudaGetSymbolAddress((void**)&part, g_part);
    cudaGetSymbolAddress((void**)&xhi, g_xhi);
    cudaGetSymbolAddress((void**)&phi, g_phi);
    cudaGetSymbolAddress((void**)&plo, g_plo);
    cudaGetSymbolAddress((void**)&ffhi, g_ffhi);
    cudaGetSymbolAddress((void**)&w1h, g_w1h);
    cudaGetSymbolAddress((void**)&w2h, g_w2h);
    cudaGetSymbolAddress((void**)&wch, g_wch);
    float* part0 = part;
    float* part1 = part + (size_t)M_ * D_;

    cudaFuncSetAttribute(attn_kernel, cudaFuncAttributeMaxDynamicSharedMemorySize, ATTN_SMEM);
    cudaFuncSetAttribute((mma_gemm<1, 0>), cudaFuncAttributeMaxDynamicSharedMemorySize, GEMM_SMEM);
    cudaFuncSetAttribute((mma_gemm<2, 1>), cudaFuncAttributeMaxDynamicSharedMemorySize, GEMM_SMEM);
    cudaFuncSetAttribute((mma_gemm<2, 0>), cudaFuncAttributeMaxDynamicSharedMemorySize, GEMM_SMEM);

    // weight transpose + fp16 convert (tiny, one-time per launch)
    wconv_kernel<<<dim3(D_ / 32, FF_ / 32), dim3(32, 8)>>>(W1, w1h, D_, FF_);
    wconv_kernel<<<dim3(FF_ / 32, D_ / 32), dim3(32, 8)>>>(W2, w2h, FF_, D_);
    wconv_kernel<<<dim3(D_ / 32, D_ / 32),  dim3(32, 8)>>>(Wc, wch, D_, D_);

    const int total = M_ * D_;
    add_pe_kernel<<<(total + 255) / 256, 256>>>(tseq, x);
    pool_kernel<<<(total + 255) / 256, 256>>>(pseq, phi, plo);

    // param encoder: enc = LN(pooled @ Wc + bc)  (split-K=2, exact 2-term A)
    mma_gemm<2, 1><<<dim3(D_ / BNT, M_ / BMT, 2), 256, GEMM_SMEM>>>(
        phi, plo, wch, nullptr, part0, nullptr, M_, D_, D_);
    ln_kernel<0><<<M_, 256>>>(part0, part1, nullptr, bc, gp, bp, enc, nullptr);

    // layer-invariant attention bias
    pbias_kernel<<<B_ * H_, 256>>>(enc, pbias);

    for (int l = 0; l < NLAYERS; l++) {
        attn_kernel<<<B_ * H_, 256, ATTN_SMEM>>>(x, pbias, part0);
        ln_kernel<1><<<M_, 256>>>(x, part0, nullptr, nullptr, g1, bn1, x, xhi);
        // FFN1: single-fp16 A (LN output), gelu -> single fp16 ff
        mma_gemm<1, 0><<<dim3(FF_ / BNT, M_ / BMT), 256, GEMM_SMEM>>>(
            xhi, nullptr, w1h, b1, nullptr, ffhi, M_, FF_, D_);
        // FFN2: single-fp16 A (gelu output), split-K=2 -> fp32 partials, b2 folded into LN
        mma_gemm<2, 0><<<dim3(D_ / BNT, M_ / BMT, 2), 256, GEMM_SMEM>>>(
            ffhi, nullptr, w2h, nullptr, part0, nullptr, M_, D_, FF_);
        ln_kernel<0><<<M_, 256>>>(x, part0, part1, b2, g2, bn2, x, nullptr);
    }

    fc_kernel<<<B_, 256>>>(x, Wfc, bfc, out);
}

// round 10
// speedup vs baseline: 2.1414x; 1.0204x over previous
#include <cuda_runtime.h>
#include <cuda_fp16.h>
#include <math.h>
#include <stdint.h>

// ---------------- problem constants ----------------
#define B_   64
#define S_   100
#define D_   768
#define H_   8
#define HD_  96
#define P_   8
#define FF_  3072
#define M_   (B_ * S_)            // 6400 rows
#define NLAYERS 4
#define EPS_ 1e-5f
#define INV_SQRT_HD 0.10206207261596575f   // 1/sqrt(96)

// ---------------- device scratch ----------------
__device__ float g_x[M_ * D_];
__device__ float g_enc[M_ * D_];
__device__ float g_pbias[B_ * H_ * S_ * S_];
__device__ float g_part[2][M_ * D_];   // split-K fp32 partials
__device__ float g_pe[S_ * D_];

__device__ __half g_xhi[M_ * D_];
__device__ __half g_phi[M_ * D_];
__device__ __half g_plo[M_ * D_];
__device__ __half g_ffhi[(size_t)M_ * FF_];
__device__ __half g_w1h[(size_t)FF_ * D_];   // [N=3072][K=768] fp16
__device__ __half g_w2h[(size_t)D_ * FF_];   // [N=768][K=3072] fp16
__device__ __half g_wch[(size_t)D_ * D_];    // [N=768][K=768]  fp16

// ============================================================
// PTX helpers (mma.sync / ldmatrix / cp.async — all baseline sm_80+)
// ============================================================
__device__ __forceinline__ uint32_t smem_u32(const void* p) {
    uint32_t a;
    asm("{ .reg .u64 t; cvta.to.shared.u64 t, %1; cvt.u32.u64 %0, t; }" : "=r"(a) : "l"(p));
    return a;
}

#define CP_ASYNC16(dst, src) \
    asm volatile("cp.async.cg.shared.global [%0], [%1], 16;\n" :: "r"(dst), "l"(src) : "memory")
#define CP_COMMIT() asm volatile("cp.async.commit_group;\n" ::: "memory")
#define CP_WAIT0()  asm volatile("cp.async.wait_group 0;\n" ::: "memory")
#define CP_WAIT1()  asm volatile("cp.async.wait_group 1;\n" ::: "memory")

#define LDSM4(r, addr) \
    asm volatile("ldmatrix.sync.aligned.m8n8.x4.shared.b16 {%0,%1,%2,%3}, [%4];" \
        : "=r"((r)[0]), "=r"((r)[1]), "=r"((r)[2]), "=r"((r)[3]) : "r"(addr))

#define MMA_F16(c, a, b) \
    asm volatile("mma.sync.aligned.m16n8k16.row.col.f32.f16.f16.f32 " \
        "{%0,%1,%2,%3}, {%4,%5,%6,%7}, {%8,%9}, {%0,%1,%2,%3};" \
        : "+f"((c)[0]), "+f"((c)[1]), "+f"((c)[2]), "+f"((c)[3]) \
        : "r"((a)[0]), "r"((a)[1]), "r"((a)[2]), "r"((a)[3]), "r"((b)[0]), "r"((b)[1]))

__device__ __forceinline__ float gelu_exact(float v) {
    return 0.5f * v * (1.0f + erff(v * 0.70710678118654752f));
}
__device__ __forceinline__ void split_f16(float v, __half& h, __half& l) {
    h = __float2half(v);
    l = __float2half(v - __half2float(h));
}

// ============================================================
// GEMM: C[M,N] = A[M,K] @ B^T[N,K] (+ bias)
// TT=1: A = Ah + Al (fp16 pair, exact to 2^-22); 2 MMAs per fragment.
// TT=0: A = Ah single fp16; 1 MMA per fragment.
// B single fp16 in both cases.
// EPI 1: bias + gelu -> single fp16 out (Ch).
// EPI 2: plain fp32 partial store, NO bias; z-th split writes Cf + z*M*N.
// 3-stage cp.async ring, 2 CTAs/SM, one barrier per k-step.
// ============================================================
#define BMT 128
#define BNT 128
#define BKS 32
#define NSTAGE 3
#define MATB 10240u                // 128*40*2 bytes (rows padded to 40 fp16)
#define BUFB (3 * MATB)            // 30720 (TT=0 leaves the Al slot unused)
#define GEMM_SMEM (NSTAGE * BUFB)  // 92160

template <int EPI, int TT>
__global__ __launch_bounds__(256, 2)
void mma_gemm(const __half* __restrict__ Ah_, const __half* __restrict__ Al_,
              const __half* __restrict__ Bh_,
              const float* __restrict__ bias,
              float* __restrict__ Cf, __half* __restrict__ Ch,
              int M, int N, int K)
{
    extern __shared__ char dsm[];
    const uint32_t sb0 = smem_u32(dsm);
    const int tid = threadIdx.x;
    const int wid = tid >> 5, lane = tid & 31;
    const int wm = wid >> 1, wn = wid & 1;          // warp tile: 32 x 64
    const int row0 = blockIdx.y * BMT, col0 = blockIdx.x * BNT;
    const int Kloc = K / gridDim.z;
    const int koff = blockIdx.z * Kloc;
    const int NS = Kloc / BKS;

    const __half* Ahp = Ah_ + koff;
    const __half* Alp = TT ? Al_ + koff : nullptr;
    const __half* Bhp = Bh_ + koff;

    float acc[2][8][4];
    #pragma unroll
    for (int i = 0; i < 2; i++)
        #pragma unroll
        for (int j = 0; j < 8; j++)
            #pragma unroll
            for (int k = 0; k < 4; k++) acc[i][j][k] = 0.f;

    // ldmatrix per-lane base offsets (bytes, within one stage buffer)
    const uint32_t aoff = (uint32_t)((wm * 32 + (lane & 15)) * 80 + (lane >> 4) * 16);
    const uint32_t boff = (uint32_t)((wn * 64 + ((lane >> 4) << 3) + (lane & 7)) * 80
                                     + ((lane >> 3) & 1) * 16);
    const uint32_t BOFFM = (TT ? 2u : 1u) * MATB;    // B matrix slot

    auto load_step = [&](int s) {
        const uint32_t sb = sb0 + (uint32_t)(s % NSTAGE) * BUFB;
        const int k0 = s * BKS;
        #pragma unroll
        for (int i = 0; i < (TT ? 6 : 4); i++) {
            int u = i * 256 + tid;
            int mat = u >> 9;          // TT=1: 0 Ah, 1 Al, 2 B ; TT=0: 0 Ah, 1 B
            int v = u & 511;
            int r = v >> 2, c = v & 3;
            const __half* src;
            if (TT) {
                if (mat == 0)      src = Ahp + (size_t)(row0 + r) * K + k0 + c * 8;
                else if (mat == 1) src = Alp + (size_t)(row0 + r) * K + k0 + c * 8;
                else               src = Bhp + (size_t)(col0 + r) * K + k0 + c * 8;
            } else {
                if (mat == 0)      src = Ahp + (size_t)(row0 + r) * K + k0 + c * 8;
                else               src = Bhp + (size_t)(col0 + r) * K + k0 + c * 8;
            }
            CP_ASYNC16(sb + (uint32_t)mat * MATB + (uint32_t)(r * 80 + c * 16), src);
        }
        CP_COMMIT();
    };

    load_step(0);
    if (NS > 1) load_step(1);

    for (int s = 0; s < NS; s++) {
        if (s < NS - 1) { CP_WAIT1(); } else { CP_WAIT0(); }
        __syncthreads();
        if (s + 2 < NS) load_step(s + 2);

        const uint32_t sb = sb0 + (uint32_t)(s % NSTAGE) * BUFB;
        #pragma unroll
        for (int kh = 0; kh < 2; kh++) {     // two k16 halves of the k32 step
            uint32_t ah[2][4], al[2][4], b[8][2];
            #pragma unroll
            for (int mf = 0; mf < 2; mf++) {
                LDSM4(ah[mf], sb + aoff + (uint32_t)(mf * 1280 + kh * 32));
                if (TT) LDSM4(al[mf], sb + MATB + aoff + (uint32_t)(mf * 1280 + kh * 32));
            }
            #pragma unroll
            for (int p = 0; p < 4; p++) {
                uint32_t t[4];
                LDSM4(t, sb + BOFFM + boff + (uint32_t)(p * 1280 + kh * 32));
                b[2 * p][0] = t[0]; b[2 * p][1] = t[1];
                b[2 * p + 1][0] = t[2]; b[2 * p + 1][1] = t[3];
            }
            #pragma unroll
            for (int mf = 0; mf < 2; mf++)
                #pragma unroll
                for (int nf = 0; nf < 8; nf++) {
                    MMA_F16(acc[mf][nf], ah[mf], b[nf]);
                    if (TT) MMA_F16(acc[mf][nf], al[mf], b[nf]);
                }
        }
    }

    // ---- epilogue: regs -> per-warp smem stage (16x65 fp32) -> coalesced stores ----
    __syncthreads();
    float* stg = (float*)dsm + wid * (16 * 65);
    const int gcol0 = col0 + wn * 64;
    const float bv0 = (EPI == 2) ? 0.f : bias[gcol0 + lane];
    const float bv1 = (EPI == 2) ? 0.f : bias[gcol0 + 32 + lane];
    const int r1 = lane >> 2, c0 = (lane & 3) * 2;
    float* Cfz = (EPI == 2) ? Cf + (size_t)blockIdx.z * M * N : Cf;

    #pragma unroll
    for (int mf = 0; mf < 2; mf++) {
        #pragma unroll
        for (int nf = 0; nf < 8; nf++) {
            stg[r1 * 65 + nf * 8 + c0]           = acc[mf][nf][0];
            stg[r1 * 65 + nf * 8 + c0 + 1]       = acc[mf][nf][1];
            stg[(r1 + 8) * 65 + nf * 8 + c0]     = acc[mf][nf][2];
            stg[(r1 + 8) * 65 + nf * 8 + c0 + 1] = acc[mf][nf][3];
        }
        __syncwarp();
        const int grow = row0 + wm * 32 + mf * 16;
        #pragma unroll
        for (int r = 0; r < 16; r++) {
            float v0 = stg[r * 65 + lane] + bv0;
            float v1 = stg[r * 65 + 32 + lane] + bv1;
            if (EPI == 1) {
                v0 = gelu_exact(v0);
                v1 = gelu_exact(v1);
                size_t base = (size_t)(grow + r) * N + gcol0;
                Ch[base + lane] = __float2half(v0);
                Ch[base + 32 + lane] = __float2half(v1);
            } else {
                size_t base = (size_t)(grow + r) * N + gcol0;
                Cfz[base + lane] = v0;
                Cfz[base + 32 + lane] = v1;
            }
        }
        __syncwarp();
    }
}

// ============================================================
// weight transpose + fp16 convert: W[K][N] -> T[N][K]
// ============================================================
__global__ void wconv_kernel(const float* __restrict__ W, __half* __restrict__ Th,
                             int K, int N) {
    __shared__ float t[32][33];
    int k0 = blockIdx.x * 32, n0 = blockIdx.y * 32;
    int tx = threadIdx.x, ty = threadIdx.y;  // (32, 8)
    #pragma unroll
    for (int i = 0; i < 4; i++)
        t[ty + i * 8][tx] = W[(size_t)(k0 + ty + i * 8) * N + n0 + tx];
    __syncthreads();
    #pragma unroll
    for (int i = 0; i < 4; i++) {
        int n = n0 + ty + i * 8, k = k0 + tx;
        Th[(size_t)n * K + k] = __float2half(t[tx][ty + i * 8]);
    }
}

// ---------------- positional-encoding table (once per launch) ----------------
__global__ void pe_kernel(float* __restrict__ pe) {
    int idx = blockIdx.x * 256 + threadIdx.x;
    if (idx >= S_ * D_) return;
    int d = idx % D_;
    int s = idx / D_;
    int i2 = d & ~1;
    float div = expf((float)i2 * (-9.210340371976184f / (float)D_));
    float ang = (float)s * div;
    pe[idx] = (d & 1) ? cosf(ang) : sinf(ang);
}

// ---------------- elementwise: x = template + pe table ----------------
__global__ void add_pe_kernel(const float* __restrict__ t, const float* __restrict__ pe,
                              float* __restrict__ x) {
    int idx = blockIdx.x * 256 + threadIdx.x;
    if (idx >= M_ * D_) return;
    x[idx] = t[idx] + pe[idx % (S_ * D_)];
}

// ---------------- pooled = mean over P, emitted as fp16 hi/lo ----------------
__global__ void pool_kernel(const float* __restrict__ ps,
                            __half* __restrict__ ph, __half* __restrict__ pl) {
    int idx = blockIdx.x * 256 + threadIdx.x;
    if (idx >= M_ * D_) return;
    int bs = idx / D_;
    int c  = idx % D_;
    const float* base = ps + (size_t)bs * (P_ * D_) + c;
    float s = 0.f;
    #pragma unroll
    for (int p = 0; p < P_; p++) s += base[p * D_];
    float m = s * (1.0f / P_);
    __half h, l;
    split_f16(m, h, l);
    ph[idx] = h; pl[idx] = l;
}

// ---------------- block-reduce helper ----------------
__device__ __forceinline__ float warp_sum(float v) {
    #pragma unroll
    for (int o = 16; o; o >>= 1) v += __shfl_down_sync(0xffffffffu, v, o);
    return v;
}

// ---------------- LayerNorm (row length 768) ----------------
// t = x (+ res) (+ res2) (+ colbias);  out = LN(t)*g + b;  optional single-fp16 out
template <int F16OUT>
__global__ void ln_kernel(const float* __restrict__ x, const float* __restrict__ res,
                          const float* __restrict__ res2,
                          const float* __restrict__ colbias,
                          const float* __restrict__ g, const float* __restrict__ b,
                          float* __restrict__ out,
                          __half* __restrict__ oh) {
    const int row = blockIdx.x;
    const int tid = threadIdx.x;  // 256
    const float* xr = x + (size_t)row * D_;
    const float* rr = res ? res + (size_t)row * D_ : nullptr;
    const float* r2 = res2 ? res2 + (size_t)row * D_ : nullptr;

    float v[3];
    float s = 0.f, s2 = 0.f;
    #pragma unroll
    for (int i = 0; i < 3; i++) {
        int c = tid + i * 256;
        float t = xr[c];
        if (rr) t += rr[c];
        if (r2) t += r2[c];
        if (colbias) t += colbias[c];
        v[i] = t; s += t; s2 += t * t;
    }

    __shared__ float red[2][8];
    __shared__ float stat[2];
    int lane = tid & 31, wid = tid >> 5;
    s = warp_sum(s); s2 = warp_sum(s2);
    if (lane == 0) { red[0][wid] = s; red[1][wid] = s2; }
    __syncthreads();
    if (wid == 0) {
        float a = (lane < 8) ? red[0][lane] : 0.f;
        float c = (lane < 8) ? red[1][lane] : 0.f;
        a = warp_sum(a); c = warp_sum(c);
        if (lane == 0) {
            float mean = a * (1.0f / D_);
            float var = c * (1.0f / D_) - mean * mean;
            stat[0] = mean;
            stat[1] = rsqrtf(var + EPS_);
        }
    }
    __syncthreads();
    float mean = stat[0], inv = stat[1];
    float* orow = out + (size_t)row * D_;
    #pragma unroll
    for (int i = 0; i < 3; i++) {
        int c = tid + i * 256;
        float o = (v[i] - mean) * inv * g[c] + b[c];
        orow[c] = o;
        if (F16OUT) {
            oh[(size_t)row * D_ + c] = __float2half(o);
        }
    }
}

// ---------------- param_bias[b,h] = (pe_bh @ pe_bh^T) * inv_sqrt_hd ----------------
// Symmetric: compute tiles jj>=ii only, mirror-write.
__global__ __launch_bounds__(256)
void pbias_kernel(const float* __restrict__ enc, float* __restrict__ pbias) {
    __shared__ float Es[112 * 97];
    const int b = blockIdx.x >> 3;
    const int h = blockIdx.x & 7;
    const int tid = threadIdx.x;
    const float* src = enc + (size_t)(b * S_) * D_ + h * HD_;

    for (int i = tid; i < 112 * 96; i += 256) {
        int s = i / 96, d = i - s * 96;
        Es[s * 97 + d] = (s < S_) ? src[(size_t)s * D_ + d] : 0.f;
    }
    __syncthreads();

    const int tx = tid & 15, ty = tid >> 4;
    float acc[7][7];
    #pragma unroll
    for (int ii = 0; ii < 7; ii++)
        #pragma unroll
        for (int jj = 0; jj < 7; jj++) acc[ii][jj] = 0.f;

    for (int d = 0; d < 96; d++) {
        float a[7], bb[7];
        #pragma unroll
        for (int ii = 0; ii < 7; ii++) a[ii]  = Es[(ty + 16 * ii) * 97 + d];
        #pragma unroll
        for (int jj = 0; jj < 7; jj++) bb[jj] = Es[(tx + 16 * jj) * 97 + d];
        #pragma unroll
        for (int ii = 0; ii < 7; ii++)
            #pragma unroll
            for (int jj = 0; jj < 7; jj++)
                if (jj >= ii) acc[ii][jj] += a[ii] * bb[jj];
    }

    float* dst = pbias + (size_t)blockIdx.x * (S_ * S_);
    #pragma unroll
    for (int ii = 0; ii < 7; ii++) {
        int i = ty + 16 * ii;
        if (i >= S_) continue;
        #pragma unroll
        for (int jj = 0; jj < 7; jj++) {
            if (jj < ii) continue;
            int j = tx + 16 * jj;
            if (j < S_) {
                float v = acc[ii][jj] * INV_SQRT_HD;
                dst[i * S_ + j] = v;
                if (jj > ii) dst[j * S_ + i] = v;
            }
        }
    }
}

// ---------------- fused attention per (b,h) ----------------
// Qs fp32 [112][97], Ss fp16 [112][104]; symmetric scores (tiles jj>=ii + mirror);
// 3 CTAs/SM.
#define ATTN_SMEM (112 * 97 * 4 + 112 * 104 * 2)   // 66752
__global__ __launch_bounds__(256, 3)
void attn_kernel(const float* __restrict__ x, const float* __restrict__ pbias,
                 float* __restrict__ out) {
    extern __shared__ float smem[];
    float* Qs = smem;                              // [112][97] fp32
    __half* Ss = (__half*)(smem + 112 * 97);       // [112][104] fp16

    const int b = blockIdx.x >> 3;
    const int h = blockIdx.x & 7;
    const int tid = threadIdx.x;
    const float* xb = x + (size_t)(b * S_) * D_ + h * HD_;

    for (int i = tid; i < 112 * 96; i += 256) {
        int s = i / 96, d = i - s * 96;
        Qs[s * 97 + d] = (s < S_) ? xb[(size_t)s * D_ + d] : 0.f;
    }
    __syncthreads();

    const int tx = tid & 15, ty = tid >> 4;
    // ---- scores (symmetric): q q^T * scale + pbias ----
    {
        float acc[7][7];
        #pragma unroll
        for (int ii = 0; ii < 7; ii++)
            #pragma unroll
            for (int jj = 0; jj < 7; jj++) acc[ii][jj] = 0.f;

        for (int d = 0; d < 96; d++) {
            float a[7], bb[7];
            #pragma unroll
            for (int ii = 0; ii < 7; ii++) a[ii]  = Qs[(ty + 16 * ii) * 97 + d];
            #pragma unroll
            for (int jj = 0; jj < 7; jj++) bb[jj] = Qs[(tx + 16 * jj) * 97 + d];
            #pragma unroll
            for (int ii = 0; ii < 7; ii++)
                #pragma unroll
                for (int jj = 0; jj < 7; jj++)
                    if (jj >= ii) acc[ii][jj] += a[ii] * bb[jj];
        }
        const float* pb = pbias + (size_t)blockIdx.x * (S_ * S_);
        #pragma unroll
        for (int ii = 0; ii < 7; ii++) {
            int i = ty + 16 * ii;
            if (i >= S_) continue;
            #pragma unroll
            for (int jj = 0; jj < 7; jj++) {
                if (jj < ii) continue;
                int j = tx + 16 * jj;
                if (j < S_) {
                    float v = acc[ii][jj] * INV_SQRT_HD + pb[i * S_ + j];
                    __half hv = __float2half(v);
                    Ss[i * 104 + j] = hv;
                    if (jj > ii) Ss[j * 104 + i] = hv;
                }
            }
        }
    }
    __syncthreads();

    // ---- softmax per row (threads 0..99), fp32 math, fp16 storage ----
    if (tid < S_) {
        __half* row = Ss + tid * 104;
        float m = -1e30f;
        for (int j = 0; j < S_; j++) m = fmaxf(m, __half2float(row[j]));
        float sum = 0.f;
        for (int j = 0; j < S_; j++) {
            float e = expf(__half2float(row[j]) - m);
            row[j] = __float2half(e);
            sum += e;
        }
        float inv = 1.0f / sum;
        for (int j = 0; j < S_; j++)
            row[j] = __float2half(__half2float(row[j]) * inv);
    }
    __syncthreads();

    // ---- out = attn @ q  (100 x 96) ----
    {
        float acc[7][6];
        #pragma unroll
        for (int ii = 0; ii < 7; ii++)
            #pragma unroll
            for (int jj = 0; jj < 6; jj++) acc[ii][jj] = 0.f;

        for (int j = 0; j < S_; j++) {
            float a[7], bb[6];
            #pragma unroll
            for (int ii = 0; ii < 7; ii++)
                a[ii] = __half2float(Ss[(ty + 16 * ii) * 104 + j]);
            #pragma unroll
            for (int jj = 0; jj < 6; jj++) bb[jj] = Qs[j * 97 + tx + 16 * jj];
            #pragma unroll
            for (int ii = 0; ii < 7; ii++)
                #pragma unroll
                for (int jj = 0; jj < 6; jj++) acc[ii][jj] += a[ii] * bb[jj];
        }
        float* dst = out + (size_t)(b * S_) * D_ + h * HD_;
        #pragma unroll
        for (int ii = 0; ii < 7; ii++) {
            int i = ty + 16 * ii;
            if (i >= S_) continue;
            #pragma unroll
            for (int jj = 0; jj < 6; jj++) {
                int dd = tx + 16 * jj;
                dst[(size_t)i * D_ + dd] = acc[ii][jj];
            }
        }
    }
}

// ---------------- final classifier ----------------
__global__ void fc_kernel(const float* __restrict__ x, const float* __restrict__ Wfc,
                          const float* __restrict__ bfc, float* __restrict__ out) {
    const int b = blockIdx.x;
    const int tid = threadIdx.x;
    const float* xr = x + (size_t)b * (S_ * D_);
    float a0 = 0.f, a1 = 0.f;
    for (int i = tid; i < S_ * D_; i += 256) {
        float v = xr[i];
        a0 += v * Wfc[2 * i];
        a1 += v * Wfc[2 * i + 1];
    }
    __shared__ float red[2][8];
    int lane = tid & 31, wid = tid >> 5;
    a0 = warp_sum(a0); a1 = warp_sum(a1);
    if (lane == 0) { red[0][wid] = a0; red[1][wid] = a1; }
    __syncthreads();
    if (wid == 0) {
        float r0 = (lane < 8) ? red[0][lane] : 0.f;
        float r1 = (lane < 8) ? red[1][lane] : 0.f;
        r0 = warp_sum(r0); r1 = warp_sum(r1);
        if (lane == 0) {
            out[2 * b + 0] = r0 + bfc[0];
            out[2 * b + 1] = r1 + bfc[1];
        }
    }
}

// ---------------- launch ----------------
extern "C" void kernel_launch(void* const* d_in, const int* in_sizes, int n_in,
                              void* d_out, int out_size) {
    const float* tseq = (const float*)d_in[0];
    const float* pseq = (const float*)d_in[1];
    const float* Wc  = (const float*)d_in[2];
    const float* bc  = (const float*)d_in[3];
    const float* gp  = (const float*)d_in[4];
    const float* bp  = (const float*)d_in[5];
    const float* W1  = (const float*)d_in[6];
    const float* b1  = (const float*)d_in[7];
    const float* W2  = (const float*)d_in[8];
    const float* b2  = (const float*)d_in[9];
    const float* g1  = (const float*)d_in[10];
    const float* bn1 = (const float*)d_in[11];
    const float* g2  = (const float*)d_in[12];
    const float* bn2 = (const float*)d_in[13];
    const float* Wfc = (const float*)d_in[14];
    const float* bfc = (const float*)d_in[15];
    float* out = (float*)d_out;

    float *x, *enc, *pbias, *part, *pe;
    __half *xhi, *phi, *plo, *ffhi;
    __half *w1h, *w2h, *wch;
    cudaGetSymbolAddress((void**)&x, g_x);
    cudaGetSymbolAddress((void**)&enc, g_enc);
    cudaGetSymbolAddress((void**)&pbias, g_pbias);
    cudaGetSymbolAddress((void**)&part, g_part);
    cudaGetSymbolAddress((void**)&pe, g_pe);
    cudaGetSymbolAddress((void**)&xhi, g_xhi);
    cudaGetSymbolAddress((void**)&phi, g_phi);
    cudaGetSymbolAddress((void**)&plo, g_plo);
    cudaGetSymbolAddress((void**)&ffhi, g_ffhi);
    cudaGetSymbolAddress((void**)&w1h, g_w1h);
    cudaGetSymbolAddress((void**)&w2h, g_w2h);
    cudaGetSymbolAddress((void**)&wch, g_wch);
    float* part0 = part;
    float* part1 = part + (size_t)M_ * D_;

    cudaFuncSetAttribute(attn_kernel, cudaFuncAttributeMaxDynamicSharedMemorySize, ATTN_SMEM);
    cudaFuncSetAttribute((mma_gemm<1, 0>), cudaFuncAttributeMaxDynamicSharedMemorySize, GEMM_SMEM);
    cudaFuncSetAttribute((mma_gemm<2, 1>), cudaFuncAttributeMaxDynamicSharedMemorySize, GEMM_SMEM);
    cudaFuncSetAttribute((mma_gemm<2, 0>), cudaFuncAttributeMaxDynamicSharedMemorySize, GEMM_SMEM);

    // weight transpose + fp16 convert (tiny, one-time per launch)
    wconv_kernel<<<dim3(D_ / 32, FF_ / 32), dim3(32, 8)>>>(W1, w1h, D_, FF_);
    wconv_kernel<<<dim3(FF_ / 32, D_ / 32), dim3(32, 8)>>>(W2, w2h, FF_, D_);
    wconv_kernel<<<dim3(D_ / 32, D_ / 32),  dim3(32, 8)>>>(Wc, wch, D_, D_);

    const int total = M_ * D_;
    pe_kernel<<<(S_ * D_ + 255) / 256, 256>>>(pe);
    add_pe_kernel<<<(total + 255) / 256, 256>>>(tseq, pe, x);
    pool_kernel<<<(total + 255) / 256, 256>>>(pseq, phi, plo);

    // param encoder: enc = LN(pooled @ Wc + bc)  (split-K=2, exact 2-term A)
    mma_gemm<2, 1><<<dim3(D_ / BNT, M_ / BMT, 2), 256, GEMM_SMEM>>>(
        phi, plo, wch, nullptr, part0, nullptr, M_, D_, D_);
    ln_kernel<0><<<M_, 256>>>(part0, part1, nullptr, bc, gp, bp, enc, nullptr);

    // layer-invariant attention bias
    pbias_kernel<<<B_ * H_, 256>>>(enc, pbias);

    for (int l = 0; l < NLAYERS; l++) {
        attn_kernel<<<B_ * H_, 256, ATTN_SMEM>>>(x, pbias, part0);
        ln_kernel<1><<<M_, 256>>>(x, part0, nullptr, nullptr, g1, bn1, x, xhi);
        // FFN1: single-fp16 A (LN output), gelu -> single fp16 ff
        mma_gemm<1, 0><<<dim3(FF_ / BNT, M_ / BMT), 256, GEMM_SMEM>>>(
            xhi, nullptr, w1h, b1, nullptr, ffhi, M_, FF_, D_);
        // FFN2: single-fp16 A (gelu output), split-K=2 -> fp32 partials, b2 folded into LN
        mma_gemm<2, 0><<<dim3(D_ / BNT, M_ / BMT, 2), 256, GEMM_SMEM>>>(
            ffhi, nullptr, w2h, nullptr, part0, nullptr, M_, D_, FF_);
        ln_kernel<0><<<M_, 256>>>(x, part0, part1, b2, g2, bn2, x, nullptr);
    }

    fc_kernel<<<B_, 256>>>(x, Wfc, bfc, out);
}

// round 11
// speedup vs baseline: 2.4404x; 1.1396x over previous
#include <cuda_runtime.h>
#include <cuda_fp16.h>
#include <math.h>
#include <stdint.h>

// ---------------- problem constants ----------------
#define B_   64
#define S_   100
#define D_   768
#define H_   8
#define HD_  96
#define P_   8
#define FF_  3072
#define M_   (B_ * S_)            // 6400 rows
#define NLAYERS 4
#define EPS_ 1e-5f
#define INV_SQRT_HD 0.10206207261596575f   // 1/sqrt(96)

// ---------------- device scratch ----------------
__device__ float g_x[M_ * D_];
__device__ float g_enc[M_ * D_];
__device__ float g_pbias[B_ * H_ * S_ * S_];
__device__ float g_part[2][M_ * D_];   // split-K fp32 partials
__device__ float g_pe[S_ * D_];

__device__ __half g_xq[M_ * D_];     // fp16 of attn input (layer input)
__device__ __half g_xhi[M_ * D_];    // fp16 of LN1 output (FFN1 input)
__device__ __half g_phi[M_ * D_];
__device__ __half g_plo[M_ * D_];
__device__ __half g_ffhi[(size_t)M_ * FF_];
__device__ __half g_w1h[(size_t)FF_ * D_];   // [N=3072][K=768] fp16
__device__ __half g_w2h[(size_t)D_ * FF_];   // [N=768][K=3072] fp16
__device__ __half g_wch[(size_t)D_ * D_];    // [N=768][K=768]  fp16

// ============================================================
// PTX helpers (mma.sync / ldmatrix / cp.async — all baseline sm_80+)
// ============================================================
__device__ __forceinline__ uint32_t smem_u32(const void* p) {
    uint32_t a;
    asm("{ .reg .u64 t; cvta.to.shared.u64 t, %1; cvt.u32.u64 %0, t; }" : "=r"(a) : "l"(p));
    return a;
}

#define CP_ASYNC16(dst, src) \
    asm volatile("cp.async.cg.shared.global [%0], [%1], 16;\n" :: "r"(dst), "l"(src) : "memory")
#define CP_COMMIT() asm volatile("cp.async.commit_group;\n" ::: "memory")
#define CP_WAIT0()  asm volatile("cp.async.wait_group 0;\n" ::: "memory")
#define CP_WAIT1()  asm volatile("cp.async.wait_group 1;\n" ::: "memory")

#define LDSM4(r, addr) \
    asm volatile("ldmatrix.sync.aligned.m8n8.x4.shared.b16 {%0,%1,%2,%3}, [%4];" \
        : "=r"((r)[0]), "=r"((r)[1]), "=r"((r)[2]), "=r"((r)[3]) : "r"(addr))

#define LDSM4T(r, addr) \
    asm volatile("ldmatrix.sync.aligned.m8n8.x4.trans.shared.b16 {%0,%1,%2,%3}, [%4];" \
        : "=r"((r)[0]), "=r"((r)[1]), "=r"((r)[2]), "=r"((r)[3]) : "r"(addr))

#define MMA_F16(c, a, b) \
    asm volatile("mma.sync.aligned.m16n8k16.row.col.f32.f16.f16.f32 " \
        "{%0,%1,%2,%3}, {%4,%5,%6,%7}, {%8,%9}, {%0,%1,%2,%3};" \
        : "+f"((c)[0]), "+f"((c)[1]), "+f"((c)[2]), "+f"((c)[3]) \
        : "r"((a)[0]), "r"((a)[1]), "r"((a)[2]), "r"((a)[3]), "r"((b)[0]), "r"((b)[1]))

__device__ __forceinline__ float gelu_exact(float v) {
    return 0.5f * v * (1.0f + erff(v * 0.70710678118654752f));
}
__device__ __forceinline__ void split_f16(float v, __half& h, __half& l) {
    h = __float2half(v);
    l = __float2half(v - __half2float(h));
}

// ============================================================
// GEMM: C[M,N] = A[M,K] @ B^T[N,K] (+ bias)   (unchanged from R9/R10)
// ============================================================
#define BMT 128
#define BNT 128
#define BKS 32
#define NSTAGE 3
#define MATB 10240u
#define BUFB (3 * MATB)
#define GEMM_SMEM (NSTAGE * BUFB)  // 92160

template <int EPI, int TT>
__global__ __launch_bounds__(256, 2)
void mma_gemm(const __half* __restrict__ Ah_, const __half* __restrict__ Al_,
              const __half* __restrict__ Bh_,
              const float* __restrict__ bias,
              float* __restrict__ Cf, __half* __restrict__ Ch,
              int M, int N, int K)
{
    extern __shared__ char dsm[];
    const uint32_t sb0 = smem_u32(dsm);
    const int tid = threadIdx.x;
    const int wid = tid >> 5, lane = tid & 31;
    const int wm = wid >> 1, wn = wid & 1;
    const int row0 = blockIdx.y * BMT, col0 = blockIdx.x * BNT;
    const int Kloc = K / gridDim.z;
    const int koff = blockIdx.z * Kloc;
    const int NS = Kloc / BKS;

    const __half* Ahp = Ah_ + koff;
    const __half* Alp = TT ? Al_ + koff : nullptr;
    const __half* Bhp = Bh_ + koff;

    float acc[2][8][4];
    #pragma unroll
    for (int i = 0; i < 2; i++)
        #pragma unroll
        for (int j = 0; j < 8; j++)
            #pragma unroll
            for (int k = 0; k < 4; k++) acc[i][j][k] = 0.f;

    const uint32_t aoff = (uint32_t)((wm * 32 + (lane & 15)) * 80 + (lane >> 4) * 16);
    const uint32_t boff = (uint32_t)((wn * 64 + ((lane >> 4) << 3) + (lane & 7)) * 80
                                     + ((lane >> 3) & 1) * 16);
    const uint32_t BOFFM = (TT ? 2u : 1u) * MATB;

    auto load_step = [&](int s) {
        const uint32_t sb = sb0 + (uint32_t)(s % NSTAGE) * BUFB;
        const int k0 = s * BKS;
        #pragma unroll
        for (int i = 0; i < (TT ? 6 : 4); i++) {
            int u = i * 256 + tid;
            int mat = u >> 9;
            int v = u & 511;
            int r = v >> 2, c = v & 3;
            const __half* src;
            if (TT) {
                if (mat == 0)      src = Ahp + (size_t)(row0 + r) * K + k0 + c * 8;
                else if (mat == 1) src = Alp + (size_t)(row0 + r) * K + k0 + c * 8;
                else               src = Bhp + (size_t)(col0 + r) * K + k0 + c * 8;
            } else {
                if (mat == 0)      src = Ahp + (size_t)(row0 + r) * K + k0 + c * 8;
                else               src = Bhp + (size_t)(col0 + r) * K + k0 + c * 8;
            }
            CP_ASYNC16(sb + (uint32_t)mat * MATB + (uint32_t)(r * 80 + c * 16), src);
        }
        CP_COMMIT();
    };

    load_step(0);
    if (NS > 1) load_step(1);

    for (int s = 0; s < NS; s++) {
        if (s < NS - 1) { CP_WAIT1(); } else { CP_WAIT0(); }
        __syncthreads();
        if (s + 2 < NS) load_step(s + 2);

        const uint32_t sb = sb0 + (uint32_t)(s % NSTAGE) * BUFB;
        #pragma unroll
        for (int kh = 0; kh < 2; kh++) {
            uint32_t ah[2][4], al[2][4], b[8][2];
            #pragma unroll
            for (int mf = 0; mf < 2; mf++) {
                LDSM4(ah[mf], sb + aoff + (uint32_t)(mf * 1280 + kh * 32));
                if (TT) LDSM4(al[mf], sb + MATB + aoff + (uint32_t)(mf * 1280 + kh * 32));
            }
            #pragma unroll
            for (int p = 0; p < 4; p++) {
                uint32_t t[4];
                LDSM4(t, sb + BOFFM + boff + (uint32_t)(p * 1280 + kh * 32));
                b[2 * p][0] = t[0]; b[2 * p][1] = t[1];
                b[2 * p + 1][0] = t[2]; b[2 * p + 1][1] = t[3];
            }
            #pragma unroll
            for (int mf = 0; mf < 2; mf++)
                #pragma unroll
                for (int nf = 0; nf < 8; nf++) {
                    MMA_F16(acc[mf][nf], ah[mf], b[nf]);
                    if (TT) MMA_F16(acc[mf][nf], al[mf], b[nf]);
                }
        }
    }

    __syncthreads();
    float* stg = (float*)dsm + wid * (16 * 65);
    const int gcol0 = col0 + wn * 64;
    const float bv0 = (EPI == 2) ? 0.f : bias[gcol0 + lane];
    const float bv1 = (EPI == 2) ? 0.f : bias[gcol0 + 32 + lane];
    const int r1 = lane >> 2, c0 = (lane & 3) * 2;
    float* Cfz = (EPI == 2) ? Cf + (size_t)blockIdx.z * M * N : Cf;

    #pragma unroll
    for (int mf = 0; mf < 2; mf++) {
        #pragma unroll
        for (int nf = 0; nf < 8; nf++) {
            stg[r1 * 65 + nf * 8 + c0]           = acc[mf][nf][0];
            stg[r1 * 65 + nf * 8 + c0 + 1]       = acc[mf][nf][1];
            stg[(r1 + 8) * 65 + nf * 8 + c0]     = acc[mf][nf][2];
            stg[(r1 + 8) * 65 + nf * 8 + c0 + 1] = acc[mf][nf][3];
        }
        __syncwarp();
        const int grow = row0 + wm * 32 + mf * 16;
        #pragma unroll
        for (int r = 0; r < 16; r++) {
            float v0 = stg[r * 65 + lane] + bv0;
            float v1 = stg[r * 65 + 32 + lane] + bv1;
            if (EPI == 1) {
                v0 = gelu_exact(v0);
                v1 = gelu_exact(v1);
                size_t base = (size_t)(grow + r) * N + gcol0;
                Ch[base + lane] = __float2half(v0);
                Ch[base + 32 + lane] = __float2half(v1);
            } else {
                size_t base = (size_t)(grow + r) * N + gcol0;
                Cfz[base + lane] = v0;
                Cfz[base + 32 + lane] = v1;
            }
        }
        __syncwarp();
    }
}

// ============================================================
// weight transpose + fp16 convert
// ============================================================
__global__ void wconv_kernel(const float* __restrict__ W, __half* __restrict__ Th,
                             int K, int N) {
    __shared__ float t[32][33];
    int k0 = blockIdx.x * 32, n0 = blockIdx.y * 32;
    int tx = threadIdx.x, ty = threadIdx.y;
    #pragma unroll
    for (int i = 0; i < 4; i++)
        t[ty + i * 8][tx] = W[(size_t)(k0 + ty + i * 8) * N + n0 + tx];
    __syncthreads();
    #pragma unroll
    for (int i = 0; i < 4; i++) {
        int n = n0 + ty + i * 8, k = k0 + tx;
        Th[(size_t)n * K + k] = __float2half(t[tx][ty + i * 8]);
    }
}

// ---------------- positional-encoding table (once per launch) ----------------
__global__ void pe_kernel(float* __restrict__ pe) {
    int idx = blockIdx.x * 256 + threadIdx.x;
    if (idx >= S_ * D_) return;
    int d = idx % D_;
    int s = idx / D_;
    int i2 = d & ~1;
    float div = expf((float)i2 * (-9.210340371976184f / (float)D_));
    float ang = (float)s * div;
    pe[idx] = (d & 1) ? cosf(ang) : sinf(ang);
}

// ---------------- x = template + pe; also emit fp16 copy for attention ----------------
__global__ void add_pe_kernel(const float* __restrict__ t, const float* __restrict__ pe,
                              float* __restrict__ x, __half* __restrict__ xq) {
    int idx = blockIdx.x * 256 + threadIdx.x;
    if (idx >= M_ * D_) return;
    float v = t[idx] + pe[idx % (S_ * D_)];
    x[idx] = v;
    xq[idx] = __float2half(v);
}

// ---------------- pooled = mean over P, emitted as fp16 hi/lo ----------------
__global__ void pool_kernel(const float* __restrict__ ps,
                            __half* __restrict__ ph, __half* __restrict__ pl) {
    int idx = blockIdx.x * 256 + threadIdx.x;
    if (idx >= M_ * D_) return;
    int bs = idx / D_;
    int c  = idx % D_;
    const float* base = ps + (size_t)bs * (P_ * D_) + c;
    float s = 0.f;
    #pragma unroll
    for (int p = 0; p < P_; p++) s += base[p * D_];
    float m = s * (1.0f / P_);
    __half h, l;
    split_f16(m, h, l);
    ph[idx] = h; pl[idx] = l;
}

// ---------------- block-reduce helper ----------------
__device__ __forceinline__ float warp_sum(float v) {
    #pragma unroll
    for (int o = 16; o; o >>= 1) v += __shfl_down_sync(0xffffffffu, v, o);
    return v;
}

// ---------------- LayerNorm (row length 768) ----------------
template <int F16OUT>
__global__ void ln_kernel(const float* __restrict__ x, const float* __restrict__ res,
                          const float* __restrict__ res2,
                          const float* __restrict__ colbias,
                          const float* __restrict__ g, const float* __restrict__ b,
                          float* __restrict__ out,
                          __half* __restrict__ oh) {
    const int row = blockIdx.x;
    const int tid = threadIdx.x;
    const float* xr = x + (size_t)row * D_;
    const float* rr = res ? res + (size_t)row * D_ : nullptr;
    const float* r2 = res2 ? res2 + (size_t)row * D_ : nullptr;

    float v[3];
    float s = 0.f, s2 = 0.f;
    #pragma unroll
    for (int i = 0; i < 3; i++) {
        int c = tid + i * 256;
        float t = xr[c];
        if (rr) t += rr[c];
        if (r2) t += r2[c];
        if (colbias) t += colbias[c];
        v[i] = t; s += t; s2 += t * t;
    }

    __shared__ float red[2][8];
    __shared__ float stat[2];
    int lane = tid & 31, wid = tid >> 5;
    s = warp_sum(s); s2 = warp_sum(s2);
    if (lane == 0) { red[0][wid] = s; red[1][wid] = s2; }
    __syncthreads();
    if (wid == 0) {
        float a = (lane < 8) ? red[0][lane] : 0.f;
        float c = (lane < 8) ? red[1][lane] : 0.f;
        a = warp_sum(a); c = warp_sum(c);
        if (lane == 0) {
            float mean = a * (1.0f / D_);
            float var = c * (1.0f / D_) - mean * mean;
            stat[0] = mean;
            stat[1] = rsqrtf(var + EPS_);
        }
    }
    __syncthreads();
    float mean = stat[0], inv = stat[1];
    float* orow = out + (size_t)row * D_;
    #pragma unroll
    for (int i = 0; i < 3; i++) {
        int c = tid + i * 256;
        float o = (v[i] - mean) * inv * g[c] + b[c];
        orow[c] = o;
        if (F16OUT) {
            oh[(size_t)row * D_ + c] = __float2half(o);
        }
    }
}

// ---------------- param_bias (symmetric, runs once) ----------------
__global__ __launch_bounds__(256)
void pbias_kernel(const float* __restrict__ enc, float* __restrict__ pbias) {
    __shared__ float Es[112 * 97];
    const int b = blockIdx.x >> 3;
    const int h = blockIdx.x & 7;
    const int tid = threadIdx.x;
    const float* src = enc + (size_t)(b * S_) * D_ + h * HD_;

    for (int i = tid; i < 112 * 96; i += 256) {
        int s = i / 96, d = i - s * 96;
        Es[s * 97 + d] = (s < S_) ? src[(size_t)s * D_ + d] : 0.f;
    }
    __syncthreads();

    const int tx = tid & 15, ty = tid >> 4;
    float acc[7][7];
    #pragma unroll
    for (int ii = 0; ii < 7; ii++)
        #pragma unroll
        for (int jj = 0; jj < 7; jj++) acc[ii][jj] = 0.f;

    for (int d = 0; d < 96; d++) {
        float a[7], bb[7];
        #pragma unroll
        for (int ii = 0; ii < 7; ii++) a[ii]  = Es[(ty + 16 * ii) * 97 + d];
        #pragma unroll
        for (int jj = 0; jj < 7; jj++) bb[jj] = Es[(tx + 16 * jj) * 97 + d];
        #pragma unroll
        for (int ii = 0; ii < 7; ii++)
            #pragma unroll
            for (int jj = 0; jj < 7; jj++)
                if (jj >= ii) acc[ii][jj] += a[ii] * bb[jj];
    }

    float* dst = pbias + (size_t)blockIdx.x * (S_ * S_);
    #pragma unroll
    for (int ii = 0; ii < 7; ii++) {
        int i = ty + 16 * ii;
        if (i >= S_) continue;
        #pragma unroll
        for (int jj = 0; jj < 7; jj++) {
            if (jj < ii) continue;
            int j = tx + 16 * jj;
            if (j < S_) {
                float v = acc[ii][jj] * INV_SQRT_HD;
                dst[i * S_ + j] = v;
                if (jj > ii) dst[j * S_ + i] = v;
            }
        }
    }
}

// ---------------- fused attention on tensor cores ----------------
// Qh fp16 [112][104], Ss fp16 [112][120]. Warps 0-6 each own one m16 row tile.
// matmul1: scores = Q Q^T (non-trans ldmatrix A and B from Qh) * scale + pbias
// matmul2: out = P Q (A from Ss, B via ldmatrix.trans on Qh rows=j)
#define QSW 104
#define SSW 120
#define ATTN_SMEM (112 * QSW * 2 + 112 * SSW * 2)   // 50176
__global__ __launch_bounds__(256, 3)
void attn_kernel(const __half* __restrict__ xq, const float* __restrict__ pbias,
                 float* __restrict__ out) {
    extern __shared__ char asm_[];
    __half* Qh = (__half*)asm_;
    __half* Ss = Qh + 112 * QSW;
    const uint32_t qb = smem_u32(Qh);
    const uint32_t sbS = smem_u32(Ss);

    const int b = blockIdx.x >> 3;
    const int h = blockIdx.x & 7;
    const int tid = threadIdx.x;
    const int wid = tid >> 5, lane = tid & 31;

    // load Q (112 x 96 fp16; rows >= 100 zero) via 16B chunks
    const __half* src = xq + (size_t)(b * S_) * D_ + h * HD_;
    for (int i = tid; i < 112 * 12; i += 256) {
        int s = i / 12, c = i % 12;
        uint4 v = make_uint4(0u, 0u, 0u, 0u);
        if (s < S_) v = *(const uint4*)(src + (size_t)s * D_ + c * 8);
        *(uint4*)(Qh + s * QSW + c * 8) = v;
    }
    __syncthreads();

    // ---- matmul1: scores ----
    if (wid < 7) {
        float acc[14][4];
        #pragma unroll
        for (int i = 0; i < 14; i++)
            #pragma unroll
            for (int k = 0; k < 4; k++) acc[i][k] = 0.f;

        const uint32_t aoff = qb + (uint32_t)((wid * 16 + (lane & 15)) * 208 + (lane >> 4) * 16);
        const uint32_t boff = qb + (uint32_t)((((lane >> 4) << 3) + (lane & 7)) * 208
                                              + ((lane >> 3) & 1) * 16);
        #pragma unroll
        for (int k = 0; k < 6; k++) {
            uint32_t a[4];
            LDSM4(a, aoff + k * 32);
            #pragma unroll
            for (int p = 0; p < 7; p++) {
                uint32_t t[4];
                LDSM4(t, boff + (uint32_t)(p * 16 * 208) + k * 32);
                uint32_t b0[2] = {t[0], t[1]}, b1[2] = {t[2], t[3]};
                MMA_F16(acc[2 * p], a, b0);
                MMA_F16(acc[2 * p + 1], a, b1);
            }
        }
        const float* pb = pbias + (size_t)blockIdx.x * (S_ * S_);
        const int r = lane >> 2, c0 = (lane & 3) * 2;
        const int i0 = wid * 16 + r, i1 = i0 + 8;
        #pragma unroll
        for (int nf = 0; nf < 14; nf++) {
            int j = nf * 8 + c0;
            float p00 = (i0 < S_ && j < S_)     ? pb[i0 * S_ + j]     : 0.f;
            float p01 = (i0 < S_ && j + 1 < S_) ? pb[i0 * S_ + j + 1] : 0.f;
            float p10 = (i1 < S_ && j < S_)     ? pb[i1 * S_ + j]     : 0.f;
            float p11 = (i1 < S_ && j + 1 < S_) ? pb[i1 * S_ + j + 1] : 0.f;
            Ss[i0 * SSW + j]     = __float2half(acc[nf][0] * INV_SQRT_HD + p00);
            Ss[i0 * SSW + j + 1] = __float2half(acc[nf][1] * INV_SQRT_HD + p01);
            Ss[i1 * SSW + j]     = __float2half(acc[nf][2] * INV_SQRT_HD + p10);
            Ss[i1 * SSW + j + 1] = __float2half(acc[nf][3] * INV_SQRT_HD + p11);
        }
    }
    __syncthreads();

    // ---- softmax rows (threads 0..99), fp32 math ----
    if (tid < S_) {
        __half* row = Ss + tid * SSW;
        float m = -1e30f;
        for (int j = 0; j < S_; j++) m = fmaxf(m, __half2float(row[j]));
        float sum = 0.f;
        for (int j = 0; j < S_; j++) {
            float e = expf(__half2float(row[j]) - m);
            row[j] = __float2half(e);
            sum += e;
        }
        float inv = 1.0f / sum;
        for (int j = 0; j < S_; j++)
            row[j] = __float2half(__half2float(row[j]) * inv);
        // zero padded cols 100..111 (were raw scores ~0, must be exactly 0 prob)
        for (int j = S_; j < 112; j++) row[j] = __float2half(0.f);
    }
    __syncthreads();

    // ---- matmul2: out = P Q ----
    if (wid < 7) {
        float acc[12][4];
        #pragma unroll
        for (int i = 0; i < 12; i++)
            #pragma unroll
            for (int k = 0; k < 4; k++) acc[i][k] = 0.f;

        const uint32_t aoff = sbS + (uint32_t)((wid * 16 + (lane & 15)) * 240 + (lane >> 4) * 16);
        // trans B: rows = k (j dim), cols = d
        const uint32_t btr = qb + (uint32_t)((((lane >> 3) & 1) * 8 + (lane & 7)) * 208
                                             + ((lane >> 4) * 8) * 2);
        #pragma unroll
        for (int k = 0; k < 7; k++) {
            uint32_t a[4];
            LDSM4(a, aoff + k * 32);
            #pragma unroll
            for (int p = 0; p < 6; p++) {
                uint32_t t[4];
                LDSM4T(t, btr + (uint32_t)(k * 16 * 208) + (uint32_t)(p * 32));
                uint32_t b0[2] = {t[0], t[1]}, b1[2] = {t[2], t[3]};
                MMA_F16(acc[2 * p], a, b0);
                MMA_F16(acc[2 * p + 1], a, b1);
            }
        }
        float* dst = out + (size_t)(b * S_) * D_ + h * HD_;
        const int r = lane >> 2, c0 = (lane & 3) * 2;
        const int i0 = wid * 16 + r, i1 = i0 + 8;
        #pragma unroll
        for (int nf = 0; nf < 12; nf++) {
            int d = nf * 8 + c0;
            if (i0 < S_) {
                dst[(size_t)i0 * D_ + d]     = acc[nf][0];
                dst[(size_t)i0 * D_ + d + 1] = acc[nf][1];
            }
            if (i1 < S_) {
                dst[(size_t)i1 * D_ + d]     = acc[nf][2];
                dst[(size_t)i1 * D_ + d + 1] = acc[nf][3];
            }
        }
    }
}

// ---------------- final classifier ----------------
__global__ void fc_kernel(const float* __restrict__ x, const float* __restrict__ Wfc,
                          const float* __restrict__ bfc, float* __restrict__ out) {
    const int b = blockIdx.x;
    const int tid = threadIdx.x;
    const float* xr = x + (size_t)b * (S_ * D_);
    float a0 = 0.f, a1 = 0.f;
    for (int i = tid; i < S_ * D_; i += 256) {
        float v = xr[i];
        a0 += v * Wfc[2 * i];
        a1 += v * Wfc[2 * i + 1];
    }
    __shared__ float red[2][8];
    int lane = tid & 31, wid = tid >> 5;
    a0 = warp_sum(a0); a1 = warp_sum(a1);
    if (lane == 0) { red[0][wid] = a0; red[1][wid] = a1; }
    __syncthreads();
    if (wid == 0) {
        float r0 = (lane < 8) ? red[0][lane] : 0.f;
        float r1 = (lane < 8) ? red[1][lane] : 0.f;
        r0 = warp_sum(r0); r1 = warp_sum(r1);
        if (lane == 0) {
            out[2 * b + 0] = r0 + bfc[0];
            out[2 * b + 1] = r1 + bfc[1];
        }
    }
}

// ---------------- launch ----------------
extern "C" void kernel_launch(void* const* d_in, const int* in_sizes, int n_in,
                              void* d_out, int out_size) {
    const float* tseq = (const float*)d_in[0];
    const float* pseq = (const float*)d_in[1];
    const float* Wc  = (const float*)d_in[2];
    const float* bc  = (const float*)d_in[3];
    const float* gp  = (const float*)d_in[4];
    const float* bp  = (const float*)d_in[5];
    const float* W1  = (const float*)d_in[6];
    const float* b1  = (const float*)d_in[7];
    const float* W2  = (const float*)d_in[8];
    const float* b2  = (const float*)d_in[9];
    const float* g1  = (const float*)d_in[10];
    const float* bn1 = (const float*)d_in[11];
    const float* g2  = (const float*)d_in[12];
    const float* bn2 = (const float*)d_in[13];
    const float* Wfc = (const float*)d_in[14];
    const float* bfc = (const float*)d_in[15];
    float* out = (float*)d_out;

    float *x, *enc, *pbias, *part, *pe;
    __half *xq, *xhi, *phi, *plo, *ffhi;
    __half *w1h, *w2h, *wch;
    cudaGetSymbolAddress((void**)&x, g_x);
    cudaGetSymbolAddress((void**)&enc, g_enc);
    cudaGetSymbolAddress((void**)&pbias, g_pbias);
    cudaGetSymbolAddress((void**)&part, g_part);
    cudaGetSymbolAddress((void**)&pe, g_pe);
    cudaGetSymbolAddress((void**)&xq, g_xq);
    cudaGetSymbolAddress((void**)&xhi, g_xhi);
    cudaGetSymbolAddress((void**)&phi, g_phi);
    cudaGetSymbolAddress((void**)&plo, g_plo);
    cudaGetSymbolAddress((void**)&ffhi, g_ffhi);
    cudaGetSymbolAddress((void**)&w1h, g_w1h);
    cudaGetSymbolAddress((void**)&w2h, g_w2h);
    cudaGetSymbolAddress((void**)&wch, g_wch);
    float* part0 = part;
    float* part1 = part + (size_t)M_ * D_;

    cudaFuncSetAttribute(attn_kernel, cudaFuncAttributeMaxDynamicSharedMemorySize, ATTN_SMEM);
    cudaFuncSetAttribute((mma_gemm<1, 0>), cudaFuncAttributeMaxDynamicSharedMemorySize, GEMM_SMEM);
    cudaFuncSetAttribute((mma_gemm<2, 1>), cudaFuncAttributeMaxDynamicSharedMemorySize, GEMM_SMEM);
    cudaFuncSetAttribute((mma_gemm<2, 0>), cudaFuncAttributeMaxDynamicSharedMemorySize, GEMM_SMEM);

    // weight transpose + fp16 convert (tiny, one-time per launch)
    wconv_kernel<<<dim3(D_ / 32, FF_ / 32), dim3(32, 8)>>>(W1, w1h, D_, FF_);
    wconv_kernel<<<dim3(FF_ / 32, D_ / 32), dim3(32, 8)>>>(W2, w2h, FF_, D_);
    wconv_kernel<<<dim3(D_ / 32, D_ / 32),  dim3(32, 8)>>>(Wc, wch, D_, D_);

    const int total = M_ * D_;
    pe_kernel<<<(S_ * D_ + 255) / 256, 256>>>(pe);
    add_pe_kernel<<<(total + 255) / 256, 256>>>(tseq, pe, x, xq);
    pool_kernel<<<(total + 255) / 256, 256>>>(pseq, phi, plo);

    // param encoder: enc = LN(pooled @ Wc + bc)  (split-K=2, exact 2-term A)
    mma_gemm<2, 1><<<dim3(D_ / BNT, M_ / BMT, 2), 256, GEMM_SMEM>>>(
        phi, plo, wch, nullptr, part0, nullptr, M_, D_, D_);
    ln_kernel<0><<<M_, 256>>>(part0, part1, nullptr, bc, gp, bp, enc, nullptr);

    // layer-invariant attention bias
    pbias_kernel<<<B_ * H_, 256>>>(enc, pbias);

    for (int l = 0; l < NLAYERS; l++) {
        attn_kernel<<<B_ * H_, 256, ATTN_SMEM>>>(xq, pbias, part0);
        ln_kernel<1><<<M_, 256>>>(x, part0, nullptr, nullptr, g1, bn1, x, xhi);
        // FFN1: single-fp16 A (LN output), gelu -> single fp16 ff
        mma_gemm<1, 0><<<dim3(FF_ / BNT, M_ / BMT), 256, GEMM_SMEM>>>(
            xhi, nullptr, w1h, b1, nullptr, ffhi, M_, FF_, D_);
        // FFN2: single-fp16 A, split-K=2 -> fp32 partials, b2 folded into LN
        mma_gemm<2, 0><<<dim3(D_ / BNT, M_ / BMT, 2), 256, GEMM_SMEM>>>(
            ffhi, nullptr, w2h, nullptr, part0, nullptr, M_, D_, FF_);
        // end-of-layer LN: fp32 x + fp16 copy for next layer's attention
        ln_kernel<1><<<M_, 256>>>(x, part0, part1, b2, g2, bn2, x, xq);
    }

    fc_kernel<<<B_, 256>>>(x, Wfc, bfc, out);
}

// round 12
// speedup vs baseline: 2.6386x; 1.0812x over previous
#include <cuda_runtime.h>
#include <cuda_fp16.h>
#include <math.h>
#include <stdint.h>

// ---------------- problem constants ----------------
#define B_   64
#define S_   100
#define D_   768
#define H_   8
#define HD_  96
#define P_   8
#define FF_  3072
#define M_   (B_ * S_)            // 6400 rows
#define NLAYERS 4
#define EPS_ 1e-5f
#define INV_SQRT_HD 0.10206207261596575f   // 1/sqrt(96)

// ---------------- device scratch ----------------
__device__ float g_x[M_ * D_];
__device__ float g_enc[M_ * D_];
__device__ float g_pbias[B_ * H_ * S_ * S_];
__device__ float g_part[2][M_ * D_];   // split-K fp32 partials
__device__ float g_pe[S_ * D_];

__device__ __half g_xq[M_ * D_];     // fp16 of attn input (layer input)
__device__ __half g_xhi[M_ * D_];    // fp16 of LN1 output (FFN1 input)
__device__ __half g_phi[M_ * D_];
__device__ __half g_plo[M_ * D_];
__device__ __half g_ffhi[(size_t)M_ * FF_];
__device__ __half g_w1h[(size_t)FF_ * D_];   // [N=3072][K=768] fp16
__device__ __half g_w2h[(size_t)D_ * FF_];   // [N=768][K=3072] fp16
__device__ __half g_wch[(size_t)D_ * D_];    // [N=768][K=768]  fp16

// ============================================================
// PTX helpers (mma.sync / ldmatrix / cp.async — all baseline sm_80+)
// ============================================================
__device__ __forceinline__ uint32_t smem_u32(const void* p) {
    uint32_t a;
    asm("{ .reg .u64 t; cvta.to.shared.u64 t, %1; cvt.u32.u64 %0, t; }" : "=r"(a) : "l"(p));
    return a;
}

#define CP_ASYNC16(dst, src) \
    asm volatile("cp.async.cg.shared.global [%0], [%1], 16;\n" :: "r"(dst), "l"(src) : "memory")
#define CP_COMMIT() asm volatile("cp.async.commit_group;\n" ::: "memory")
#define CP_WAIT0()  asm volatile("cp.async.wait_group 0;\n" ::: "memory")
#define CP_WAIT1()  asm volatile("cp.async.wait_group 1;\n" ::: "memory")

#define LDSM4(r, addr) \
    asm volatile("ldmatrix.sync.aligned.m8n8.x4.shared.b16 {%0,%1,%2,%3}, [%4];" \
        : "=r"((r)[0]), "=r"((r)[1]), "=r"((r)[2]), "=r"((r)[3]) : "r"(addr))

#define LDSM4T(r, addr) \
    asm volatile("ldmatrix.sync.aligned.m8n8.x4.trans.shared.b16 {%0,%1,%2,%3}, [%4];" \
        : "=r"((r)[0]), "=r"((r)[1]), "=r"((r)[2]), "=r"((r)[3]) : "r"(addr))

#define MMA_F16(c, a, b) \
    asm volatile("mma.sync.aligned.m16n8k16.row.col.f32.f16.f16.f32 " \
        "{%0,%1,%2,%3}, {%4,%5,%6,%7}, {%8,%9}, {%0,%1,%2,%3};" \
        : "+f"((c)[0]), "+f"((c)[1]), "+f"((c)[2]), "+f"((c)[3]) \
        : "r"((a)[0]), "r"((a)[1]), "r"((a)[2]), "r"((a)[3]), "r"((b)[0]), "r"((b)[1]))

__device__ __forceinline__ float gelu_exact(float v) {
    return 0.5f * v * (1.0f + erff(v * 0.70710678118654752f));
}
__device__ __forceinline__ void split_f16(float v, __half& h, __half& l) {
    h = __float2half(v);
    l = __float2half(v - __half2float(h));
}

// ============================================================
// GEMM: C[M,N] = A[M,K] @ B^T[N,K] (+ bias)
// TT=1: A = Ah + Al (fp16 pair); TT=0: A = Ah single fp16. B single fp16.
// EPI 1: bias + gelu -> single fp16 out. EPI 2: fp32 partial, z-indexed.
// BKS templated (32 or 64). 3-stage cp.async ring, 2 CTAs/SM.
// Row stride = BKS*2+16 bytes (odd multiple of 16B -> conflict-free ldmatrix).
// ============================================================
#define BMT 128
#define BNT 128
#define NSTAGE 3

template <int BKSv> struct GP {
    static constexpr uint32_t ROWB = BKSv * 2 + 16;       // bytes per smem row
    static constexpr uint32_t MATB = 128u * ROWB;         // one matrix slot
};
#define GEMM_SMEM_T1_32 (NSTAGE * 3 * GP<32>::MATB)       // 92160 (encoder)
#define GEMM_SMEM_T0_64 (NSTAGE * 2 * GP<64>::MATB)       // 110592 (FFN)

template <int EPI, int TT, int BKSv>
__global__ __launch_bounds__(256, 2)
void mma_gemm(const __half* __restrict__ Ah_, const __half* __restrict__ Al_,
              const __half* __restrict__ Bh_,
              const float* __restrict__ bias,
              float* __restrict__ Cf, __half* __restrict__ Ch,
              int M, int N, int K)
{
    constexpr uint32_t ROWB = GP<BKSv>::ROWB;
    constexpr uint32_t MATB = GP<BKSv>::MATB;
    constexpr int NMAT = TT ? 3 : 2;
    constexpr uint32_t BUFB = NMAT * MATB;
    constexpr int CHUNKS_PER_MAT = 128 * (BKSv / 8);      // 16B chunks
    constexpr int LOAD_ITERS = NMAT * CHUNKS_PER_MAT / 256;
    constexpr int KHN = BKSv / 16;

    extern __shared__ char dsm[];
    const uint32_t sb0 = smem_u32(dsm);
    const int tid = threadIdx.x;
    const int wid = tid >> 5, lane = tid & 31;
    const int wm = wid >> 1, wn = wid & 1;                // warp tile 32 x 64
    const int row0 = blockIdx.y * BMT, col0 = blockIdx.x * BNT;
    const int Kloc = K / gridDim.z;
    const int koff = blockIdx.z * Kloc;
    const int NS = Kloc / BKSv;

    const __half* Ahp = Ah_ + koff;
    const __half* Alp = TT ? Al_ + koff : nullptr;
    const __half* Bhp = Bh_ + koff;

    float acc[2][8][4];
    #pragma unroll
    for (int i = 0; i < 2; i++)
        #pragma unroll
        for (int j = 0; j < 8; j++)
            #pragma unroll
            for (int k = 0; k < 4; k++) acc[i][j][k] = 0.f;

    const uint32_t aoff = (uint32_t)(wm * 32 + (lane & 15)) * ROWB + (uint32_t)(lane >> 4) * 16;
    const uint32_t boff = (uint32_t)(wn * 64 + ((lane >> 4) << 3) + (lane & 7)) * ROWB
                        + (uint32_t)((lane >> 3) & 1) * 16;
    const uint32_t BOFFM = (TT ? 2u : 1u) * MATB;         // B matrix slot

    auto load_step = [&](int s) {
        const uint32_t sb = sb0 + (uint32_t)(s % NSTAGE) * BUFB;
        const int k0 = s * BKSv;
        #pragma unroll
        for (int i = 0; i < LOAD_ITERS; i++) {
            int u = i * 256 + tid;
            int mat = u / CHUNKS_PER_MAT;
            int v = u % CHUNKS_PER_MAT;
            int r = v / (BKSv / 8), c = v % (BKSv / 8);
            const __half* src;
            if (TT) {
                if (mat == 0)      src = Ahp + (size_t)(row0 + r) * K + k0 + c * 8;
                else if (mat == 1) src = Alp + (size_t)(row0 + r) * K + k0 + c * 8;
                else               src = Bhp + (size_t)(col0 + r) * K + k0 + c * 8;
            } else {
                if (mat == 0)      src = Ahp + (size_t)(row0 + r) * K + k0 + c * 8;
                else               src = Bhp + (size_t)(col0 + r) * K + k0 + c * 8;
            }
            CP_ASYNC16(sb + (uint32_t)mat * MATB + (uint32_t)r * ROWB + (uint32_t)c * 16, src);
        }
        CP_COMMIT();
    };

    load_step(0);
    if (NS > 1) load_step(1);

    for (int s = 0; s < NS; s++) {
        if (s < NS - 1) { CP_WAIT1(); } else { CP_WAIT0(); }
        __syncthreads();
        if (s + 2 < NS) load_step(s + 2);

        const uint32_t sb = sb0 + (uint32_t)(s % NSTAGE) * BUFB;
        #pragma unroll
        for (int kh = 0; kh < KHN; kh++) {
            uint32_t ah[2][4], al[2][4], b[8][2];
            #pragma unroll
            for (int mf = 0; mf < 2; mf++) {
                LDSM4(ah[mf], sb + aoff + (uint32_t)(mf * 16) * ROWB + (uint32_t)kh * 32);
                if (TT) LDSM4(al[mf], sb + MATB + aoff + (uint32_t)(mf * 16) * ROWB + (uint32_t)kh * 32);
            }
            #pragma unroll
            for (int p = 0; p < 4; p++) {
                uint32_t t[4];
                LDSM4(t, sb + BOFFM + boff + (uint32_t)(p * 16) * ROWB + (uint32_t)kh * 32);
                b[2 * p][0] = t[0]; b[2 * p][1] = t[1];
                b[2 * p + 1][0] = t[2]; b[2 * p + 1][1] = t[3];
            }
            #pragma unroll
            for (int mf = 0; mf < 2; mf++)
                #pragma unroll
                for (int nf = 0; nf < 8; nf++) {
                    MMA_F16(acc[mf][nf], ah[mf], b[nf]);
                    if (TT) MMA_F16(acc[mf][nf], al[mf], b[nf]);
                }
        }
    }

    // ---- epilogue: regs -> per-warp smem stage (16x65 fp32) -> coalesced stores ----
    __syncthreads();
    float* stg = (float*)dsm + wid * (16 * 65);
    const int gcol0 = col0 + wn * 64;
    const float bv0 = (EPI == 2) ? 0.f : bias[gcol0 + lane];
    const float bv1 = (EPI == 2) ? 0.f : bias[gcol0 + 32 + lane];
    const int r1 = lane >> 2, c0 = (lane & 3) * 2;
    float* Cfz = (EPI == 2) ? Cf + (size_t)blockIdx.z * M * N : Cf;

    #pragma unroll
    for (int mf = 0; mf < 2; mf++) {
        #pragma unroll
        for (int nf = 0; nf < 8; nf++) {
            stg[r1 * 65 + nf * 8 + c0]           = acc[mf][nf][0];
            stg[r1 * 65 + nf * 8 + c0 + 1]       = acc[mf][nf][1];
            stg[(r1 + 8) * 65 + nf * 8 + c0]     = acc[mf][nf][2];
            stg[(r1 + 8) * 65 + nf * 8 + c0 + 1] = acc[mf][nf][3];
        }
        __syncwarp();
        const int grow = row0 + wm * 32 + mf * 16;
        #pragma unroll
        for (int r = 0; r < 16; r++) {
            float v0 = stg[r * 65 + lane] + bv0;
            float v1 = stg[r * 65 + 32 + lane] + bv1;
            if (EPI == 1) {
                v0 = gelu_exact(v0);
                v1 = gelu_exact(v1);
                size_t base = (size_t)(grow + r) * N + gcol0;
                Ch[base + lane] = __float2half(v0);
                Ch[base + 32 + lane] = __float2half(v1);
            } else {
                size_t base = (size_t)(grow + r) * N + gcol0;
                Cfz[base + lane] = v0;
                Cfz[base + 32 + lane] = v1;
            }
        }
        __syncwarp();
    }
}

// ============================================================
// weight transpose + fp16 convert
// ============================================================
__global__ void wconv_kernel(const float* __restrict__ W, __half* __restrict__ Th,
                             int K, int N) {
    __shared__ float t[32][33];
    int k0 = blockIdx.x * 32, n0 = blockIdx.y * 32;
    int tx = threadIdx.x, ty = threadIdx.y;
    #pragma unroll
    for (int i = 0; i < 4; i++)
        t[ty + i * 8][tx] = W[(size_t)(k0 + ty + i * 8) * N + n0 + tx];
    __syncthreads();
    #pragma unroll
    for (int i = 0; i < 4; i++) {
        int n = n0 + ty + i * 8, k = k0 + tx;
        Th[(size_t)n * K + k] = __float2half(t[tx][ty + i * 8]);
    }
}

// ---------------- positional-encoding table (once per launch) ----------------
__global__ void pe_kernel(float* __restrict__ pe) {
    int idx = blockIdx.x * 256 + threadIdx.x;
    if (idx >= S_ * D_) return;
    int d = idx % D_;
    int s = idx / D_;
    int i2 = d & ~1;
    float div = expf((float)i2 * (-9.210340371976184f / (float)D_));
    float ang = (float)s * div;
    pe[idx] = (d & 1) ? cosf(ang) : sinf(ang);
}

// ---------------- x = template + pe; also emit fp16 copy for attention ----------------
__global__ void add_pe_kernel(const float* __restrict__ t, const float* __restrict__ pe,
                              float* __restrict__ x, __half* __restrict__ xq) {
    int idx = blockIdx.x * 256 + threadIdx.x;
    if (idx >= M_ * D_) return;
    float v = t[idx] + pe[idx % (S_ * D_)];
    x[idx] = v;
    xq[idx] = __float2half(v);
}

// ---------------- pooled = mean over P, emitted as fp16 hi/lo ----------------
__global__ void pool_kernel(const float* __restrict__ ps,
                            __half* __restrict__ ph, __half* __restrict__ pl) {
    int idx = blockIdx.x * 256 + threadIdx.x;
    if (idx >= M_ * D_) return;
    int bs = idx / D_;
    int c  = idx % D_;
    const float* base = ps + (size_t)bs * (P_ * D_) + c;
    float s = 0.f;
    #pragma unroll
    for (int p = 0; p < P_; p++) s += base[p * D_];
    float m = s * (1.0f / P_);
    __half h, l;
    split_f16(m, h, l);
    ph[idx] = h; pl[idx] = l;
}

// ---------------- block-reduce helper ----------------
__device__ __forceinline__ float warp_sum(float v) {
    #pragma unroll
    for (int o = 16; o; o >>= 1) v += __shfl_down_sync(0xffffffffu, v, o);
    return v;
}

// ---------------- LayerNorm (row length 768) ----------------
template <int F16OUT>
__global__ void ln_kernel(const float* __restrict__ x, const float* __restrict__ res,
                          const float* __restrict__ res2,
                          const float* __restrict__ colbias,
                          const float* __restrict__ g, const float* __restrict__ b,
                          float* __restrict__ out,
                          __half* __restrict__ oh) {
    const int row = blockIdx.x;
    const int tid = threadIdx.x;
    const float* xr = x + (size_t)row * D_;
    const float* rr = res ? res + (size_t)row * D_ : nullptr;
    const float* r2 = res2 ? res2 + (size_t)row * D_ : nullptr;

    float v[3];
    float s = 0.f, s2 = 0.f;
    #pragma unroll
    for (int i = 0; i < 3; i++) {
        int c = tid + i * 256;
        float t = xr[c];
        if (rr) t += rr[c];
        if (r2) t += r2[c];
        if (colbias) t += colbias[c];
        v[i] = t; s += t; s2 += t * t;
    }

    __shared__ float red[2][8];
    __shared__ float stat[2];
    int lane = tid & 31, wid = tid >> 5;
    s = warp_sum(s); s2 = warp_sum(s2);
    if (lane == 0) { red[0][wid] = s; red[1][wid] = s2; }
    __syncthreads();
    if (wid == 0) {
        float a = (lane < 8) ? red[0][lane] : 0.f;
        float c = (lane < 8) ? red[1][lane] : 0.f;
        a = warp_sum(a); c = warp_sum(c);
        if (lane == 0) {
            float mean = a * (1.0f / D_);
            float var = c * (1.0f / D_) - mean * mean;
            stat[0] = mean;
            stat[1] = rsqrtf(var + EPS_);
        }
    }
    __syncthreads();
    float mean = stat[0], inv = stat[1];
    float* orow = out + (size_t)row * D_;
    #pragma unroll
    for (int i = 0; i < 3; i++) {
        int c = tid + i * 256;
        float o = (v[i] - mean) * inv * g[c] + b[c];
        orow[c] = o;
        if (F16OUT) {
            oh[(size_t)row * D_ + c] = __float2half(o);
        }
    }
}

// ---------------- param_bias (symmetric, runs once) ----------------
__global__ __launch_bounds__(256)
void pbias_kernel(const float* __restrict__ enc, float* __restrict__ pbias) {
    __shared__ float Es[112 * 97];
    const int b = blockIdx.x >> 3;
    const int h = blockIdx.x & 7;
    const int tid = threadIdx.x;
    const float* src = enc + (size_t)(b * S_) * D_ + h * HD_;

    for (int i = tid; i < 112 * 96; i += 256) {
        int s = i / 96, d = i - s * 96;
        Es[s * 97 + d] = (s < S_) ? src[(size_t)s * D_ + d] : 0.f;
    }
    __syncthreads();

    const int tx = tid & 15, ty = tid >> 4;
    float acc[7][7];
    #pragma unroll
    for (int ii = 0; ii < 7; ii++)
        #pragma unroll
        for (int jj = 0; jj < 7; jj++) acc[ii][jj] = 0.f;

    for (int d = 0; d < 96; d++) {
        float a[7], bb[7];
        #pragma unroll
        for (int ii = 0; ii < 7; ii++) a[ii]  = Es[(ty + 16 * ii) * 97 + d];
        #pragma unroll
        for (int jj = 0; jj < 7; jj++) bb[jj] = Es[(tx + 16 * jj) * 97 + d];
        #pragma unroll
        for (int ii = 0; ii < 7; ii++)
            #pragma unroll
            for (int jj = 0; jj < 7; jj++)
                if (jj >= ii) acc[ii][jj] += a[ii] * bb[jj];
    }

    float* dst = pbias + (size_t)blockIdx.x * (S_ * S_);
    #pragma unroll
    for (int ii = 0; ii < 7; ii++) {
        int i = ty + 16 * ii;
        if (i >= S_) continue;
        #pragma unroll
        for (int jj = 0; jj < 7; jj++) {
            if (jj < ii) continue;
            int j = tx + 16 * jj;
            if (j < S_) {
                float v = acc[ii][jj] * INV_SQRT_HD;
                dst[i * S_ + j] = v;
                if (jj > ii) dst[j * S_ + i] = v;
            }
        }
    }
}

// ---------------- fused attention on tensor cores ----------------
#define QSW 104
#define SSW 120
#define ATTN_SMEM (112 * QSW * 2 + 112 * SSW * 2)   // 50176
__global__ __launch_bounds__(256, 3)
void attn_kernel(const __half* __restrict__ xq, const float* __restrict__ pbias,
                 float* __restrict__ out) {
    extern __shared__ char asm_[];
    __half* Qh = (__half*)asm_;
    __half* Ss = Qh + 112 * QSW;
    const uint32_t qb = smem_u32(Qh);
    const uint32_t sbS = smem_u32(Ss);

    const int b = blockIdx.x >> 3;
    const int h = blockIdx.x & 7;
    const int tid = threadIdx.x;
    const int wid = tid >> 5, lane = tid & 31;

    const __half* src = xq + (size_t)(b * S_) * D_ + h * HD_;
    for (int i = tid; i < 112 * 12; i += 256) {
        int s = i / 12, c = i % 12;
        uint4 v = make_uint4(0u, 0u, 0u, 0u);
        if (s < S_) v = *(const uint4*)(src + (size_t)s * D_ + c * 8);
        *(uint4*)(Qh + s * QSW + c * 8) = v;
    }
    __syncthreads();

    // ---- matmul1: scores ----
    if (wid < 7) {
        float acc[14][4];
        #pragma unroll
        for (int i = 0; i < 14; i++)
            #pragma unroll
            for (int k = 0; k < 4; k++) acc[i][k] = 0.f;

        const uint32_t aoff = qb + (uint32_t)((wid * 16 + (lane & 15)) * 208 + (lane >> 4) * 16);
        const uint32_t boff = qb + (uint32_t)((((lane >> 4) << 3) + (lane & 7)) * 208
                                              + ((lane >> 3) & 1) * 16);
        #pragma unroll
        for (int k = 0; k < 6; k++) {
            uint32_t a[4];
            LDSM4(a, aoff + k * 32);
            #pragma unroll
            for (int p = 0; p < 7; p++) {
                uint32_t t[4];
                LDSM4(t, boff + (uint32_t)(p * 16 * 208) + k * 32);
                uint32_t b0[2] = {t[0], t[1]}, b1[2] = {t[2], t[3]};
                MMA_F16(acc[2 * p], a, b0);
                MMA_F16(acc[2 * p + 1], a, b1);
            }
        }
        const float* pb = pbias + (size_t)blockIdx.x * (S_ * S_);
        const int r = lane >> 2, c0 = (lane & 3) * 2;
        const int i0 = wid * 16 + r, i1 = i0 + 8;
        #pragma unroll
        for (int nf = 0; nf < 14; nf++) {
            int j = nf * 8 + c0;
            float p00 = (i0 < S_ && j < S_)     ? pb[i0 * S_ + j]     : 0.f;
            float p01 = (i0 < S_ && j + 1 < S_) ? pb[i0 * S_ + j + 1] : 0.f;
            float p10 = (i1 < S_ && j < S_)     ? pb[i1 * S_ + j]     : 0.f;
            float p11 = (i1 < S_ && j + 1 < S_) ? pb[i1 * S_ + j + 1] : 0.f;
            Ss[i0 * SSW + j]     = __float2half(acc[nf][0] * INV_SQRT_HD + p00);
            Ss[i0 * SSW + j + 1] = __float2half(acc[nf][1] * INV_SQRT_HD + p01);
            Ss[i1 * SSW + j]     = __float2half(acc[nf][2] * INV_SQRT_HD + p10);
            Ss[i1 * SSW + j + 1] = __float2half(acc[nf][3] * INV_SQRT_HD + p11);
        }
    }
    __syncthreads();

    // ---- softmax rows (threads 0..99) ----
    if (tid < S_) {
        __half* row = Ss + tid * SSW;
        float m = -1e30f;
        for (int j = 0; j < S_; j++) m = fmaxf(m, __half2float(row[j]));
        float sum = 0.f;
        for (int j = 0; j < S_; j++) {
            float e = expf(__half2float(row[j]) - m);
            row[j] = __float2half(e);
            sum += e;
        }
        float inv = 1.0f / sum;
        for (int j = 0; j < S_; j++)
            row[j] = __float2half(__half2float(row[j]) * inv);
        for (int j = S_; j < 112; j++) row[j] = __float2half(0.f);
    }
    __syncthreads();

    // ---- matmul2: out = P Q ----
    if (wid < 7) {
        float acc[12][4];
        #pragma unroll
        for (int i = 0; i < 12; i++)
            #pragma unroll
            for (int k = 0; k < 4; k++) acc[i][k] = 0.f;

        const uint32_t aoff = sbS + (uint32_t)((wid * 16 + (lane & 15)) * 240 + (lane >> 4) * 16);
        const uint32_t btr = qb + (uint32_t)((((lane >> 3) & 1) * 8 + (lane & 7)) * 208
                                             + ((lane >> 4) * 8) * 2);
        #pragma unroll
        for (int k = 0; k < 7; k++) {
            uint32_t a[4];
            LDSM4(a, aoff + k * 32);
            #pragma unroll
            for (int p = 0; p < 6; p++) {
                uint32_t t[4];
                LDSM4T(t, btr + (uint32_t)(k * 16 * 208) + (uint32_t)(p * 32));
                uint32_t b0[2] = {t[0], t[1]}, b1[2] = {t[2], t[3]};
                MMA_F16(acc[2 * p], a, b0);
                MMA_F16(acc[2 * p + 1], a, b1);
            }
        }
        float* dst = out + (size_t)(b * S_) * D_ + h * HD_;
        const int r = lane >> 2, c0 = (lane & 3) * 2;
        const int i0 = wid * 16 + r, i1 = i0 + 8;
        #pragma unroll
        for (int nf = 0; nf < 12; nf++) {
            int d = nf * 8 + c0;
            if (i0 < S_) {
                dst[(size_t)i0 * D_ + d]     = acc[nf][0];
                dst[(size_t)i0 * D_ + d + 1] = acc[nf][1];
            }
            if (i1 < S_) {
                dst[(size_t)i1 * D_ + d]     = acc[nf][2];
                dst[(size_t)i1 * D_ + d + 1] = acc[nf][3];
            }
        }
    }
}

// ---------------- final classifier ----------------
__global__ void fc_kernel(const float* __restrict__ x, const float* __restrict__ Wfc,
                          const float* __restrict__ bfc, float* __restrict__ out) {
    const int b = blockIdx.x;
    const int tid = threadIdx.x;
    const float* xr = x + (size_t)b * (S_ * D_);
    float a0 = 0.f, a1 = 0.f;
    for (int i = tid; i < S_ * D_; i += 256) {
        float v = xr[i];
        a0 += v * Wfc[2 * i];
        a1 += v * Wfc[2 * i + 1];
    }
    __shared__ float red[2][8];
    int lane = tid & 31, wid = tid >> 5;
    a0 = warp_sum(a0); a1 = warp_sum(a1);
    if (lane == 0) { red[0][wid] = a0; red[1][wid] = a1; }
    __syncthreads();
    if (wid == 0) {
        float r0 = (lane < 8) ? red[0][lane] : 0.f;
        float r1 = (lane < 8) ? red[1][lane] : 0.f;
        r0 = warp_sum(r0); r1 = warp_sum(r1);
        if (lane == 0) {
            out[2 * b + 0] = r0 + bfc[0];
            out[2 * b + 1] = r1 + bfc[1];
        }
    }
}

// ---------------- launch ----------------
extern "C" void kernel_launch(void* const* d_in, const int* in_sizes, int n_in,
                              void* d_out, int out_size) {
    const float* tseq = (const float*)d_in[0];
    const float* pseq = (const float*)d_in[1];
    const float* Wc  = (const float*)d_in[2];
    const float* bc  = (const float*)d_in[3];
    const float* gp  = (const float*)d_in[4];
    const float* bp  = (const float*)d_in[5];
    const float* W1  = (const float*)d_in[6];
    const float* b1  = (const float*)d_in[7];
    const float* W2  = (const float*)d_in[8];
    const float* b2  = (const float*)d_in[9];
    const float* g1  = (const float*)d_in[10];
    const float* bn1 = (const float*)d_in[11];
    const float* g2  = (const float*)d_in[12];
    const float* bn2 = (const float*)d_in[13];
    const float* Wfc = (const float*)d_in[14];
    const float* bfc = (const float*)d_in[15];
    float* out = (float*)d_out;

    float *x, *enc, *pbias, *part, *pe;
    __half *xq, *xhi, *phi, *plo, *ffhi;
    __half *w1h, *w2h, *wch;
    cudaGetSymbolAddress((void**)&x, g_x);
    cudaGetSymbolAddress((void**)&enc, g_enc);
    cudaGetSymbolAddress((void**)&pbias, g_pbias);
    cudaGetSymbolAddress((void**)&part, g_part);
    cudaGetSymbolAddress((void**)&pe, g_pe);
    cudaGetSymbolAddress((void**)&xq, g_xq);
    cudaGetSymbolAddress((void**)&xhi, g_xhi);
    cudaGetSymbolAddress((void**)&phi, g_phi);
    cudaGetSymbolAddress((void**)&plo, g_plo);
    cudaGetSymbolAddress((void**)&ffhi, g_ffhi);
    cudaGetSymbolAddress((void**)&w1h, g_w1h);
    cudaGetSymbolAddress((void**)&w2h, g_w2h);
    cudaGetSymbolAddress((void**)&wch, g_wch);
    float* part0 = part;
    float* part1 = part + (size_t)M_ * D_;

    cudaFuncSetAttribute(attn_kernel, cudaFuncAttributeMaxDynamicSharedMemorySize, ATTN_SMEM);
    cudaFuncSetAttribute((mma_gemm<1, 0, 64>), cudaFuncAttributeMaxDynamicSharedMemorySize, GEMM_SMEM_T0_64);
    cudaFuncSetAttribute((mma_gemm<2, 0, 64>), cudaFuncAttributeMaxDynamicSharedMemorySize, GEMM_SMEM_T0_64);
    cudaFuncSetAttribute((mma_gemm<2, 1, 32>), cudaFuncAttributeMaxDynamicSharedMemorySize, GEMM_SMEM_T1_32);

    // weight transpose + fp16 convert (tiny, one-time per launch)
    wconv_kernel<<<dim3(D_ / 32, FF_ / 32), dim3(32, 8)>>>(W1, w1h, D_, FF_);
    wconv_kernel<<<dim3(FF_ / 32, D_ / 32), dim3(32, 8)>>>(W2, w2h, FF_, D_);
    wconv_kernel<<<dim3(D_ / 32, D_ / 32),  dim3(32, 8)>>>(Wc, wch, D_, D_);

    const int total = M_ * D_;
    pe_kernel<<<(S_ * D_ + 255) / 256, 256>>>(pe);
    add_pe_kernel<<<(total + 255) / 256, 256>>>(tseq, pe, x, xq);
    pool_kernel<<<(total + 255) / 256, 256>>>(pseq, phi, plo);

    // param encoder: enc = LN(pooled @ Wc + bc)  (split-K=2, exact 2-term A)
    mma_gemm<2, 1, 32><<<dim3(D_ / BNT, M_ / BMT, 2), 256, GEMM_SMEM_T1_32>>>(
        phi, plo, wch, nullptr, part0, nullptr, M_, D_, D_);
    ln_kernel<0><<<M_, 256>>>(part0, part1, nullptr, bc, gp, bp, enc, nullptr);

    // layer-invariant attention bias
    pbias_kernel<<<B_ * H_, 256>>>(enc, pbias);

    for (int l = 0; l < NLAYERS; l++) {
        attn_kernel<<<B_ * H_, 256, ATTN_SMEM>>>(xq, pbias, part0);
        ln_kernel<1><<<M_, 256>>>(x, part0, nullptr, nullptr, g1, bn1, x, xhi);
        // FFN1: single-fp16 A, gelu -> single fp16 ff   (BKS=64)
        mma_gemm<1, 0, 64><<<dim3(FF_ / BNT, M_ / BMT), 256, GEMM_SMEM_T0_64>>>(
            xhi, nullptr, w1h, b1, nullptr, ffhi, M_, FF_, D_);
        // FFN2: single-fp16 A, split-K=2 -> fp32 partials, b2 folded into LN (BKS=64)
        mma_gemm<2, 0, 64><<<dim3(D_ / BNT, M_ / BMT, 2), 256, GEMM_SMEM_T0_64>>>(
            ffhi, nullptr, w2h, nullptr, part0, nullptr, M_, D_, FF_);
        // end-of-layer LN: fp32 x + fp16 copy for next layer's attention
        ln_kernel<1><<<M_, 256>>>(x, part0, part1, b2, g2, bn2, x, xq);
    }

    fc_kernel<<<B_, 256>>>(x, Wfc, bfc, out);
}